// round 8
// baseline (speedup 1.0000x reference)
#include <cuda_runtime.h>
#include <cuda_bf16.h>
#include <cstdint>

constexpr int BATCH = 2048;
constexpr int DIM   = 1024;
constexpr int MOL   = 8;
constexpr int NPAIR = 28;
constexpr int LQ    = 36;
constexpr int OUTD  = 4;
constexpr int MROWS = 32768;           // 2 * BATCH * MOL

__constant__ int c_pi[NPAIR] = {0,0,0,0,0,0,0,1,1,1,1,1,1,2,2,2,2,2,3,3,3,3,4,4,4,5,5,6};
__constant__ int c_pj[NPAIR] = {1,2,3,4,5,6,7,2,3,4,5,6,7,3,4,5,6,7,4,5,6,7,5,6,7,6,7,7};

// ------------------------- static device scratch ---------------------------
__device__ __nv_bfloat16 g_WqHi[DIM * DIM];
__device__ __nv_bfloat16 g_WqLo[DIM * DIM];
__device__ __nv_bfloat16 g_WkHi[DIM * DIM];
__device__ __nv_bfloat16 g_WkLo[DIM * DIM];
__device__ __nv_bfloat16 g_GtHi[DIM * DIM];          // Gt[n][k] = G[k][n]
__device__ __nv_bfloat16 g_GtLo[DIM * DIM];
__device__ __nv_bfloat16 g_Xhi[(size_t)MROWS * DIM]; // 64 MB, row = s*16384+b*8+m
__device__ __nv_bfloat16 g_Xlo[(size_t)MROWS * DIM]; // 64 MB
__device__ float         g_Spart[8ull * 2 * BATCH * 64];  // 4 MB partial grams
__device__ float         g_w[2 * BATCH * MOL];

// ------------------------------ helpers ------------------------------------
__device__ __forceinline__ uint32_t s2u(const void* p) {
    uint32_t a;
    asm("{ .reg .u64 t; cvta.to.shared.u64 t, %1; cvt.u32.u64 %0, t; }" : "=r"(a) : "l"(p));
    return a;
}
__device__ __forceinline__ void cpa16(uint32_t d, const void* g) {
    asm volatile("cp.async.cg.shared.global [%0], [%1], 16;" :: "r"(d), "l"(g));
}
#define CP_COMMIT()  asm volatile("cp.async.commit_group;" ::: "memory")
#define CP_WAIT0()   asm volatile("cp.async.wait_group 0;" ::: "memory")

__device__ __forceinline__ float4 lds4f(uint32_t a) {
    float4 v;
    asm volatile("ld.shared.v4.f32 {%0,%1,%2,%3}, [%4];"
        : "=f"(v.x), "=f"(v.y), "=f"(v.z), "=f"(v.w) : "r"(a));
    return v;
}
__device__ __forceinline__ float lds1f(uint32_t a) {
    float v;
    asm volatile("ld.shared.f32 %0, [%1];" : "=f"(v) : "r"(a));
    return v;
}
__device__ __forceinline__ void sts2f(uint32_t a, float x, float y) {
    asm volatile("st.shared.v2.f32 [%0], {%1,%2};" :: "r"(a), "f"(x), "f"(y));
}

__device__ __forceinline__ void lda4(uint32_t* f, uint32_t mbase, int wm, int mt,
                                     int ks, int lane) {
    int g = lane >> 3, r = lane & 7;
    int mloc = wm + mt * 16 + (g & 1) * 8 + r;
    int kloc = ks * 16 + (g >> 1) * 8;
    uint32_t a = mbase + (mloc * 40 + kloc) * 2;
    asm volatile("ldmatrix.sync.aligned.m8n8.x4.shared.b16 {%0,%1,%2,%3}, [%4];"
        : "=r"(f[0]), "=r"(f[1]), "=r"(f[2]), "=r"(f[3]) : "r"(a));
}
// load B fragments for TWO adjacent nt tiles (8+8 rows) in one x4
// f[0..1] = nt pair row-group 0 (k0,k1 frags), f[2..3] = row-group 1
__device__ __forceinline__ void ldb4(uint32_t* f, uint32_t mbase, int wn, int ntp,
                                     int ks, int lane) {
    int g = lane >> 3, r = lane & 7;
    int nloc = wn + ntp * 16 + (g >> 1) * 8 + r;
    int kloc = ks * 16 + (g & 1) * 8;
    uint32_t a = mbase + (nloc * 40 + kloc) * 2;
    asm volatile("ldmatrix.sync.aligned.m8n8.x4.shared.b16 {%0,%1,%2,%3}, [%4];"
        : "=r"(f[0]), "=r"(f[1]), "=r"(f[2]), "=r"(f[3]) : "r"(a));
}
__device__ __forceinline__ void mma16816(float* c, const uint32_t* a, const uint32_t* b) {
    asm volatile("mma.sync.aligned.m16n8k16.row.col.f32.bf16.bf16.f32 "
        "{%0,%1,%2,%3}, {%4,%5,%6,%7}, {%8,%9}, {%0,%1,%2,%3};"
        : "+f"(c[0]), "+f"(c[1]), "+f"(c[2]), "+f"(c[3])
        : "r"(a[0]), "r"(a[1]), "r"(a[2]), "r"(a[3]), "r"(b[0]), "r"(b[1]));
}

union BfPack { __nv_bfloat16 h[8]; uint4 u; };

// ------------------------- split kernels -----------------------------------
__global__ void __launch_bounds__(128) split_w(const float* __restrict__ Wq,
                                               const float* __restrict__ Wk) {
    int bx = blockIdx.x;
    int mat = bx >> 10, row = bx & 1023;
    const float* src = (mat ? Wk : Wq) + (size_t)row * DIM;
    __nv_bfloat16* hi = (mat ? g_WkHi : g_WqHi) + (size_t)row * DIM;
    __nv_bfloat16* lo = (mat ? g_WkLo : g_WqLo) + (size_t)row * DIM;
    int t = threadIdx.x;
    float4 v0 = ((const float4*)src)[t * 2];
    float4 v1 = ((const float4*)src)[t * 2 + 1];
    float vv[8] = {v0.x, v0.y, v0.z, v0.w, v1.x, v1.y, v1.z, v1.w};
    BfPack hp, lp;
#pragma unroll
    for (int i = 0; i < 8; i++) {
        __nv_bfloat16 h = __float2bfloat16_rn(vv[i]);
        hp.h[i] = h;
        lp.h[i] = __float2bfloat16_rn(vv[i] - __bfloat162float(h));
    }
    ((uint4*)(hi))[t] = hp.u;
    ((uint4*)(lo))[t] = lp.u;
}

__global__ void __launch_bounds__(256) split_x(const float* __restrict__ p,
                                               const float* __restrict__ r) {
    int t = threadIdx.x;
    int row = blockIdx.x * 2 + (t >> 7);
    int tt = t & 127;
    int s = row >> 14, b = (row >> 3) & (BATCH - 1), m = row & 7;
    const float* src = (s ? r : p) + ((size_t)m * BATCH + b) * DIM;
    float4 v0 = ((const float4*)src)[tt * 2];
    float4 v1 = ((const float4*)src)[tt * 2 + 1];
    float vv[8] = {v0.x, v0.y, v0.z, v0.w, v1.x, v1.y, v1.z, v1.w};
    BfPack hp, lp;
#pragma unroll
    for (int i = 0; i < 8; i++) {
        __nv_bfloat16 h = __float2bfloat16_rn(vv[i]);
        hp.h[i] = h;
        lp.h[i] = __float2bfloat16_rn(vv[i] - __bfloat162float(h));
    }
    ((uint4*)(g_Xhi + (size_t)row * DIM))[tt] = hp.u;
    ((uint4*)(g_Xlo + (size_t)row * DIM))[tt] = lp.u;
}

// ------------------------- shared GEMM machinery ---------------------------
constexpr int MAT_ELE   = 128 * 40;
constexpr int STAGE_B   = 4 * MAT_ELE * 2;      // 40960 bytes
constexpr int SMEM_GEMM = 2 * STAGE_B;          // 81920 bytes
constexpr int FPAD      = 132;

__device__ __forceinline__ void load_chunk(
    uint32_t sbase, int stage,
    const __nv_bfloat16* __restrict__ Ahi, const __nv_bfloat16* __restrict__ Alo,
    const __nv_bfloat16* __restrict__ Bhi, const __nv_bfloat16* __restrict__ Blo,
    int rowBase, int colBase, int k0, int tid)
{
    uint32_t st = sbase + stage * STAGE_B;
#pragma unroll
    for (int mat = 0; mat < 4; mat++) {
        const __nv_bfloat16* src0 =
            (mat == 0) ? Ahi : (mat == 1) ? Alo : (mat == 2) ? Bhi : Blo;
        int base = (mat < 2) ? rowBase : colBase;
#pragma unroll
        for (int h = 0; h < 2; h++) {
            int idx = h * 256 + tid;
            int row = idx >> 2, ch = idx & 3;
            const __nv_bfloat16* src = src0 + (size_t)(base + row) * DIM + k0 + ch * 8;
            uint32_t dst = st + (mat * MAT_ELE + row * 40 + ch * 8) * 2;
            cpa16(dst, src);
        }
    }
    CP_COMMIT();
}

// one k32 chunk: B frags (x4-batched) held, A streamed per mt
__device__ __forceinline__ void compute_chunk(
    float acc[4][4][4], uint32_t stb, int wm, int wn, int lane)
{
    uint32_t bAhi = stb;
    uint32_t bAlo = stb + MAT_ELE * 2;
    uint32_t bBhi = stb + 2 * MAT_ELE * 2;
    uint32_t bBlo = stb + 3 * MAT_ELE * 2;
#pragma unroll
    for (int ks = 0; ks < 2; ks++) {
        uint32_t bhif[8], blof[8];
        ldb4(bhif,     bBhi, wn, 0, ks, lane);
        ldb4(bhif + 4, bBhi, wn, 1, ks, lane);
        ldb4(blof,     bBlo, wn, 0, ks, lane);
        ldb4(blof + 4, bBlo, wn, 1, ks, lane);
#pragma unroll
        for (int mt = 0; mt < 4; mt++) {
            uint32_t ahif[4], alof[4];
            lda4(ahif, bAhi, wm, mt, ks, lane);
            lda4(alof, bAlo, wm, mt, ks, lane);
#pragma unroll
            for (int nt = 0; nt < 4; nt++) {
                mma16816(acc[mt][nt], ahif, bhif + nt * 2);
                mma16816(acc[mt][nt], alof, bhif + nt * 2);
                mma16816(acc[mt][nt], ahif, blof + nt * 2);
            }
        }
    }
}

// single-sync mainloop: wait -> sync -> prefetch(c+1) -> compute(c)
#define GEMM_MAINLOOP()                                                        \
    load_chunk(sbase, 0, Ahi, Alo, Bhi, Blo, rowBase, colBase, 0, tid);        \
    for (int c = 0; c < 32; ++c) {                                             \
        int s = c & 1;                                                         \
        CP_WAIT0();                                                            \
        __syncthreads();                                                       \
        if (c < 31)                                                            \
            load_chunk(sbase, s ^ 1, Ahi, Alo, Bhi, Blo, rowBase, colBase,     \
                       (c + 1) * 32, tid);                                     \
        compute_chunk(acc, sbase + s * STAGE_B, wm, wn, lane);                 \
    }

// --------- G GEMM: C = Wq@Wk^T, epilogue writes Gt hi/lo (transposed) ------
__global__ void __launch_bounds__(256) mma_gemm_g(
    const __nv_bfloat16* __restrict__ Ahi, const __nv_bfloat16* __restrict__ Alo,
    const __nv_bfloat16* __restrict__ Bhi, const __nv_bfloat16* __restrict__ Blo)
{
    extern __shared__ char smem[];
    uint32_t sbase = s2u(smem);
    const int tid  = threadIdx.x;
    const int lane = tid & 31;
    const int wid  = tid >> 5;
    const int wm = (wid >> 2) * 64;
    const int wn = (wid & 3) * 32;
    const int rowBase = blockIdx.x * 128;   // k of Gt
    const int colBase = blockIdx.y * 128;   // n of Gt

    float acc[4][4][4];
#pragma unroll
    for (int i = 0; i < 4; i++)
#pragma unroll
        for (int j = 0; j < 4; j++)
#pragma unroll
            for (int q = 0; q < 4; q++) acc[i][j][q] = 0.f;

    GEMM_MAINLOOP();

    __syncthreads();
#pragma unroll
    for (int mt = 0; mt < 4; mt++) {
        int lr = wm + mt * 16 + (lane >> 2);
#pragma unroll
        for (int nt = 0; nt < 4; nt++) {
            int lc = wn + nt * 8 + (lane & 3) * 2;
            sts2f(sbase + (lr * FPAD + lc) * 4, acc[mt][nt][0], acc[mt][nt][1]);
            sts2f(sbase + ((lr + 8) * FPAD + lc) * 4, acc[mt][nt][2], acc[mt][nt][3]);
        }
    }
    __syncthreads();

    int n_local = tid >> 1;
    int kh = (tid & 1) * 64;
    size_t gbase = (size_t)(colBase + n_local) * DIM + rowBase + kh;
#pragma unroll
    for (int kb = 0; kb < 64; kb += 8) {
        BfPack hp, lp;
#pragma unroll
        for (int i = 0; i < 8; i++) {
            float v = lds1f(sbase + ((kh + kb + i) * FPAD + n_local) * 4);
            __nv_bfloat16 h = __float2bfloat16_rn(v);
            hp.h[i] = h;
            lp.h[i] = __float2bfloat16_rn(v - __bfloat162float(h));
        }
        *(uint4*)(g_GtHi + gbase + kb) = hp.u;
        *(uint4*)(g_GtLo + gbase + kb) = lp.u;
    }
}

// --------------- fused GEMM (Z = X@G) + gram epilogue ----------------------
// grid (8, 256): blockIdx.x = col tile, blockIdx.y = row tile -> co-resident
// CTAs share the same A rows through L2 (A DRAM traffic 1GB -> ~150MB)
__global__ void __launch_bounds__(256, 2) mma_gemm_fused(
    const __nv_bfloat16* __restrict__ Ahi, const __nv_bfloat16* __restrict__ Alo,
    const __nv_bfloat16* __restrict__ Bhi, const __nv_bfloat16* __restrict__ Blo,
    const float* __restrict__ fR, const float* __restrict__ fP)
{
    extern __shared__ char smem[];
    uint32_t sbase = s2u(smem);
    const int tid  = threadIdx.x;
    const int lane = tid & 31;
    const int wid  = tid >> 5;
    const int wm = (wid >> 2) * 64;
    const int wn = (wid & 3) * 32;
    const int rowBase = blockIdx.y * 128;
    const int colBase = blockIdx.x * 128;

    float acc[4][4][4];
#pragma unroll
    for (int i = 0; i < 4; i++)
#pragma unroll
        for (int j = 0; j < 4; j++)
#pragma unroll
            for (int q = 0; q < 4; q++) acc[i][j][q] = 0.f;

    GEMM_MAINLOOP();

    // gram epilogue: row tile = side, batches bb..bb+15, 8 query mols
    const int side = blockIdx.y >> 7;
    const int bb = (blockIdx.y & 127) * 16;
    const float* keys = side ? fP : fR;
    uint32_t zsm = sbase;
    uint32_t fsm = sbase + 64 * FPAD * 4;

#pragma unroll
    for (int pass = 0; pass < 2; pass++) {
        __syncthreads();
        // issue F loads FIRST (latency hidden behind the Z smem stores)
#pragma unroll
        for (int h = 0; h < 8; h++) {
            int idx = h * 256 + tid;
            int rowi = idx >> 5, ch = idx & 31;
            int bl = rowi >> 3, kk2 = rowi & 7;
            const float* src = keys +
                ((size_t)kk2 * BATCH + (bb + pass * 8 + bl)) * DIM + colBase + ch * 4;
            cpa16(fsm + (rowi * FPAD + ch * 4) * 4, src);
        }
        CP_COMMIT();
        if ((wid >> 2) == pass) {
#pragma unroll
            for (int mt = 0; mt < 4; mt++) {
                int lr = mt * 16 + (lane >> 2);
#pragma unroll
                for (int nt = 0; nt < 4; nt++) {
                    int lc = wn + nt * 8 + (lane & 3) * 2;
                    sts2f(zsm + (lr * FPAD + lc) * 4, acc[mt][nt][0], acc[mt][nt][1]);
                    sts2f(zsm + ((lr + 8) * FPAD + lc) * 4, acc[mt][nt][2], acc[mt][nt][3]);
                }
            }
        }
        CP_WAIT0();
        __syncthreads();

        int bl = wid, kk = lane & 7;
#pragma unroll
        for (int i = 0; i < 2; i++) {
            int q = (lane >> 3) + i * 4;
            uint32_t zr = zsm + ((bl * 8 + q) * FPAD) * 4;
            uint32_t fr = fsm + ((bl * 8 + kk) * FPAD) * 4;
            float s = 0.f;
#pragma unroll
            for (int cc = 0; cc < 128; cc += 4) {
                float4 zv = lds4f(zr + cc * 4);
                float4 fv = lds4f(fr + cc * 4);
                s += zv.x * fv.x + zv.y * fv.y + zv.z * fv.z + zv.w * fv.w;
            }
            g_Spart[((size_t)(blockIdx.x * 2 + side) * BATCH + bb + pass * 8 + bl) * 64
                    + lane + 32 * i] = s;
        }
    }
}

// -------------------- softmax / attention outputs --------------------------
__global__ void __launch_bounds__(128) softmax_kernel(float* __restrict__ d_out) {
    const int b = blockIdx.x;
    const int t = threadIdx.x;
    __shared__ float sS[2][MOL][MOL];
    __shared__ float sProb[2][LQ][LQ];
    __shared__ float sAtt[2][LQ];

    {
        int side = t >> 6, e = t & 63;
        float s = 0.f;
#pragma unroll
        for (int ct = 0; ct < 8; ct++)
            s += g_Spart[((size_t)(ct * 2 + side) * BATCH + b) * 64 + e];
        sS[side][e >> 3][e & 7] = s;
    }
    __syncthreads();

    if (t < 2 * LQ) {
        int sd = t / LQ, qq = t % LQ;
        int qi, qj;
        if (qq < MOL) { qi = qq; qj = -1; }
        else          { qi = c_pi[qq - MOL]; qj = c_pj[qq - MOL]; }
        float row[LQ];
        float maxv = -1e30f;
#pragma unroll
        for (int kk = 0; kk < LQ; kk++) {
            int ki, kj;
            if (kk < MOL) { ki = kk; kj = -1; }
            else          { ki = c_pi[kk - MOL]; kj = c_pj[kk - MOL]; }
            float v = sS[sd][qi][ki];
            if (kj >= 0) v += sS[sd][qi][kj];
            if (qj >= 0) {
                v += sS[sd][qj][ki];
                if (kj >= 0) v += sS[sd][qj][kj];
            }
            v *= 0.03125f;
            row[kk] = v;
            maxv = fmaxf(maxv, v);
        }
        float sum = 0.f;
#pragma unroll
        for (int kk = 0; kk < LQ; kk++) { row[kk] = expf(row[kk] - maxv); sum += row[kk]; }
        float inv = 1.f / sum;
#pragma unroll
        for (int kk = 0; kk < LQ; kk++) sProb[sd][qq][kk] = row[kk] * inv;
    }
    __syncthreads();

    if (t < 2 * LQ) {
        int sd = t / LQ, kk = t % LQ;
        float a = 0.f;
#pragma unroll
        for (int qq = 0; qq < LQ; qq++) a += sProb[sd][qq][kk];
        a *= (1.0f / LQ);
        sAtt[sd][kk] = a;
        d_out[BATCH * OUTD + sd * (BATCH * LQ) + b * LQ + kk] = a;
    }
    __syncthreads();

    if (t < 16) {
        int sd = t >> 3, m = t & 7;
        float w = sAtt[sd][m];
#pragma unroll
        for (int pp = 0; pp < NPAIR; pp++)
            if (c_pi[pp] == m || c_pj[pp] == m) w += sAtt[sd][MOL + pp];
        g_w[sd * BATCH * MOL + b * MOL + m] = w;
    }
}

// ------------------------- pooling + head (float4) -------------------------
__global__ void __launch_bounds__(256) pool_kernel(
    const float* __restrict__ r_feats, const float* __restrict__ p_feats,
    const float* __restrict__ r_new,   const float* __restrict__ p_new,
    const float* __restrict__ W_pred,  const float* __restrict__ b_pred,
    float* __restrict__ d_out)
{
    const int b = blockIdx.x;
    const int t = threadIdx.x;
    __shared__ float sw[16];
    __shared__ float sRed[OUTD][8];
    if (t < 16) sw[t] = g_w[(t >> 3) * BATCH * MOL + b * MOL + (t & 7)];
    __syncthreads();

    const int d = t * 4;
    float4 acc = make_float4(0.f, 0.f, 0.f, 0.f);
#pragma unroll
    for (int m = 0; m < MOL; m++) {
        size_t off = ((size_t)m * BATCH + b) * DIM + d;
        float4 a  = *(const float4*)(r_feats + off);
        float4 an = *(const float4*)(r_new + off);
        float4 pv = *(const float4*)(p_feats + off);
        float4 pn = *(const float4*)(p_new + off);
        float wr = sw[m], wp = sw[8 + m];
        acc.x += wr * (a.x + an.x) - wp * (pv.x + pn.x);
        acc.y += wr * (a.y + an.y) - wp * (pv.y + pn.y);
        acc.z += wr * (a.z + an.z) - wp * (pv.z + pn.z);
        acc.w += wr * (a.w + an.w) - wp * (pv.w + pn.w);
    }
    float part[OUTD];
#pragma unroll
    for (int o = 0; o < OUTD; o++) {
        float4 wv = *(const float4*)(W_pred + (size_t)o * DIM + d);
        part[o] = acc.x * wv.x + acc.y * wv.y + acc.z * wv.z + acc.w * wv.w;
    }
    int lane = t & 31, wid = t >> 5;
#pragma unroll
    for (int o = 0; o < OUTD; o++) {
        float v = part[o];
#pragma unroll
        for (int off = 16; off > 0; off >>= 1)
            v += __shfl_down_sync(0xFFFFFFFFu, v, off);
        if (lane == 0) sRed[o][wid] = v;
    }
    __syncthreads();
    if (t < OUTD) {
        float s = 0.f;
#pragma unroll
        for (int w = 0; w < 8; w++) s += sRed[t][w];
        d_out[b * OUTD + t] = s + b_pred[t];
    }
}

// ---------------------------------------------------------------------------
extern "C" void kernel_launch(void* const* d_in, const int* in_sizes, int n_in,
                              void* d_out, int out_size) {
    const float* r_feats = (const float*)d_in[0];
    const float* p_feats = (const float*)d_in[1];
    const float* r_new   = (const float*)d_in[2];
    const float* p_new   = (const float*)d_in[3];
    const float* Wq      = (const float*)d_in[4];
    const float* Wk      = (const float*)d_in[5];
    const float* W_pred  = (const float*)d_in[6];
    const float* b_pred  = (const float*)d_in[7];
    float* out = (float*)d_out;

    cudaFuncSetAttribute(mma_gemm_g, cudaFuncAttributeMaxDynamicSharedMemorySize,
                         SMEM_GEMM);
    cudaFuncSetAttribute(mma_gemm_fused, cudaFuncAttributeMaxDynamicSharedMemorySize,
                         SMEM_GEMM);

    __nv_bfloat16 *WqHi, *WqLo, *WkHi, *WkLo, *GtHi, *GtLo, *Xhi, *Xlo;
    cudaGetSymbolAddress((void**)&WqHi, g_WqHi);
    cudaGetSymbolAddress((void**)&WqLo, g_WqLo);
    cudaGetSymbolAddress((void**)&WkHi, g_WkHi);
    cudaGetSymbolAddress((void**)&WkLo, g_WkLo);
    cudaGetSymbolAddress((void**)&GtHi, g_GtHi);
    cudaGetSymbolAddress((void**)&GtLo, g_GtLo);
    cudaGetSymbolAddress((void**)&Xhi,  g_Xhi);
    cudaGetSymbolAddress((void**)&Xlo,  g_Xlo);

    // 1) weight splits
    split_w<<<2048, 128>>>(Wq, Wk);
    // 2) G = Wq @ Wk^T, epilogue writes Gt hi/lo directly
    mma_gemm_g<<<dim3(8, 8), 256, SMEM_GEMM>>>(WqHi, WqLo, WkHi, WkLo);
    // 3) gather+split X
    split_x<<<MROWS / 2, 256>>>(p_feats, r_feats);
    // 4) fused GEMM + gram epilogue — grid swapped for A reuse in L2
    mma_gemm_fused<<<dim3(8, 256), 256, SMEM_GEMM>>>(Xhi, Xlo, GtHi, GtLo,
                                                     r_feats, p_feats);
    // 5) softmax / attention outputs
    softmax_kernel<<<BATCH, 128>>>(out);
    // 6) pooling + head
    pool_kernel<<<BATCH, 256>>>(r_feats, p_feats, r_new, p_new, W_pred, b_pred, out);
}

// round 9
// speedup vs baseline: 1.0272x; 1.0272x over previous
#include <cuda_runtime.h>
#include <cuda_bf16.h>
#include <cstdint>

constexpr int BATCH = 2048;
constexpr int DIM   = 1024;
constexpr int MOL   = 8;
constexpr int NPAIR = 28;
constexpr int LQ    = 36;
constexpr int OUTD  = 4;
constexpr int MROWS = 32768;           // 2 * BATCH * MOL

__constant__ int c_pi[NPAIR] = {0,0,0,0,0,0,0,1,1,1,1,1,1,2,2,2,2,2,3,3,3,3,4,4,4,5,5,6};
__constant__ int c_pj[NPAIR] = {1,2,3,4,5,6,7,2,3,4,5,6,7,3,4,5,6,7,4,5,6,7,5,6,7,6,7,7};

// ------------------------- static device scratch ---------------------------
__device__ __nv_bfloat16 g_WqHi[DIM * DIM];
__device__ __nv_bfloat16 g_WqLo[DIM * DIM];
__device__ __nv_bfloat16 g_WkHi[DIM * DIM];
__device__ __nv_bfloat16 g_WkLo[DIM * DIM];
__device__ __nv_bfloat16 g_GtHi[DIM * DIM];          // Gt[n][k] = G[k][n]
__device__ __nv_bfloat16 g_GtLo[DIM * DIM];
__device__ __nv_bfloat16 g_Xhi[(size_t)MROWS * DIM]; // 64 MB, row = s*16384+b*8+m
__device__ __nv_bfloat16 g_Xlo[(size_t)MROWS * DIM]; // 64 MB
__device__ float         g_Spart[8ull * 2 * BATCH * 64];  // 4 MB partial grams
__device__ float         g_w[2 * BATCH * MOL];

// ------------------------------ helpers ------------------------------------
__device__ __forceinline__ uint32_t s2u(const void* p) {
    uint32_t a;
    asm("{ .reg .u64 t; cvta.to.shared.u64 t, %1; cvt.u32.u64 %0, t; }" : "=r"(a) : "l"(p));
    return a;
}
__device__ __forceinline__ void cpa16(uint32_t d, const void* g) {
    asm volatile("cp.async.cg.shared.global [%0], [%1], 16;" :: "r"(d), "l"(g));
}
#define CP_COMMIT()  asm volatile("cp.async.commit_group;" ::: "memory")
#define CP_WAIT0()   asm volatile("cp.async.wait_group 0;" ::: "memory")

__device__ __forceinline__ float4 lds4f(uint32_t a) {
    float4 v;
    asm volatile("ld.shared.v4.f32 {%0,%1,%2,%3}, [%4];"
        : "=f"(v.x), "=f"(v.y), "=f"(v.z), "=f"(v.w) : "r"(a));
    return v;
}
__device__ __forceinline__ float lds1f(uint32_t a) {
    float v;
    asm volatile("ld.shared.f32 %0, [%1];" : "=f"(v) : "r"(a));
    return v;
}
__device__ __forceinline__ void sts2f(uint32_t a, float x, float y) {
    asm volatile("st.shared.v2.f32 [%0], {%1,%2};" :: "r"(a), "f"(x), "f"(y));
}

__device__ __forceinline__ void lda4(uint32_t* f, uint32_t mbase, int wm, int mt,
                                     int ks, int lane) {
    int g = lane >> 3, r = lane & 7;
    int mloc = wm + mt * 16 + (g & 1) * 8 + r;
    int kloc = ks * 16 + (g >> 1) * 8;
    uint32_t a = mbase + (mloc * 40 + kloc) * 2;
    asm volatile("ldmatrix.sync.aligned.m8n8.x4.shared.b16 {%0,%1,%2,%3}, [%4];"
        : "=r"(f[0]), "=r"(f[1]), "=r"(f[2]), "=r"(f[3]) : "r"(a));
}
// B fragments for TWO adjacent nt tiles in one x4
__device__ __forceinline__ void ldb4(uint32_t* f, uint32_t mbase, int wn, int ntp,
                                     int ks, int lane) {
    int g = lane >> 3, r = lane & 7;
    int nloc = wn + ntp * 16 + (g >> 1) * 8 + r;
    int kloc = ks * 16 + (g & 1) * 8;
    uint32_t a = mbase + (nloc * 40 + kloc) * 2;
    asm volatile("ldmatrix.sync.aligned.m8n8.x4.shared.b16 {%0,%1,%2,%3}, [%4];"
        : "=r"(f[0]), "=r"(f[1]), "=r"(f[2]), "=r"(f[3]) : "r"(a));
}
__device__ __forceinline__ void mma16816(float* c, const uint32_t* a, const uint32_t* b) {
    asm volatile("mma.sync.aligned.m16n8k16.row.col.f32.bf16.bf16.f32 "
        "{%0,%1,%2,%3}, {%4,%5,%6,%7}, {%8,%9}, {%0,%1,%2,%3};"
        : "+f"(c[0]), "+f"(c[1]), "+f"(c[2]), "+f"(c[3])
        : "r"(a[0]), "r"(a[1]), "r"(a[2]), "r"(a[3]), "r"(b[0]), "r"(b[1]));
}

union BfPack { __nv_bfloat16 h[8]; uint4 u; };

// ------------------------- split kernels -----------------------------------
__global__ void __launch_bounds__(128) split_w(const float* __restrict__ Wq,
                                               const float* __restrict__ Wk) {
    int bx = blockIdx.x;
    int mat = bx >> 10, row = bx & 1023;
    const float* src = (mat ? Wk : Wq) + (size_t)row * DIM;
    __nv_bfloat16* hi = (mat ? g_WkHi : g_WqHi) + (size_t)row * DIM;
    __nv_bfloat16* lo = (mat ? g_WkLo : g_WqLo) + (size_t)row * DIM;
    int t = threadIdx.x;
    float4 v0 = ((const float4*)src)[t * 2];
    float4 v1 = ((const float4*)src)[t * 2 + 1];
    float vv[8] = {v0.x, v0.y, v0.z, v0.w, v1.x, v1.y, v1.z, v1.w};
    BfPack hp, lp;
#pragma unroll
    for (int i = 0; i < 8; i++) {
        __nv_bfloat16 h = __float2bfloat16_rn(vv[i]);
        hp.h[i] = h;
        lp.h[i] = __float2bfloat16_rn(vv[i] - __bfloat162float(h));
    }
    ((uint4*)(hi))[t] = hp.u;
    ((uint4*)(lo))[t] = lp.u;
}

__global__ void __launch_bounds__(256) split_x(const float* __restrict__ p,
                                               const float* __restrict__ r) {
    int t = threadIdx.x;
    int row = blockIdx.x * 2 + (t >> 7);
    int tt = t & 127;
    int s = row >> 14, b = (row >> 3) & (BATCH - 1), m = row & 7;
    const float* src = (s ? r : p) + ((size_t)m * BATCH + b) * DIM;
    float4 v0 = ((const float4*)src)[tt * 2];
    float4 v1 = ((const float4*)src)[tt * 2 + 1];
    float vv[8] = {v0.x, v0.y, v0.z, v0.w, v1.x, v1.y, v1.z, v1.w};
    BfPack hp, lp;
#pragma unroll
    for (int i = 0; i < 8; i++) {
        __nv_bfloat16 h = __float2bfloat16_rn(vv[i]);
        hp.h[i] = h;
        lp.h[i] = __float2bfloat16_rn(vv[i] - __bfloat162float(h));
    }
    ((uint4*)(g_Xhi + (size_t)row * DIM))[tt] = hp.u;
    ((uint4*)(g_Xlo + (size_t)row * DIM))[tt] = lp.u;
}

// ------------------------- shared GEMM machinery ---------------------------
constexpr int MAT_ELE   = 128 * 40;
constexpr int STAGE_B   = 4 * MAT_ELE * 2;      // 40960 bytes
constexpr int SMEM_GEMM = 2 * STAGE_B;          // 81920 bytes
constexpr int FPAD      = 132;

__device__ __forceinline__ void load_chunk(
    uint32_t sbase, int stage,
    const __nv_bfloat16* __restrict__ Ahi, const __nv_bfloat16* __restrict__ Alo,
    const __nv_bfloat16* __restrict__ Bhi, const __nv_bfloat16* __restrict__ Blo,
    int rowBase, int colBase, int k0, int tid)
{
    uint32_t st = sbase + stage * STAGE_B;
#pragma unroll
    for (int mat = 0; mat < 4; mat++) {
        const __nv_bfloat16* src0 =
            (mat == 0) ? Ahi : (mat == 1) ? Alo : (mat == 2) ? Bhi : Blo;
        int base = (mat < 2) ? rowBase : colBase;
#pragma unroll
        for (int h = 0; h < 2; h++) {
            int idx = h * 256 + tid;
            int row = idx >> 2, ch = idx & 3;
            const __nv_bfloat16* src = src0 + (size_t)(base + row) * DIM + k0 + ch * 8;
            uint32_t dst = st + (mat * MAT_ELE + row * 40 + ch * 8) * 2;
            cpa16(dst, src);
        }
    }
    CP_COMMIT();
}

// one k32 chunk: B frags (x4-batched) held, A streamed per mt
__device__ __forceinline__ void compute_chunk(
    float acc[4][4][4], uint32_t stb, int wm, int wn, int lane)
{
    uint32_t bAhi = stb;
    uint32_t bAlo = stb + MAT_ELE * 2;
    uint32_t bBhi = stb + 2 * MAT_ELE * 2;
    uint32_t bBlo = stb + 3 * MAT_ELE * 2;
#pragma unroll
    for (int ks = 0; ks < 2; ks++) {
        uint32_t bhif[8], blof[8];
        ldb4(bhif,     bBhi, wn, 0, ks, lane);
        ldb4(bhif + 4, bBhi, wn, 1, ks, lane);
        ldb4(blof,     bBlo, wn, 0, ks, lane);
        ldb4(blof + 4, bBlo, wn, 1, ks, lane);
#pragma unroll
        for (int mt = 0; mt < 4; mt++) {
            uint32_t ahif[4], alof[4];
            lda4(ahif, bAhi, wm, mt, ks, lane);
            lda4(alof, bAlo, wm, mt, ks, lane);
#pragma unroll
            for (int nt = 0; nt < 4; nt++) {
                mma16816(acc[mt][nt], ahif, bhif + nt * 2);
                mma16816(acc[mt][nt], alof, bhif + nt * 2);
                mma16816(acc[mt][nt], ahif, blof + nt * 2);
            }
        }
    }
}

// single-sync mainloop: wait -> sync -> prefetch(c+1) -> compute(c)
#define GEMM_MAINLOOP()                                                        \
    load_chunk(sbase, 0, Ahi, Alo, Bhi, Blo, rowBase, colBase, 0, tid);        \
    for (int c = 0; c < 32; ++c) {                                             \
        int s = c & 1;                                                         \
        CP_WAIT0();                                                            \
        __syncthreads();                                                       \
        if (c < 31)                                                            \
            load_chunk(sbase, s ^ 1, Ahi, Alo, Bhi, Blo, rowBase, colBase,     \
                       (c + 1) * 32, tid);                                     \
        compute_chunk(acc, sbase + s * STAGE_B, wm, wn, lane);                 \
    }

// --------- G GEMM: C = Wq@Wk^T, epilogue writes Gt hi/lo (transposed) ------
__global__ void __launch_bounds__(256) mma_gemm_g(
    const __nv_bfloat16* __restrict__ Ahi, const __nv_bfloat16* __restrict__ Alo,
    const __nv_bfloat16* __restrict__ Bhi, const __nv_bfloat16* __restrict__ Blo)
{
    extern __shared__ char smem[];
    uint32_t sbase = s2u(smem);
    const int tid  = threadIdx.x;
    const int lane = tid & 31;
    const int wid  = tid >> 5;
    const int wm = (wid >> 2) * 64;
    const int wn = (wid & 3) * 32;
    const int rowBase = blockIdx.x * 128;   // k of Gt
    const int colBase = blockIdx.y * 128;   // n of Gt

    float acc[4][4][4];
#pragma unroll
    for (int i = 0; i < 4; i++)
#pragma unroll
        for (int j = 0; j < 4; j++)
#pragma unroll
            for (int q = 0; q < 4; q++) acc[i][j][q] = 0.f;

    GEMM_MAINLOOP();

    __syncthreads();
#pragma unroll
    for (int mt = 0; mt < 4; mt++) {
        int lr = wm + mt * 16 + (lane >> 2);
#pragma unroll
        for (int nt = 0; nt < 4; nt++) {
            int lc = wn + nt * 8 + (lane & 3) * 2;
            sts2f(sbase + (lr * FPAD + lc) * 4, acc[mt][nt][0], acc[mt][nt][1]);
            sts2f(sbase + ((lr + 8) * FPAD + lc) * 4, acc[mt][nt][2], acc[mt][nt][3]);
        }
    }
    __syncthreads();

    int n_local = tid >> 1;
    int kh = (tid & 1) * 64;
    size_t gbase = (size_t)(colBase + n_local) * DIM + rowBase + kh;
#pragma unroll
    for (int kb = 0; kb < 64; kb += 8) {
        BfPack hp, lp;
#pragma unroll
        for (int i = 0; i < 8; i++) {
            float v = lds1f(sbase + ((kh + kb + i) * FPAD + n_local) * 4);
            __nv_bfloat16 h = __float2bfloat16_rn(v);
            hp.h[i] = h;
            lp.h[i] = __float2bfloat16_rn(v - __bfloat162float(h));
        }
        *(uint4*)(g_GtHi + gbase + kb) = hp.u;
        *(uint4*)(g_GtLo + gbase + kb) = lp.u;
    }
}

// --------------- fused GEMM (Z = X@G) + gram epilogue ----------------------
// grid (256, 8): row tile fastest (measured faster than col-fast in R8)
__global__ void __launch_bounds__(256, 2) mma_gemm_fused(
    const __nv_bfloat16* __restrict__ Ahi, const __nv_bfloat16* __restrict__ Alo,
    const __nv_bfloat16* __restrict__ Bhi, const __nv_bfloat16* __restrict__ Blo,
    const float* __restrict__ fR, const float* __restrict__ fP)
{
    extern __shared__ char smem[];
    uint32_t sbase = s2u(smem);
    const int tid  = threadIdx.x;
    const int lane = tid & 31;
    const int wid  = tid >> 5;
    const int wm = (wid >> 2) * 64;
    const int wn = (wid & 3) * 32;
    const int rowBase = blockIdx.x * 128;
    const int colBase = blockIdx.y * 128;

    float acc[4][4][4];
#pragma unroll
    for (int i = 0; i < 4; i++)
#pragma unroll
        for (int j = 0; j < 4; j++)
#pragma unroll
            for (int q = 0; q < 4; q++) acc[i][j][q] = 0.f;

    GEMM_MAINLOOP();

    // gram epilogue: row tile = side, batches bb..bb+15, 8 query mols
    const int side = blockIdx.x >> 7;
    const int bb = (blockIdx.x & 127) * 16;
    const float* keys = side ? fP : fR;
    uint32_t zsm = sbase;
    uint32_t fsm = sbase + 64 * FPAD * 4;

#pragma unroll
    for (int pass = 0; pass < 2; pass++) {
        __syncthreads();
        // F loads first (latency hidden behind Z smem stores)
#pragma unroll
        for (int h = 0; h < 8; h++) {
            int idx = h * 256 + tid;
            int rowi = idx >> 5, ch = idx & 31;
            int bl = rowi >> 3, kk2 = rowi & 7;
            const float* src = keys +
                ((size_t)kk2 * BATCH + (bb + pass * 8 + bl)) * DIM + colBase + ch * 4;
            cpa16(fsm + (rowi * FPAD + ch * 4) * 4, src);
        }
        CP_COMMIT();
        if ((wid >> 2) == pass) {
#pragma unroll
            for (int mt = 0; mt < 4; mt++) {
                int lr = mt * 16 + (lane >> 2);
#pragma unroll
                for (int nt = 0; nt < 4; nt++) {
                    int lc = wn + nt * 8 + (lane & 3) * 2;
                    sts2f(zsm + (lr * FPAD + lc) * 4, acc[mt][nt][0], acc[mt][nt][1]);
                    sts2f(zsm + ((lr + 8) * FPAD + lc) * 4, acc[mt][nt][2], acc[mt][nt][3]);
                }
            }
        }
        CP_WAIT0();
        __syncthreads();

        // 2x2-blocked gram: lane -> (2q x 2k) block over half the D-range
        int bl = wid;
        int hh = lane >> 4;           // cc half
        int q0 = ((lane >> 2) & 3) * 2;
        int k0 = (lane & 3) * 2;
        uint32_t z0 = zsm + ((bl * 8 + q0) * FPAD + hh * 64) * 4;
        uint32_t z1 = z0 + FPAD * 4;
        uint32_t f0 = fsm + ((bl * 8 + k0) * FPAD + hh * 64) * 4;
        uint32_t f1 = f0 + FPAD * 4;
        float s00 = 0.f, s01 = 0.f, s10 = 0.f, s11 = 0.f;
#pragma unroll
        for (int cc = 0; cc < 64; cc += 4) {
            float4 a0 = lds4f(z0 + cc * 4);
            float4 a1 = lds4f(z1 + cc * 4);
            float4 b0 = lds4f(f0 + cc * 4);
            float4 b1 = lds4f(f1 + cc * 4);
            s00 += a0.x * b0.x + a0.y * b0.y + a0.z * b0.z + a0.w * b0.w;
            s01 += a0.x * b1.x + a0.y * b1.y + a0.z * b1.z + a0.w * b1.w;
            s10 += a1.x * b0.x + a1.y * b0.y + a1.z * b0.z + a1.w * b0.w;
            s11 += a1.x * b1.x + a1.y * b1.y + a1.z * b1.z + a1.w * b1.w;
        }
        s00 += __shfl_xor_sync(0xFFFFFFFFu, s00, 16);
        s01 += __shfl_xor_sync(0xFFFFFFFFu, s01, 16);
        s10 += __shfl_xor_sync(0xFFFFFFFFu, s10, 16);
        s11 += __shfl_xor_sync(0xFFFFFFFFu, s11, 16);
        if (hh == 0) {
            size_t base = ((size_t)(blockIdx.y * 2 + side) * BATCH
                           + bb + pass * 8 + bl) * 64;
            g_Spart[base + q0 * 8 + k0]           = s00;
            g_Spart[base + q0 * 8 + k0 + 1]       = s01;
            g_Spart[base + (q0 + 1) * 8 + k0]     = s10;
            g_Spart[base + (q0 + 1) * 8 + k0 + 1] = s11;
        }
    }
}

// -------------------- softmax / attention outputs --------------------------
__global__ void __launch_bounds__(128) softmax_kernel(float* __restrict__ d_out) {
    const int b = blockIdx.x;
    const int t = threadIdx.x;
    __shared__ float sS[2][MOL][MOL];
    __shared__ float sProb[2][LQ][LQ];
    __shared__ float sAtt[2][LQ];

    {
        int side = t >> 6, e = t & 63;
        float s = 0.f;
#pragma unroll
        for (int ct = 0; ct < 8; ct++)
            s += g_Spart[((size_t)(ct * 2 + side) * BATCH + b) * 64 + e];
        sS[side][e >> 3][e & 7] = s;
    }
    __syncthreads();

    if (t < 2 * LQ) {
        int sd = t / LQ, qq = t % LQ;
        int qi, qj;
        if (qq < MOL) { qi = qq; qj = -1; }
        else          { qi = c_pi[qq - MOL]; qj = c_pj[qq - MOL]; }
        float row[LQ];
        float maxv = -1e30f;
#pragma unroll
        for (int kk = 0; kk < LQ; kk++) {
            int ki, kj;
            if (kk < MOL) { ki = kk; kj = -1; }
            else          { ki = c_pi[kk - MOL]; kj = c_pj[kk - MOL]; }
            float v = sS[sd][qi][ki];
            if (kj >= 0) v += sS[sd][qi][kj];
            if (qj >= 0) {
                v += sS[sd][qj][ki];
                if (kj >= 0) v += sS[sd][qj][kj];
            }
            v *= 0.03125f;
            row[kk] = v;
            maxv = fmaxf(maxv, v);
        }
        float sum = 0.f;
#pragma unroll
        for (int kk = 0; kk < LQ; kk++) { row[kk] = expf(row[kk] - maxv); sum += row[kk]; }
        float inv = 1.f / sum;
#pragma unroll
        for (int kk = 0; kk < LQ; kk++) sProb[sd][qq][kk] = row[kk] * inv;
    }
    __syncthreads();

    if (t < 2 * LQ) {
        int sd = t / LQ, kk = t % LQ;
        float a = 0.f;
#pragma unroll
        for (int qq = 0; qq < LQ; qq++) a += sProb[sd][qq][kk];
        a *= (1.0f / LQ);
        sAtt[sd][kk] = a;
        d_out[BATCH * OUTD + sd * (BATCH * LQ) + b * LQ + kk] = a;
    }
    __syncthreads();

    if (t < 16) {
        int sd = t >> 3, m = t & 7;
        float w = sAtt[sd][m];
#pragma unroll
        for (int pp = 0; pp < NPAIR; pp++)
            if (c_pi[pp] == m || c_pj[pp] == m) w += sAtt[sd][MOL + pp];
        g_w[sd * BATCH * MOL + b * MOL + m] = w;
    }
}

// ------------------------- pooling + head (float4) -------------------------
__global__ void __launch_bounds__(256) pool_kernel(
    const float* __restrict__ r_feats, const float* __restrict__ p_feats,
    const float* __restrict__ r_new,   const float* __restrict__ p_new,
    const float* __restrict__ W_pred,  const float* __restrict__ b_pred,
    float* __restrict__ d_out)
{
    const int b = blockIdx.x;
    const int t = threadIdx.x;
    __shared__ float sw[16];
    __shared__ float sRed[OUTD][8];
    if (t < 16) sw[t] = g_w[(t >> 3) * BATCH * MOL + b * MOL + (t & 7)];
    __syncthreads();

    const int d = t * 4;
    float4 acc = make_float4(0.f, 0.f, 0.f, 0.f);
#pragma unroll
    for (int m = 0; m < MOL; m++) {
        size_t off = ((size_t)m * BATCH + b) * DIM + d;
        float4 a  = *(const float4*)(r_feats + off);
        float4 an = *(const float4*)(r_new + off);
        float4 pv = *(const float4*)(p_feats + off);
        float4 pn = *(const float4*)(p_new + off);
        float wr = sw[m], wp = sw[8 + m];
        acc.x += wr * (a.x + an.x) - wp * (pv.x + pn.x);
        acc.y += wr * (a.y + an.y) - wp * (pv.y + pn.y);
        acc.z += wr * (a.z + an.z) - wp * (pv.z + pn.z);
        acc.w += wr * (a.w + an.w) - wp * (pv.w + pn.w);
    }
    float part[OUTD];
#pragma unroll
    for (int o = 0; o < OUTD; o++) {
        float4 wv = *(const float4*)(W_pred + (size_t)o * DIM + d);
        part[o] = acc.x * wv.x + acc.y * wv.y + acc.z * wv.z + acc.w * wv.w;
    }
    int lane = t & 31, wid = t >> 5;
#pragma unroll
    for (int o = 0; o < OUTD; o++) {
        float v = part[o];
#pragma unroll
        for (int off = 16; off > 0; off >>= 1)
            v += __shfl_down_sync(0xFFFFFFFFu, v, off);
        if (lane == 0) sRed[o][wid] = v;
    }
    __syncthreads();
    if (t < OUTD) {
        float s = 0.f;
#pragma unroll
        for (int w = 0; w < 8; w++) s += sRed[t][w];
        d_out[b * OUTD + t] = s + b_pred[t];
    }
}

// ---------------------------------------------------------------------------
extern "C" void kernel_launch(void* const* d_in, const int* in_sizes, int n_in,
                              void* d_out, int out_size) {
    const float* r_feats = (const float*)d_in[0];
    const float* p_feats = (const float*)d_in[1];
    const float* r_new   = (const float*)d_in[2];
    const float* p_new   = (const float*)d_in[3];
    const float* Wq      = (const float*)d_in[4];
    const float* Wk      = (const float*)d_in[5];
    const float* W_pred  = (const float*)d_in[6];
    const float* b_pred  = (const float*)d_in[7];
    float* out = (float*)d_out;

    cudaFuncSetAttribute(mma_gemm_g, cudaFuncAttributeMaxDynamicSharedMemorySize,
                         SMEM_GEMM);
    cudaFuncSetAttribute(mma_gemm_fused, cudaFuncAttributeMaxDynamicSharedMemorySize,
                         SMEM_GEMM);

    __nv_bfloat16 *WqHi, *WqLo, *WkHi, *WkLo, *GtHi, *GtLo, *Xhi, *Xlo;
    cudaGetSymbolAddress((void**)&WqHi, g_WqHi);
    cudaGetSymbolAddress((void**)&WqLo, g_WqLo);
    cudaGetSymbolAddress((void**)&WkHi, g_WkHi);
    cudaGetSymbolAddress((void**)&WkLo, g_WkLo);
    cudaGetSymbolAddress((void**)&GtHi, g_GtHi);
    cudaGetSymbolAddress((void**)&GtLo, g_GtLo);
    cudaGetSymbolAddress((void**)&Xhi,  g_Xhi);
    cudaGetSymbolAddress((void**)&Xlo,  g_Xlo);

    // 1) weight splits
    split_w<<<2048, 128>>>(Wq, Wk);
    // 2) G = Wq @ Wk^T, epilogue writes Gt hi/lo directly
    mma_gemm_g<<<dim3(8, 8), 256, SMEM_GEMM>>>(WqHi, WqLo, WkHi, WkLo);
    // 3) gather+split X
    split_x<<<MROWS / 2, 256>>>(p_feats, r_feats);
    // 4) fused GEMM + gram epilogue — row-fast grid (fastest measured)
    mma_gemm_fused<<<dim3(256, 8), 256, SMEM_GEMM>>>(Xhi, Xlo, GtHi, GtLo,
                                                     r_feats, p_feats);
    // 5) softmax / attention outputs
    softmax_kernel<<<BATCH, 128>>>(out);
    // 6) pooling + head
    pool_kernel<<<BATCH, 256>>>(r_feats, p_feats, r_new, p_new, W_pred, b_pred, out);
}

// round 10
// speedup vs baseline: 1.0589x; 1.0309x over previous
#include <cuda_runtime.h>
#include <cuda_bf16.h>
#include <cstdint>

constexpr int BATCH = 2048;
constexpr int DIM   = 1024;
constexpr int MOL   = 8;
constexpr int NPAIR = 28;
constexpr int LQ    = 36;
constexpr int OUTD  = 4;
constexpr int MROWS = 32768;           // 2 * BATCH * MOL

__constant__ int c_pi[NPAIR] = {0,0,0,0,0,0,0,1,1,1,1,1,1,2,2,2,2,2,3,3,3,3,4,4,4,5,5,6};
__constant__ int c_pj[NPAIR] = {1,2,3,4,5,6,7,2,3,4,5,6,7,3,4,5,6,7,4,5,6,7,5,6,7,6,7,7};

// ------------------------- static device scratch ---------------------------
__device__ __nv_bfloat16 g_WqHi[DIM * DIM];
__device__ __nv_bfloat16 g_WqLo[DIM * DIM];
__device__ __nv_bfloat16 g_WkHi[DIM * DIM];
__device__ __nv_bfloat16 g_WkLo[DIM * DIM];
__device__ __nv_bfloat16 g_GtHi[DIM * DIM];          // Gt[n][k] = G[k][n]
__device__ __nv_bfloat16 g_GtLo[DIM * DIM];
__device__ __nv_bfloat16 g_Xhi[(size_t)MROWS * DIM]; // 64 MB, row = s*16384+b*8+m
__device__ __nv_bfloat16 g_Xlo[(size_t)MROWS * DIM]; // 64 MB
__device__ float         g_Spart[8ull * 2 * BATCH * 64];  // 4 MB partial grams

// ------------------------------ helpers ------------------------------------
__device__ __forceinline__ uint32_t s2u(const void* p) {
    uint32_t a;
    asm("{ .reg .u64 t; cvta.to.shared.u64 t, %1; cvt.u32.u64 %0, t; }" : "=r"(a) : "l"(p));
    return a;
}
__device__ __forceinline__ void cpa16(uint32_t d, const void* g) {
    asm volatile("cp.async.cg.shared.global [%0], [%1], 16;" :: "r"(d), "l"(g));
}
#define CP_COMMIT()  asm volatile("cp.async.commit_group;" ::: "memory")
#define CP_WAIT0()   asm volatile("cp.async.wait_group 0;" ::: "memory")

__device__ __forceinline__ float4 lds4f(uint32_t a) {
    float4 v;
    asm volatile("ld.shared.v4.f32 {%0,%1,%2,%3}, [%4];"
        : "=f"(v.x), "=f"(v.y), "=f"(v.z), "=f"(v.w) : "r"(a));
    return v;
}
__device__ __forceinline__ float lds1f(uint32_t a) {
    float v;
    asm volatile("ld.shared.f32 %0, [%1];" : "=f"(v) : "r"(a));
    return v;
}
__device__ __forceinline__ void sts2f(uint32_t a, float x, float y) {
    asm volatile("st.shared.v2.f32 [%0], {%1,%2};" :: "r"(a), "f"(x), "f"(y));
}

__device__ __forceinline__ void lda4(uint32_t* f, uint32_t mbase, int wm, int mt,
                                     int ks, int lane) {
    int g = lane >> 3, r = lane & 7;
    int mloc = wm + mt * 16 + (g & 1) * 8 + r;
    int kloc = ks * 16 + (g >> 1) * 8;
    uint32_t a = mbase + (mloc * 40 + kloc) * 2;
    asm volatile("ldmatrix.sync.aligned.m8n8.x4.shared.b16 {%0,%1,%2,%3}, [%4];"
        : "=r"(f[0]), "=r"(f[1]), "=r"(f[2]), "=r"(f[3]) : "r"(a));
}
// B fragments for TWO adjacent nt tiles in one x4
__device__ __forceinline__ void ldb4(uint32_t* f, uint32_t mbase, int wn, int ntp,
                                     int ks, int lane) {
    int g = lane >> 3, r = lane & 7;
    int nloc = wn + ntp * 16 + (g >> 1) * 8 + r;
    int kloc = ks * 16 + (g & 1) * 8;
    uint32_t a = mbase + (nloc * 40 + kloc) * 2;
    asm volatile("ldmatrix.sync.aligned.m8n8.x4.shared.b16 {%0,%1,%2,%3}, [%4];"
        : "=r"(f[0]), "=r"(f[1]), "=r"(f[2]), "=r"(f[3]) : "r"(a));
}
__device__ __forceinline__ void mma16816(float* c, const uint32_t* a, const uint32_t* b) {
    asm volatile("mma.sync.aligned.m16n8k16.row.col.f32.bf16.bf16.f32 "
        "{%0,%1,%2,%3}, {%4,%5,%6,%7}, {%8,%9}, {%0,%1,%2,%3};"
        : "+f"(c[0]), "+f"(c[1]), "+f"(c[2]), "+f"(c[3])
        : "r"(a[0]), "r"(a[1]), "r"(a[2]), "r"(a[3]), "r"(b[0]), "r"(b[1]));
}

union BfPack { __nv_bfloat16 h[8]; uint4 u; };

// ------------------------- split_w kernel ----------------------------------
__global__ void __launch_bounds__(128) split_w(const float* __restrict__ Wq,
                                               const float* __restrict__ Wk) {
    int bx = blockIdx.x;
    int mat = bx >> 10, row = bx & 1023;
    const float* src = (mat ? Wk : Wq) + (size_t)row * DIM;
    __nv_bfloat16* hi = (mat ? g_WkHi : g_WqHi) + (size_t)row * DIM;
    __nv_bfloat16* lo = (mat ? g_WkLo : g_WqLo) + (size_t)row * DIM;
    int t = threadIdx.x;
    float4 v0 = ((const float4*)src)[t * 2];
    float4 v1 = ((const float4*)src)[t * 2 + 1];
    float vv[8] = {v0.x, v0.y, v0.z, v0.w, v1.x, v1.y, v1.z, v1.w};
    BfPack hp, lp;
#pragma unroll
    for (int i = 0; i < 8; i++) {
        __nv_bfloat16 h = __float2bfloat16_rn(vv[i]);
        hp.h[i] = h;
        lp.h[i] = __float2bfloat16_rn(vv[i] - __bfloat162float(h));
    }
    ((uint4*)(hi))[t] = hp.u;
    ((uint4*)(lo))[t] = lp.u;
}

// ------------------------- shared GEMM machinery ---------------------------
constexpr int MAT_ELE   = 128 * 40;
constexpr int STAGE_B   = 4 * MAT_ELE * 2;      // 40960 bytes
constexpr int SMEM_GEMM = 2 * STAGE_B;          // 81920 bytes
constexpr int FPAD      = 132;

__device__ __forceinline__ void load_chunk(
    uint32_t sbase, int stage,
    const __nv_bfloat16* __restrict__ Ahi, const __nv_bfloat16* __restrict__ Alo,
    const __nv_bfloat16* __restrict__ Bhi, const __nv_bfloat16* __restrict__ Blo,
    int rowBase, int colBase, int k0, int tid)
{
    uint32_t st = sbase + stage * STAGE_B;
#pragma unroll
    for (int mat = 0; mat < 4; mat++) {
        const __nv_bfloat16* src0 =
            (mat == 0) ? Ahi : (mat == 1) ? Alo : (mat == 2) ? Bhi : Blo;
        int base = (mat < 2) ? rowBase : colBase;
#pragma unroll
        for (int h = 0; h < 2; h++) {
            int idx = h * 256 + tid;
            int row = idx >> 2, ch = idx & 3;
            const __nv_bfloat16* src = src0 + (size_t)(base + row) * DIM + k0 + ch * 8;
            uint32_t dst = st + (mat * MAT_ELE + row * 40 + ch * 8) * 2;
            cpa16(dst, src);
        }
    }
    CP_COMMIT();
}

// one k32 chunk; warp-group 1 traverses ks in reverse to de-burst LDSM
__device__ __forceinline__ void compute_chunk(
    float acc[4][4][4], uint32_t stb, int wm, int wn, int lane, int swap)
{
    uint32_t bAhi = stb;
    uint32_t bAlo = stb + MAT_ELE * 2;
    uint32_t bBhi = stb + 2 * MAT_ELE * 2;
    uint32_t bBlo = stb + 3 * MAT_ELE * 2;
#pragma unroll
    for (int ks2 = 0; ks2 < 2; ks2++) {
        int ks = swap ? (1 - ks2) : ks2;
        uint32_t bhif[8], blof[8];
        ldb4(bhif,     bBhi, wn, 0, ks, lane);
        ldb4(bhif + 4, bBhi, wn, 1, ks, lane);
        ldb4(blof,     bBlo, wn, 0, ks, lane);
        ldb4(blof + 4, bBlo, wn, 1, ks, lane);
#pragma unroll
        for (int mt = 0; mt < 4; mt++) {
            uint32_t ahif[4], alof[4];
            lda4(ahif, bAhi, wm, mt, ks, lane);
            lda4(alof, bAlo, wm, mt, ks, lane);
#pragma unroll
            for (int nt = 0; nt < 4; nt++) {
                mma16816(acc[mt][nt], ahif, bhif + nt * 2);
                mma16816(acc[mt][nt], alof, bhif + nt * 2);
                mma16816(acc[mt][nt], ahif, blof + nt * 2);
            }
        }
    }
}

// single-sync mainloop: wait -> sync -> prefetch(c+1) -> compute(c)
#define GEMM_MAINLOOP()                                                        \
    load_chunk(sbase, 0, Ahi, Alo, Bhi, Blo, rowBase, colBase, 0, tid);        \
    for (int c = 0; c < 32; ++c) {                                             \
        int s = c & 1;                                                         \
        CP_WAIT0();                                                            \
        __syncthreads();                                                       \
        if (c < 31)                                                            \
            load_chunk(sbase, s ^ 1, Ahi, Alo, Bhi, Blo, rowBase, colBase,     \
                       (c + 1) * 32, tid);                                     \
        compute_chunk(acc, sbase + s * STAGE_B, wm, wn, lane, wid >> 2);       \
    }

// --------- G GEMM body: C = Wq@Wk^T, epilogue writes Gt hi/lo --------------
__device__ void gemm_g_body(
    const __nv_bfloat16* __restrict__ Ahi, const __nv_bfloat16* __restrict__ Alo,
    const __nv_bfloat16* __restrict__ Bhi, const __nv_bfloat16* __restrict__ Blo,
    int gb)
{
    extern __shared__ char smem[];
    uint32_t sbase = s2u(smem);
    const int tid  = threadIdx.x;
    const int lane = tid & 31;
    const int wid  = tid >> 5;
    const int wm = (wid >> 2) * 64;
    const int wn = (wid & 3) * 32;
    const int rowBase = (gb & 7) * 128;   // k of Gt
    const int colBase = (gb >> 3) * 128;  // n of Gt

    float acc[4][4][4];
#pragma unroll
    for (int i = 0; i < 4; i++)
#pragma unroll
        for (int j = 0; j < 4; j++)
#pragma unroll
            for (int q = 0; q < 4; q++) acc[i][j][q] = 0.f;

    GEMM_MAINLOOP();

    __syncthreads();
#pragma unroll
    for (int mt = 0; mt < 4; mt++) {
        int lr = wm + mt * 16 + (lane >> 2);
#pragma unroll
        for (int nt = 0; nt < 4; nt++) {
            int lc = wn + nt * 8 + (lane & 3) * 2;
            sts2f(sbase + (lr * FPAD + lc) * 4, acc[mt][nt][0], acc[mt][nt][1]);
            sts2f(sbase + ((lr + 8) * FPAD + lc) * 4, acc[mt][nt][2], acc[mt][nt][3]);
        }
    }
    __syncthreads();

    int n_local = tid >> 1;
    int kh = (tid & 1) * 64;
    size_t gbase = (size_t)(colBase + n_local) * DIM + rowBase + kh;
#pragma unroll
    for (int kb = 0; kb < 64; kb += 8) {
        BfPack hp, lp;
#pragma unroll
        for (int i = 0; i < 8; i++) {
            float v = lds1f(sbase + ((kh + kb + i) * FPAD + n_local) * 4);
            __nv_bfloat16 h = __float2bfloat16_rn(v);
            hp.h[i] = h;
            lp.h[i] = __float2bfloat16_rn(v - __bfloat162float(h));
        }
        *(uint4*)(g_GtHi + gbase + kb) = hp.u;
        *(uint4*)(g_GtLo + gbase + kb) = lp.u;
    }
}

// --------- split_x body: gather + fp32->bf16 hi/lo split --------------------
__device__ void split_x_body(const float* __restrict__ p,
                             const float* __restrict__ r, int bx)
{
    int t = threadIdx.x;
    int row = bx * 2 + (t >> 7);
    int tt = t & 127;
    int s = row >> 14, b = (row >> 3) & (BATCH - 1), m = row & 7;
    const float* src = (s ? r : p) + ((size_t)m * BATCH + b) * DIM;
    float4 v0 = ((const float4*)src)[tt * 2];
    float4 v1 = ((const float4*)src)[tt * 2 + 1];
    float vv[8] = {v0.x, v0.y, v0.z, v0.w, v1.x, v1.y, v1.z, v1.w};
    BfPack hp, lp;
#pragma unroll
    for (int i = 0; i < 8; i++) {
        __nv_bfloat16 h = __float2bfloat16_rn(vv[i]);
        hp.h[i] = h;
        lp.h[i] = __float2bfloat16_rn(vv[i] - __bfloat162float(h));
    }
    ((uint4*)(g_Xhi + (size_t)row * DIM))[tt] = hp.u;
    ((uint4*)(g_Xlo + (size_t)row * DIM))[tt] = lp.u;
}

// --------- combined aux: G-GEMM (64 CTAs) overlapped with split_x ----------
__global__ void __launch_bounds__(256) aux_kernel(
    const __nv_bfloat16* __restrict__ WqHi, const __nv_bfloat16* __restrict__ WqLo,
    const __nv_bfloat16* __restrict__ WkHi, const __nv_bfloat16* __restrict__ WkLo,
    const float* __restrict__ p_feats, const float* __restrict__ r_feats)
{
    if (blockIdx.x < 64)
        gemm_g_body(WqHi, WqLo, WkHi, WkLo, blockIdx.x);
    else
        split_x_body(p_feats, r_feats, blockIdx.x - 64);
}

// --------------- fused GEMM (Z = X@G) + gram epilogue ----------------------
__global__ void __launch_bounds__(256, 2) mma_gemm_fused(
    const __nv_bfloat16* __restrict__ Ahi, const __nv_bfloat16* __restrict__ Alo,
    const __nv_bfloat16* __restrict__ Bhi, const __nv_bfloat16* __restrict__ Blo,
    const float* __restrict__ fR, const float* __restrict__ fP)
{
    extern __shared__ char smem[];
    uint32_t sbase = s2u(smem);
    const int tid  = threadIdx.x;
    const int lane = tid & 31;
    const int wid  = tid >> 5;
    const int wm = (wid >> 2) * 64;
    const int wn = (wid & 3) * 32;
    const int rowBase = blockIdx.x * 128;
    const int colBase = blockIdx.y * 128;

    float acc[4][4][4];
#pragma unroll
    for (int i = 0; i < 4; i++)
#pragma unroll
        for (int j = 0; j < 4; j++)
#pragma unroll
            for (int q = 0; q < 4; q++) acc[i][j][q] = 0.f;

    GEMM_MAINLOOP();

    // gram epilogue: row tile = side, batches bb..bb+15, 8 query mols
    const int side = blockIdx.x >> 7;
    const int bb = (blockIdx.x & 127) * 16;
    const float* keys = side ? fP : fR;
    uint32_t zsm = sbase;
    uint32_t fsm = sbase + 64 * FPAD * 4;

#pragma unroll
    for (int pass = 0; pass < 2; pass++) {
        __syncthreads();
        // F loads first (latency hidden behind Z smem stores)
#pragma unroll
        for (int h = 0; h < 8; h++) {
            int idx = h * 256 + tid;
            int rowi = idx >> 5, ch = idx & 31;
            int bl = rowi >> 3, kk2 = rowi & 7;
            const float* src = keys +
                ((size_t)kk2 * BATCH + (bb + pass * 8 + bl)) * DIM + colBase + ch * 4;
            cpa16(fsm + (rowi * FPAD + ch * 4) * 4, src);
        }
        CP_COMMIT();
        if ((wid >> 2) == pass) {
#pragma unroll
            for (int mt = 0; mt < 4; mt++) {
                int lr = mt * 16 + (lane >> 2);
#pragma unroll
                for (int nt = 0; nt < 4; nt++) {
                    int lc = wn + nt * 8 + (lane & 3) * 2;
                    sts2f(zsm + (lr * FPAD + lc) * 4, acc[mt][nt][0], acc[mt][nt][1]);
                    sts2f(zsm + ((lr + 8) * FPAD + lc) * 4, acc[mt][nt][2], acc[mt][nt][3]);
                }
            }
        }
        CP_WAIT0();
        __syncthreads();

        // 2x2-blocked gram: lane -> (2q x 2k) block over half the D-range
        int bl = wid;
        int hh = lane >> 4;
        int q0 = ((lane >> 2) & 3) * 2;
        int k0 = (lane & 3) * 2;
        uint32_t z0 = zsm + ((bl * 8 + q0) * FPAD + hh * 64) * 4;
        uint32_t z1 = z0 + FPAD * 4;
        uint32_t f0 = fsm + ((bl * 8 + k0) * FPAD + hh * 64) * 4;
        uint32_t f1 = f0 + FPAD * 4;
        float s00 = 0.f, s01 = 0.f, s10 = 0.f, s11 = 0.f;
#pragma unroll
        for (int cc = 0; cc < 64; cc += 4) {
            float4 a0 = lds4f(z0 + cc * 4);
            float4 a1 = lds4f(z1 + cc * 4);
            float4 b0 = lds4f(f0 + cc * 4);
            float4 b1 = lds4f(f1 + cc * 4);
            s00 += a0.x * b0.x + a0.y * b0.y + a0.z * b0.z + a0.w * b0.w;
            s01 += a0.x * b1.x + a0.y * b1.y + a0.z * b1.z + a0.w * b1.w;
            s10 += a1.x * b0.x + a1.y * b0.y + a1.z * b0.z + a1.w * b0.w;
            s11 += a1.x * b1.x + a1.y * b1.y + a1.z * b1.z + a1.w * b1.w;
        }
        s00 += __shfl_xor_sync(0xFFFFFFFFu, s00, 16);
        s01 += __shfl_xor_sync(0xFFFFFFFFu, s01, 16);
        s10 += __shfl_xor_sync(0xFFFFFFFFu, s10, 16);
        s11 += __shfl_xor_sync(0xFFFFFFFFu, s11, 16);
        if (hh == 0) {
            size_t base = ((size_t)(blockIdx.y * 2 + side) * BATCH
                           + bb + pass * 8 + bl) * 64;
            g_Spart[base + q0 * 8 + k0]           = s00;
            g_Spart[base + q0 * 8 + k0 + 1]       = s01;
            g_Spart[base + (q0 + 1) * 8 + k0]     = s10;
            g_Spart[base + (q0 + 1) * 8 + k0 + 1] = s11;
        }
    }
}

// --------------- fused softmax + pooling + prediction head -----------------
__global__ void __launch_bounds__(256) pool_att_kernel(
    const float* __restrict__ r_feats, const float* __restrict__ p_feats,
    const float* __restrict__ r_new,   const float* __restrict__ p_new,
    const float* __restrict__ W_pred,  const float* __restrict__ b_pred,
    float* __restrict__ d_out)
{
    const int b = blockIdx.x;
    const int t = threadIdx.x;
    __shared__ float sS[2][MOL][MOL];
    __shared__ float sProb[2][LQ][LQ];
    __shared__ float sAtt[2][LQ];
    __shared__ float sw[16];
    __shared__ float sRed[OUTD][8];

    // ---- phase 1 (threads 0..127): reduce partials, softmax, att outputs ---
    if (t < 128) {
        int side = t >> 6, e = t & 63;
        float s = 0.f;
#pragma unroll
        for (int ct = 0; ct < 8; ct++)
            s += g_Spart[((size_t)(ct * 2 + side) * BATCH + b) * 64 + e];
        sS[side][e >> 3][e & 7] = s;
    }
    __syncthreads();

    if (t < 2 * LQ) {
        int sd = t / LQ, qq = t % LQ;
        int qi, qj;
        if (qq < MOL) { qi = qq; qj = -1; }
        else          { qi = c_pi[qq - MOL]; qj = c_pj[qq - MOL]; }
        float row[LQ];
        float maxv = -1e30f;
#pragma unroll
        for (int kk = 0; kk < LQ; kk++) {
            int ki, kj;
            if (kk < MOL) { ki = kk; kj = -1; }
            else          { ki = c_pi[kk - MOL]; kj = c_pj[kk - MOL]; }
            float v = sS[sd][qi][ki];
            if (kj >= 0) v += sS[sd][qi][kj];
            if (qj >= 0) {
                v += sS[sd][qj][ki];
                if (kj >= 0) v += sS[sd][qj][kj];
            }
            v *= 0.03125f;
            row[kk] = v;
            maxv = fmaxf(maxv, v);
        }
        float sum = 0.f;
#pragma unroll
        for (int kk = 0; kk < LQ; kk++) { row[kk] = expf(row[kk] - maxv); sum += row[kk]; }
        float inv = 1.f / sum;
#pragma unroll
        for (int kk = 0; kk < LQ; kk++) sProb[sd][qq][kk] = row[kk] * inv;
    }
    __syncthreads();

    if (t < 2 * LQ) {
        int sd = t / LQ, kk = t % LQ;
        float a = 0.f;
#pragma unroll
        for (int qq = 0; qq < LQ; qq++) a += sProb[sd][qq][kk];
        a *= (1.0f / LQ);
        sAtt[sd][kk] = a;
        d_out[BATCH * OUTD + sd * (BATCH * LQ) + b * LQ + kk] = a;
    }
    __syncthreads();

    if (t < 16) {
        int sd = t >> 3, m = t & 7;
        float w = sAtt[sd][m];
#pragma unroll
        for (int pp = 0; pp < NPAIR; pp++)
            if (c_pi[pp] == m || c_pj[pp] == m) w += sAtt[sd][MOL + pp];
        sw[sd * MOL + m] = w;
    }
    __syncthreads();

    // ---- phase 2 (all 256 threads): pooling + prediction head -------------
    const int d = t * 4;
    float4 acc = make_float4(0.f, 0.f, 0.f, 0.f);
#pragma unroll
    for (int m = 0; m < MOL; m++) {
        size_t off = ((size_t)m * BATCH + b) * DIM + d;
        float4 a  = *(const float4*)(r_feats + off);
        float4 an = *(const float4*)(r_new + off);
        float4 pv = *(const float4*)(p_feats + off);
        float4 pn = *(const float4*)(p_new + off);
        float wr = sw[m], wp = sw[8 + m];
        acc.x += wr * (a.x + an.x) - wp * (pv.x + pn.x);
        acc.y += wr * (a.y + an.y) - wp * (pv.y + pn.y);
        acc.z += wr * (a.z + an.z) - wp * (pv.z + pn.z);
        acc.w += wr * (a.w + an.w) - wp * (pv.w + pn.w);
    }
    float part[OUTD];
#pragma unroll
    for (int o = 0; o < OUTD; o++) {
        float4 wv = *(const float4*)(W_pred + (size_t)o * DIM + d);
        part[o] = acc.x * wv.x + acc.y * wv.y + acc.z * wv.z + acc.w * wv.w;
    }
    int lane = t & 31, wid = t >> 5;
#pragma unroll
    for (int o = 0; o < OUTD; o++) {
        float v = part[o];
#pragma unroll
        for (int off = 16; off > 0; off >>= 1)
            v += __shfl_down_sync(0xFFFFFFFFu, v, off);
        if (lane == 0) sRed[o][wid] = v;
    }
    __syncthreads();
    if (t < OUTD) {
        float s = 0.f;
#pragma unroll
        for (int w = 0; w < 8; w++) s += sRed[t][w];
        d_out[b * OUTD + t] = s + b_pred[t];
    }
}

// ---------------------------------------------------------------------------
extern "C" void kernel_launch(void* const* d_in, const int* in_sizes, int n_in,
                              void* d_out, int out_size) {
    const float* r_feats = (const float*)d_in[0];
    const float* p_feats = (const float*)d_in[1];
    const float* r_new   = (const float*)d_in[2];
    const float* p_new   = (const float*)d_in[3];
    const float* Wq      = (const float*)d_in[4];
    const float* Wk      = (const float*)d_in[5];
    const float* W_pred  = (const float*)d_in[6];
    const float* b_pred  = (const float*)d_in[7];
    float* out = (float*)d_out;

    cudaFuncSetAttribute(aux_kernel, cudaFuncAttributeMaxDynamicSharedMemorySize,
                         SMEM_GEMM);
    cudaFuncSetAttribute(mma_gemm_fused, cudaFuncAttributeMaxDynamicSharedMemorySize,
                         SMEM_GEMM);

    __nv_bfloat16 *WqHi, *WqLo, *WkHi, *WkLo, *GtHi, *GtLo, *Xhi, *Xlo;
    cudaGetSymbolAddress((void**)&WqHi, g_WqHi);
    cudaGetSymbolAddress((void**)&WqLo, g_WqLo);
    cudaGetSymbolAddress((void**)&WkHi, g_WkHi);
    cudaGetSymbolAddress((void**)&WkLo, g_WkLo);
    cudaGetSymbolAddress((void**)&GtHi, g_GtHi);
    cudaGetSymbolAddress((void**)&GtLo, g_GtLo);
    cudaGetSymbolAddress((void**)&Xhi,  g_Xhi);
    cudaGetSymbolAddress((void**)&Xlo,  g_Xlo);

    // 1) weight splits
    split_w<<<2048, 128>>>(Wq, Wk);
    // 2) G-GEMM (64 CTAs) overlapped with split_x (16384 virtual blocks)
    aux_kernel<<<64 + MROWS / 2, 256, SMEM_GEMM>>>(WqHi, WqLo, WkHi, WkLo,
                                                   p_feats, r_feats);
    // 3) fused GEMM + gram epilogue
    mma_gemm_fused<<<dim3(256, 8), 256, SMEM_GEMM>>>(Xhi, Xlo, GtHi, GtLo,
                                                     r_feats, p_feats);
    // 4) softmax + pooling + head (fused)
    pool_att_kernel<<<BATCH, 256>>>(r_feats, p_feats, r_new, p_new,
                                    W_pred, b_pred, out);
}

// round 11
// speedup vs baseline: 1.1825x; 1.1167x over previous
#include <cuda_runtime.h>
#include <cuda_bf16.h>
#include <cstdint>

constexpr int BATCH = 2048;
constexpr int DIM   = 1024;
constexpr int MOL   = 8;
constexpr int NPAIR = 28;
constexpr int LQ    = 36;
constexpr int OUTD  = 4;
constexpr int MROWS = 32768;           // 2 * BATCH * MOL

__constant__ int c_pi[NPAIR] = {0,0,0,0,0,0,0,1,1,1,1,1,1,2,2,2,2,2,3,3,3,3,4,4,4,5,5,6};
__constant__ int c_pj[NPAIR] = {1,2,3,4,5,6,7,2,3,4,5,6,7,3,4,5,6,7,4,5,6,7,5,6,7,6,7,7};

// ------------------------- static device scratch ---------------------------
__device__ __nv_bfloat16 g_WqHi[DIM * DIM];
__device__ __nv_bfloat16 g_WqLo[DIM * DIM];
__device__ __nv_bfloat16 g_WkHi[DIM * DIM];
__device__ __nv_bfloat16 g_WkLo[DIM * DIM];
__device__ __nv_bfloat16 g_GtHi[DIM * DIM];          // Gt[n][k] = G[k][n]
__device__ __nv_bfloat16 g_GtLo[DIM * DIM];
__device__ __nv_bfloat16 g_Xhi[(size_t)MROWS * DIM]; // 64 MB, row = s*16384+b*8+m
__device__ __nv_bfloat16 g_Xlo[(size_t)MROWS * DIM]; // 64 MB
__device__ float         g_Spart[8ull * 2 * BATCH * 64];  // 4 MB partial grams

// ------------------------------ helpers ------------------------------------
__device__ __forceinline__ uint32_t s2u(const void* p) {
    uint32_t a;
    asm("{ .reg .u64 t; cvta.to.shared.u64 t, %1; cvt.u32.u64 %0, t; }" : "=r"(a) : "l"(p));
    return a;
}
__device__ __forceinline__ void cpa16(uint32_t d, const void* g) {
    asm volatile("cp.async.cg.shared.global [%0], [%1], 16;" :: "r"(d), "l"(g));
}
#define CP_COMMIT()  asm volatile("cp.async.commit_group;" ::: "memory")
#define CP_WAIT0()   asm volatile("cp.async.wait_group 0;" ::: "memory")

__device__ __forceinline__ float4 lds4f(uint32_t a) {
    float4 v;
    asm volatile("ld.shared.v4.f32 {%0,%1,%2,%3}, [%4];"
        : "=f"(v.x), "=f"(v.y), "=f"(v.z), "=f"(v.w) : "r"(a));
    return v;
}
__device__ __forceinline__ float lds1f(uint32_t a) {
    float v;
    asm volatile("ld.shared.f32 %0, [%1];" : "=f"(v) : "r"(a));
    return v;
}
__device__ __forceinline__ void sts2f(uint32_t a, float x, float y) {
    asm volatile("st.shared.v2.f32 [%0], {%1,%2};" :: "r"(a), "f"(x), "f"(y));
}

__device__ __forceinline__ void lda4(uint32_t* f, uint32_t mbase, int wm, int mt,
                                     int ks, int lane) {
    int g = lane >> 3, r = lane & 7;
    int mloc = wm + mt * 16 + (g & 1) * 8 + r;
    int kloc = ks * 16 + (g >> 1) * 8;
    uint32_t a = mbase + (mloc * 40 + kloc) * 2;
    asm volatile("ldmatrix.sync.aligned.m8n8.x4.shared.b16 {%0,%1,%2,%3}, [%4];"
        : "=r"(f[0]), "=r"(f[1]), "=r"(f[2]), "=r"(f[3]) : "r"(a));
}
// B fragments for TWO adjacent nt tiles in one x4
__device__ __forceinline__ void ldb4(uint32_t* f, uint32_t mbase, int wn, int ntp,
                                     int ks, int lane) {
    int g = lane >> 3, r = lane & 7;
    int nloc = wn + ntp * 16 + (g >> 1) * 8 + r;
    int kloc = ks * 16 + (g & 1) * 8;
    uint32_t a = mbase + (nloc * 40 + kloc) * 2;
    asm volatile("ldmatrix.sync.aligned.m8n8.x4.shared.b16 {%0,%1,%2,%3}, [%4];"
        : "=r"(f[0]), "=r"(f[1]), "=r"(f[2]), "=r"(f[3]) : "r"(a));
}
__device__ __forceinline__ void mma16816(float* c, const uint32_t* a, const uint32_t* b) {
    asm volatile("mma.sync.aligned.m16n8k16.row.col.f32.bf16.bf16.f32 "
        "{%0,%1,%2,%3}, {%4,%5,%6,%7}, {%8,%9}, {%0,%1,%2,%3};"
        : "+f"(c[0]), "+f"(c[1]), "+f"(c[2]), "+f"(c[3])
        : "r"(a[0]), "r"(a[1]), "r"(a[2]), "r"(a[3]), "r"(b[0]), "r"(b[1]));
}

union BfPack { __nv_bfloat16 h[8]; uint4 u; };

// ------------------------- split_w kernel ----------------------------------
__global__ void __launch_bounds__(128) split_w(const float* __restrict__ Wq,
                                               const float* __restrict__ Wk) {
    int bx = blockIdx.x;
    int mat = bx >> 10, row = bx & 1023;
    const float* src = (mat ? Wk : Wq) + (size_t)row * DIM;
    __nv_bfloat16* hi = (mat ? g_WkHi : g_WqHi) + (size_t)row * DIM;
    __nv_bfloat16* lo = (mat ? g_WkLo : g_WqLo) + (size_t)row * DIM;
    int t = threadIdx.x;
    float4 v0 = ((const float4*)src)[t * 2];
    float4 v1 = ((const float4*)src)[t * 2 + 1];
    float vv[8] = {v0.x, v0.y, v0.z, v0.w, v1.x, v1.y, v1.z, v1.w};
    BfPack hp, lp;
#pragma unroll
    for (int i = 0; i < 8; i++) {
        __nv_bfloat16 h = __float2bfloat16_rn(vv[i]);
        hp.h[i] = h;
        lp.h[i] = __float2bfloat16_rn(vv[i] - __bfloat162float(h));
    }
    ((uint4*)(hi))[t] = hp.u;
    ((uint4*)(lo))[t] = lp.u;
}

// ------------------------- shared GEMM machinery ---------------------------
constexpr int MAT_ELE   = 128 * 40;
constexpr int STAGE_B   = 4 * MAT_ELE * 2;      // 40960 bytes
constexpr int SMEM_GEMM = 2 * STAGE_B;          // 81920 bytes
constexpr int FPAD      = 132;

__device__ __forceinline__ void load_chunk(
    uint32_t sbase, int stage,
    const __nv_bfloat16* __restrict__ Ahi, const __nv_bfloat16* __restrict__ Alo,
    const __nv_bfloat16* __restrict__ Bhi, const __nv_bfloat16* __restrict__ Blo,
    int rowBase, int colBase, int k0, int tid)
{
    uint32_t st = sbase + stage * STAGE_B;
#pragma unroll
    for (int mat = 0; mat < 4; mat++) {
        const __nv_bfloat16* src0 =
            (mat == 0) ? Ahi : (mat == 1) ? Alo : (mat == 2) ? Bhi : Blo;
        int base = (mat < 2) ? rowBase : colBase;
#pragma unroll
        for (int h = 0; h < 2; h++) {
            int idx = h * 256 + tid;
            int row = idx >> 2, ch = idx & 3;
            const __nv_bfloat16* src = src0 + (size_t)(base + row) * DIM + k0 + ch * 8;
            uint32_t dst = st + (mat * MAT_ELE + row * 40 + ch * 8) * 2;
            cpa16(dst, src);
        }
    }
    CP_COMMIT();
}

// one k16 half-chunk: B frags (x4-batched) held, A streamed per mt
__device__ __forceinline__ void compute_ks(
    float acc[4][4][4], uint32_t stb, int wm, int wn, int lane, int ks)
{
    uint32_t bAhi = stb;
    uint32_t bAlo = stb + MAT_ELE * 2;
    uint32_t bBhi = stb + 2 * MAT_ELE * 2;
    uint32_t bBlo = stb + 3 * MAT_ELE * 2;
    uint32_t bhif[8], blof[8];
    ldb4(bhif,     bBhi, wn, 0, ks, lane);
    ldb4(bhif + 4, bBhi, wn, 1, ks, lane);
    ldb4(blof,     bBlo, wn, 0, ks, lane);
    ldb4(blof + 4, bBlo, wn, 1, ks, lane);
#pragma unroll
    for (int mt = 0; mt < 4; mt++) {
        uint32_t ahif[4], alof[4];
        lda4(ahif, bAhi, wm, mt, ks, lane);
        lda4(alof, bAlo, wm, mt, ks, lane);
#pragma unroll
        for (int nt = 0; nt < 4; nt++) {
            mma16816(acc[mt][nt], ahif, bhif + nt * 2);
            mma16816(acc[mt][nt], alof, bhif + nt * 2);
            mma16816(acc[mt][nt], ahif, blof + nt * 2);
        }
    }
}

// mainloop: wait -> sync -> compute ks0 -> prefetch(c+1) mid-chunk -> ks1
#define GEMM_MAINLOOP()                                                        \
    load_chunk(sbase, 0, Ahi, Alo, Bhi, Blo, rowBase, colBase, 0, tid);        \
    for (int c = 0; c < 32; ++c) {                                             \
        int s = c & 1;                                                         \
        CP_WAIT0();                                                            \
        __syncthreads();                                                       \
        compute_ks(acc, sbase + s * STAGE_B, wm, wn, lane, 0);                 \
        if (c < 31)                                                            \
            load_chunk(sbase, s ^ 1, Ahi, Alo, Bhi, Blo, rowBase, colBase,     \
                       (c + 1) * 32, tid);                                     \
        compute_ks(acc, sbase + s * STAGE_B, wm, wn, lane, 1);                 \
    }

// --------- G GEMM body: C = Wq@Wk^T, epilogue writes Gt hi/lo --------------
__device__ void gemm_g_body(
    const __nv_bfloat16* __restrict__ Ahi, const __nv_bfloat16* __restrict__ Alo,
    const __nv_bfloat16* __restrict__ Bhi, const __nv_bfloat16* __restrict__ Blo,
    int gb)
{
    extern __shared__ char smem[];
    uint32_t sbase = s2u(smem);
    const int tid  = threadIdx.x;
    const int lane = tid & 31;
    const int wid  = tid >> 5;
    const int wm = (wid >> 2) * 64;
    const int wn = (wid & 3) * 32;
    const int rowBase = (gb & 7) * 128;   // k of Gt
    const int colBase = (gb >> 3) * 128;  // n of Gt

    float acc[4][4][4];
#pragma unroll
    for (int i = 0; i < 4; i++)
#pragma unroll
        for (int j = 0; j < 4; j++)
#pragma unroll
            for (int q = 0; q < 4; q++) acc[i][j][q] = 0.f;

    GEMM_MAINLOOP();

    __syncthreads();
#pragma unroll
    for (int mt = 0; mt < 4; mt++) {
        int lr = wm + mt * 16 + (lane >> 2);
#pragma unroll
        for (int nt = 0; nt < 4; nt++) {
            int lc = wn + nt * 8 + (lane & 3) * 2;
            sts2f(sbase + (lr * FPAD + lc) * 4, acc[mt][nt][0], acc[mt][nt][1]);
            sts2f(sbase + ((lr + 8) * FPAD + lc) * 4, acc[mt][nt][2], acc[mt][nt][3]);
        }
    }
    __syncthreads();

    int n_local = tid >> 1;
    int kh = (tid & 1) * 64;
    size_t gbase = (size_t)(colBase + n_local) * DIM + rowBase + kh;
#pragma unroll
    for (int kb = 0; kb < 64; kb += 8) {
        BfPack hp, lp;
#pragma unroll
        for (int i = 0; i < 8; i++) {
            float v = lds1f(sbase + ((kh + kb + i) * FPAD + n_local) * 4);
            __nv_bfloat16 h = __float2bfloat16_rn(v);
            hp.h[i] = h;
            lp.h[i] = __float2bfloat16_rn(v - __bfloat162float(h));
        }
        *(uint4*)(g_GtHi + gbase + kb) = hp.u;
        *(uint4*)(g_GtLo + gbase + kb) = lp.u;
    }
}

// --------- split_x body: gather + fp32->bf16 hi/lo split --------------------
__device__ void split_x_body(const float* __restrict__ p,
                             const float* __restrict__ r, int bx)
{
    int t = threadIdx.x;
    int row = bx * 2 + (t >> 7);
    int tt = t & 127;
    int s = row >> 14, b = (row >> 3) & (BATCH - 1), m = row & 7;
    const float* src = (s ? r : p) + ((size_t)m * BATCH + b) * DIM;
    float4 v0 = ((const float4*)src)[tt * 2];
    float4 v1 = ((const float4*)src)[tt * 2 + 1];
    float vv[8] = {v0.x, v0.y, v0.z, v0.w, v1.x, v1.y, v1.z, v1.w};
    BfPack hp, lp;
#pragma unroll
    for (int i = 0; i < 8; i++) {
        __nv_bfloat16 h = __float2bfloat16_rn(vv[i]);
        hp.h[i] = h;
        lp.h[i] = __float2bfloat16_rn(vv[i] - __bfloat162float(h));
    }
    ((uint4*)(g_Xhi + (size_t)row * DIM))[tt] = hp.u;
    ((uint4*)(g_Xlo + (size_t)row * DIM))[tt] = lp.u;
}

// --------- combined aux: G-GEMM (64 CTAs) overlapped with split_x ----------
__global__ void __launch_bounds__(256) aux_kernel(
    const __nv_bfloat16* __restrict__ WqHi, const __nv_bfloat16* __restrict__ WqLo,
    const __nv_bfloat16* __restrict__ WkHi, const __nv_bfloat16* __restrict__ WkLo,
    const float* __restrict__ p_feats, const float* __restrict__ r_feats)
{
    if (blockIdx.x < 64)
        gemm_g_body(WqHi, WqLo, WkHi, WkLo, blockIdx.x);
    else
        split_x_body(p_feats, r_feats, blockIdx.x - 64);
}

// --------------- fused GEMM (Z = X@G) + gram epilogue ----------------------
__global__ void __launch_bounds__(256, 2) mma_gemm_fused(
    const __nv_bfloat16* __restrict__ Ahi, const __nv_bfloat16* __restrict__ Alo,
    const __nv_bfloat16* __restrict__ Bhi, const __nv_bfloat16* __restrict__ Blo,
    const float* __restrict__ fR, const float* __restrict__ fP)
{
    extern __shared__ char smem[];
    uint32_t sbase = s2u(smem);
    const int tid  = threadIdx.x;
    const int lane = tid & 31;
    const int wid  = tid >> 5;
    const int wm = (wid >> 2) * 64;
    const int wn = (wid & 3) * 32;
    const int rowBase = blockIdx.x * 128;
    const int colBase = blockIdx.y * 128;

    float acc[4][4][4];
#pragma unroll
    for (int i = 0; i < 4; i++)
#pragma unroll
        for (int j = 0; j < 4; j++)
#pragma unroll
            for (int q = 0; q < 4; q++) acc[i][j][q] = 0.f;

    GEMM_MAINLOOP();

    // gram epilogue: row tile = side, batches bb..bb+15, 8 query mols
    const int side = blockIdx.x >> 7;
    const int bb = (blockIdx.x & 127) * 16;
    const float* keys = side ? fP : fR;
    uint32_t zsm = sbase;
    uint32_t fsm = sbase + 64 * FPAD * 4;

#pragma unroll
    for (int pass = 0; pass < 2; pass++) {
        __syncthreads();
        // F loads first (latency hidden behind Z smem stores)
#pragma unroll
        for (int h = 0; h < 8; h++) {
            int idx = h * 256 + tid;
            int rowi = idx >> 5, ch = idx & 31;
            int bl = rowi >> 3, kk2 = rowi & 7;
            const float* src = keys +
                ((size_t)kk2 * BATCH + (bb + pass * 8 + bl)) * DIM + colBase + ch * 4;
            cpa16(fsm + (rowi * FPAD + ch * 4) * 4, src);
        }
        CP_COMMIT();
        if ((wid >> 2) == pass) {
#pragma unroll
            for (int mt = 0; mt < 4; mt++) {
                int lr = mt * 16 + (lane >> 2);
#pragma unroll
                for (int nt = 0; nt < 4; nt++) {
                    int lc = wn + nt * 8 + (lane & 3) * 2;
                    sts2f(zsm + (lr * FPAD + lc) * 4, acc[mt][nt][0], acc[mt][nt][1]);
                    sts2f(zsm + ((lr + 8) * FPAD + lc) * 4, acc[mt][nt][2], acc[mt][nt][3]);
                }
            }
        }
        CP_WAIT0();
        __syncthreads();

        // 2x2-blocked gram: lane -> (2q x 2k) block over half the D-range
        int bl = wid;
        int hh = lane >> 4;
        int q0 = ((lane >> 2) & 3) * 2;
        int k0 = (lane & 3) * 2;
        uint32_t z0 = zsm + ((bl * 8 + q0) * FPAD + hh * 64) * 4;
        uint32_t z1 = z0 + FPAD * 4;
        uint32_t f0 = fsm + ((bl * 8 + k0) * FPAD + hh * 64) * 4;
        uint32_t f1 = f0 + FPAD * 4;
        float s00 = 0.f, s01 = 0.f, s10 = 0.f, s11 = 0.f;
#pragma unroll
        for (int cc = 0; cc < 64; cc += 4) {
            float4 a0 = lds4f(z0 + cc * 4);
            float4 a1 = lds4f(z1 + cc * 4);
            float4 b0 = lds4f(f0 + cc * 4);
            float4 b1 = lds4f(f1 + cc * 4);
            s00 += a0.x * b0.x + a0.y * b0.y + a0.z * b0.z + a0.w * b0.w;
            s01 += a0.x * b1.x + a0.y * b1.y + a0.z * b1.z + a0.w * b1.w;
            s10 += a1.x * b0.x + a1.y * b0.y + a1.z * b0.z + a1.w * b0.w;
            s11 += a1.x * b1.x + a1.y * b1.y + a1.z * b1.z + a1.w * b1.w;
        }
        s00 += __shfl_xor_sync(0xFFFFFFFFu, s00, 16);
        s01 += __shfl_xor_sync(0xFFFFFFFFu, s01, 16);
        s10 += __shfl_xor_sync(0xFFFFFFFFu, s10, 16);
        s11 += __shfl_xor_sync(0xFFFFFFFFu, s11, 16);
        if (hh == 0) {
            size_t base = ((size_t)(blockIdx.y * 2 + side) * BATCH
                           + bb + pass * 8 + bl) * 64;
            g_Spart[base + q0 * 8 + k0]           = s00;
            g_Spart[base + q0 * 8 + k0 + 1]       = s01;
            g_Spart[base + (q0 + 1) * 8 + k0]     = s10;
            g_Spart[base + (q0 + 1) * 8 + k0 + 1] = s11;
        }
    }
}

// --------- fused softmax + pooling + head: 2 batches per 512-thr CTA -------
__global__ void __launch_bounds__(512) pool_att_kernel(
    const float* __restrict__ r_feats, const float* __restrict__ p_feats,
    const float* __restrict__ r_new,   const float* __restrict__ p_new,
    const float* __restrict__ W_pred,  const float* __restrict__ b_pred,
    float* __restrict__ d_out)
{
    const int half = threadIdx.x >> 8;        // which batch of the pair
    const int t = threadIdx.x & 255;
    const int b = blockIdx.x * 2 + half;

    __shared__ float sS[2][2][MOL][MOL];
    __shared__ float sProb[2][2][LQ][LQ];
    __shared__ float sAtt[2][2][LQ];
    __shared__ float sw[2][16];
    __shared__ float sRed[2][OUTD][8];

    // ---- phase 1: reduce partials, softmax, att outputs ----
    if (t < 128) {
        int side = t >> 6, e = t & 63;
        float s = 0.f;
#pragma unroll
        for (int ct = 0; ct < 8; ct++)
            s += g_Spart[((size_t)(ct * 2 + side) * BATCH + b) * 64 + e];
        sS[half][side][e >> 3][e & 7] = s;
    }
    __syncthreads();

    if (t < 2 * LQ) {
        int sd = t / LQ, qq = t % LQ;
        int qi, qj;
        if (qq < MOL) { qi = qq; qj = -1; }
        else          { qi = c_pi[qq - MOL]; qj = c_pj[qq - MOL]; }
        float row[LQ];
        float maxv = -1e30f;
#pragma unroll
        for (int kk = 0; kk < LQ; kk++) {
            int ki, kj;
            if (kk < MOL) { ki = kk; kj = -1; }
            else          { ki = c_pi[kk - MOL]; kj = c_pj[kk - MOL]; }
            float v = sS[half][sd][qi][ki];
            if (kj >= 0) v += sS[half][sd][qi][kj];
            if (qj >= 0) {
                v += sS[half][sd][qj][ki];
                if (kj >= 0) v += sS[half][sd][qj][kj];
            }
            v *= 0.03125f;
            row[kk] = v;
            maxv = fmaxf(maxv, v);
        }
        float sum = 0.f;
#pragma unroll
        for (int kk = 0; kk < LQ; kk++) { row[kk] = expf(row[kk] - maxv); sum += row[kk]; }
        float inv = 1.f / sum;
#pragma unroll
        for (int kk = 0; kk < LQ; kk++) sProb[half][sd][qq][kk] = row[kk] * inv;
    }
    __syncthreads();

    if (t < 2 * LQ) {
        int sd = t / LQ, kk = t % LQ;
        float a = 0.f;
#pragma unroll
        for (int qq = 0; qq < LQ; qq++) a += sProb[half][sd][qq][kk];
        a *= (1.0f / LQ);
        sAtt[half][sd][kk] = a;
        d_out[BATCH * OUTD + sd * (BATCH * LQ) + b * LQ + kk] = a;
    }
    __syncthreads();

    if (t < 16) {
        int sd = t >> 3, m = t & 7;
        float w = sAtt[half][sd][m];
#pragma unroll
        for (int pp = 0; pp < NPAIR; pp++)
            if (c_pi[pp] == m || c_pj[pp] == m) w += sAtt[half][sd][MOL + pp];
        sw[half][sd * MOL + m] = w;
    }
    __syncthreads();

    // ---- phase 2: pooling + prediction head ----
    const int d = t * 4;
    float4 acc = make_float4(0.f, 0.f, 0.f, 0.f);
#pragma unroll
    for (int m = 0; m < MOL; m++) {
        size_t off = ((size_t)m * BATCH + b) * DIM + d;
        float4 a  = *(const float4*)(r_feats + off);
        float4 an = *(const float4*)(r_new + off);
        float4 pv = *(const float4*)(p_feats + off);
        float4 pn = *(const float4*)(p_new + off);
        float wr = sw[half][m], wp = sw[half][8 + m];
        acc.x += wr * (a.x + an.x) - wp * (pv.x + pn.x);
        acc.y += wr * (a.y + an.y) - wp * (pv.y + pn.y);
        acc.z += wr * (a.z + an.z) - wp * (pv.z + pn.z);
        acc.w += wr * (a.w + an.w) - wp * (pv.w + pn.w);
    }
    float part[OUTD];
#pragma unroll
    for (int o = 0; o < OUTD; o++) {
        float4 wv = *(const float4*)(W_pred + (size_t)o * DIM + d);
        part[o] = acc.x * wv.x + acc.y * wv.y + acc.z * wv.z + acc.w * wv.w;
    }
    int lane = t & 31, wid = t >> 5;
#pragma unroll
    for (int o = 0; o < OUTD; o++) {
        float v = part[o];
#pragma unroll
        for (int off = 16; off > 0; off >>= 1)
            v += __shfl_down_sync(0xFFFFFFFFu, v, off);
        if (lane == 0) sRed[half][o][wid] = v;
    }
    __syncthreads();
    if (t < OUTD) {
        float s = 0.f;
#pragma unroll
        for (int w = 0; w < 8; w++) s += sRed[half][t][w];
        d_out[b * OUTD + t] = s + b_pred[t];
    }
}

// ---------------------------------------------------------------------------
extern "C" void kernel_launch(void* const* d_in, const int* in_sizes, int n_in,
                              void* d_out, int out_size) {
    const float* r_feats = (const float*)d_in[0];
    const float* p_feats = (const float*)d_in[1];
    const float* r_new   = (const float*)d_in[2];
    const float* p_new   = (const float*)d_in[3];
    const float* Wq      = (const float*)d_in[4];
    const float* Wk      = (const float*)d_in[5];
    const float* W_pred  = (const float*)d_in[6];
    const float* b_pred  = (const float*)d_in[7];
    float* out = (float*)d_out;

    cudaFuncSetAttribute(aux_kernel, cudaFuncAttributeMaxDynamicSharedMemorySize,
                         SMEM_GEMM);
    cudaFuncSetAttribute(mma_gemm_fused, cudaFuncAttributeMaxDynamicSharedMemorySize,
                         SMEM_GEMM);

    __nv_bfloat16 *WqHi, *WqLo, *WkHi, *WkLo, *GtHi, *GtLo, *Xhi, *Xlo;
    cudaGetSymbolAddress((void**)&WqHi, g_WqHi);
    cudaGetSymbolAddress((void**)&WqLo, g_WqLo);
    cudaGetSymbolAddress((void**)&WkHi, g_WkHi);
    cudaGetSymbolAddress((void**)&WkLo, g_WkLo);
    cudaGetSymbolAddress((void**)&GtHi, g_GtHi);
    cudaGetSymbolAddress((void**)&GtLo, g_GtLo);
    cudaGetSymbolAddress((void**)&Xhi,  g_Xhi);
    cudaGetSymbolAddress((void**)&Xlo,  g_Xlo);

    // 1) weight splits
    split_w<<<2048, 128>>>(Wq, Wk);
    // 2) G-GEMM (64 CTAs) overlapped with split_x (16384 virtual blocks)
    aux_kernel<<<64 + MROWS / 2, 256, SMEM_GEMM>>>(WqHi, WqLo, WkHi, WkLo,
                                                   p_feats, r_feats);
    // 3) fused GEMM + gram epilogue
    mma_gemm_fused<<<dim3(256, 8), 256, SMEM_GEMM>>>(Xhi, Xlo, GtHi, GtLo,
                                                     r_feats, p_feats);
    // 4) softmax + pooling + head (fused, 2 batches/CTA)
    pool_att_kernel<<<BATCH / 2, 512>>>(r_feats, p_feats, r_new, p_new,
                                        W_pred, b_pred, out);
}

// round 12
// speedup vs baseline: 1.2231x; 1.0343x over previous
#include <cuda_runtime.h>
#include <cuda_bf16.h>
#include <cstdint>

constexpr int BATCH = 2048;
constexpr int DIM   = 1024;
constexpr int MOL   = 8;
constexpr int NPAIR = 28;
constexpr int LQ    = 36;
constexpr int OUTD  = 4;
constexpr int MROWS = 32768;           // 2 * BATCH * MOL

__constant__ int c_pi[NPAIR] = {0,0,0,0,0,0,0,1,1,1,1,1,1,2,2,2,2,2,3,3,3,3,4,4,4,5,5,6};
__constant__ int c_pj[NPAIR] = {1,2,3,4,5,6,7,2,3,4,5,6,7,3,4,5,6,7,4,5,6,7,5,6,7,6,7,7};

// ------------------------- static device scratch ---------------------------
__device__ __nv_bfloat16 g_WqHi[DIM * DIM];
__device__ __nv_bfloat16 g_WqLo[DIM * DIM];
__device__ __nv_bfloat16 g_WkHi[DIM * DIM];
__device__ __nv_bfloat16 g_WkLo[DIM * DIM];
__device__ __nv_bfloat16 g_GtHi[DIM * DIM];          // Gt[n][k] = G[k][n]
__device__ __nv_bfloat16 g_GtLo[DIM * DIM];
__device__ __nv_bfloat16 g_Xhi[(size_t)MROWS * DIM]; // 64 MB
__device__ __nv_bfloat16 g_Xlo[(size_t)MROWS * DIM]; // 64 MB
__device__ float         g_Spart[8ull * 2 * BATCH * 64];  // 4 MB partial grams
__device__ float         g_tr[MOL * BATCH * OUTD];   // (r+rn)[m,b,:].W_pred[o,:]
__device__ float         g_tp[MOL * BATCH * OUTD];   // (p+pn)[m,b,:].W_pred[o,:]

// ------------------------------ helpers ------------------------------------
__device__ __forceinline__ uint32_t s2u(const void* p) {
    uint32_t a;
    asm("{ .reg .u64 t; cvta.to.shared.u64 t, %1; cvt.u32.u64 %0, t; }" : "=r"(a) : "l"(p));
    return a;
}
__device__ __forceinline__ void cpa16(uint32_t d, const void* g) {
    asm volatile("cp.async.cg.shared.global [%0], [%1], 16;" :: "r"(d), "l"(g));
}
#define CP_COMMIT()  asm volatile("cp.async.commit_group;" ::: "memory")
#define CP_WAIT0()   asm volatile("cp.async.wait_group 0;" ::: "memory")

__device__ __forceinline__ float4 lds4f(uint32_t a) {
    float4 v;
    asm volatile("ld.shared.v4.f32 {%0,%1,%2,%3}, [%4];"
        : "=f"(v.x), "=f"(v.y), "=f"(v.z), "=f"(v.w) : "r"(a));
    return v;
}
__device__ __forceinline__ float lds1f(uint32_t a) {
    float v;
    asm volatile("ld.shared.f32 %0, [%1];" : "=f"(v) : "r"(a));
    return v;
}
__device__ __forceinline__ void sts2f(uint32_t a, float x, float y) {
    asm volatile("st.shared.v2.f32 [%0], {%1,%2};" :: "r"(a), "f"(x), "f"(y));
}

__device__ __forceinline__ void lda4(uint32_t* f, uint32_t mbase, int wm, int mt,
                                     int ks, int lane) {
    int g = lane >> 3, r = lane & 7;
    int mloc = wm + mt * 16 + (g & 1) * 8 + r;
    int kloc = ks * 16 + (g >> 1) * 8;
    uint32_t a = mbase + (mloc * 40 + kloc) * 2;
    asm volatile("ldmatrix.sync.aligned.m8n8.x4.shared.b16 {%0,%1,%2,%3}, [%4];"
        : "=r"(f[0]), "=r"(f[1]), "=r"(f[2]), "=r"(f[3]) : "r"(a));
}
// B fragments for TWO adjacent nt tiles in one x4
__device__ __forceinline__ void ldb4(uint32_t* f, uint32_t mbase, int wn, int ntp,
                                     int ks, int lane) {
    int g = lane >> 3, r = lane & 7;
    int nloc = wn + ntp * 16 + (g >> 1) * 8 + r;
    int kloc = ks * 16 + (g & 1) * 8;
    uint32_t a = mbase + (nloc * 40 + kloc) * 2;
    asm volatile("ldmatrix.sync.aligned.m8n8.x4.shared.b16 {%0,%1,%2,%3}, [%4];"
        : "=r"(f[0]), "=r"(f[1]), "=r"(f[2]), "=r"(f[3]) : "r"(a));
}
__device__ __forceinline__ void mma16816(float* c, const uint32_t* a, const uint32_t* b) {
    asm volatile("mma.sync.aligned.m16n8k16.row.col.f32.bf16.bf16.f32 "
        "{%0,%1,%2,%3}, {%4,%5,%6,%7}, {%8,%9}, {%0,%1,%2,%3};"
        : "+f"(c[0]), "+f"(c[1]), "+f"(c[2]), "+f"(c[3])
        : "r"(a[0]), "r"(a[1]), "r"(a[2]), "r"(a[3]), "r"(b[0]), "r"(b[1]));
}

union BfPack { __nv_bfloat16 h[8]; uint4 u; };

// ------------------------- split_w kernel ----------------------------------
__global__ void __launch_bounds__(128) split_w(const float* __restrict__ Wq,
                                               const float* __restrict__ Wk) {
    int bx = blockIdx.x;
    int mat = bx >> 10, row = bx & 1023;
    const float* src = (mat ? Wk : Wq) + (size_t)row * DIM;
    __nv_bfloat16* hi = (mat ? g_WkHi : g_WqHi) + (size_t)row * DIM;
    __nv_bfloat16* lo = (mat ? g_WkLo : g_WqLo) + (size_t)row * DIM;
    int t = threadIdx.x;
    float4 v0 = ((const float4*)src)[t * 2];
    float4 v1 = ((const float4*)src)[t * 2 + 1];
    float vv[8] = {v0.x, v0.y, v0.z, v0.w, v1.x, v1.y, v1.z, v1.w};
    BfPack hp, lp;
#pragma unroll
    for (int i = 0; i < 8; i++) {
        __nv_bfloat16 h = __float2bfloat16_rn(vv[i]);
        hp.h[i] = h;
        lp.h[i] = __float2bfloat16_rn(vv[i] - __bfloat162float(h));
    }
    ((uint4*)(hi))[t] = hp.u;
    ((uint4*)(lo))[t] = lp.u;
}

// ------------------------- shared GEMM machinery ---------------------------
constexpr int MAT_ELE   = 128 * 40;
constexpr int STAGE_B   = 4 * MAT_ELE * 2;      // 40960 bytes
constexpr int SMEM_GEMM = 2 * STAGE_B;          // 81920 bytes
constexpr int FPAD      = 132;

__device__ __forceinline__ void load_chunk(
    uint32_t sbase, int stage,
    const __nv_bfloat16* __restrict__ Ahi, const __nv_bfloat16* __restrict__ Alo,
    const __nv_bfloat16* __restrict__ Bhi, const __nv_bfloat16* __restrict__ Blo,
    int rowBase, int colBase, int k0, int tid)
{
    uint32_t st = sbase + stage * STAGE_B;
#pragma unroll
    for (int mat = 0; mat < 4; mat++) {
        const __nv_bfloat16* src0 =
            (mat == 0) ? Ahi : (mat == 1) ? Alo : (mat == 2) ? Bhi : Blo;
        int base = (mat < 2) ? rowBase : colBase;
#pragma unroll
        for (int h = 0; h < 2; h++) {
            int idx = h * 256 + tid;
            int row = idx >> 2, ch = idx & 3;
            const __nv_bfloat16* src = src0 + (size_t)(base + row) * DIM + k0 + ch * 8;
            uint32_t dst = st + (mat * MAT_ELE + row * 40 + ch * 8) * 2;
            cpa16(dst, src);
        }
    }
    CP_COMMIT();
}

// one k16 half-chunk: B frags (x4-batched) held, A streamed per mt
__device__ __forceinline__ void compute_ks(
    float acc[4][4][4], uint32_t stb, int wm, int wn, int lane, int ks)
{
    uint32_t bAhi = stb;
    uint32_t bAlo = stb + MAT_ELE * 2;
    uint32_t bBhi = stb + 2 * MAT_ELE * 2;
    uint32_t bBlo = stb + 3 * MAT_ELE * 2;
    uint32_t bhif[8], blof[8];
    ldb4(bhif,     bBhi, wn, 0, ks, lane);
    ldb4(bhif + 4, bBhi, wn, 1, ks, lane);
    ldb4(blof,     bBlo, wn, 0, ks, lane);
    ldb4(blof + 4, bBlo, wn, 1, ks, lane);
#pragma unroll
    for (int mt = 0; mt < 4; mt++) {
        uint32_t ahif[4], alof[4];
        lda4(ahif, bAhi, wm, mt, ks, lane);
        lda4(alof, bAlo, wm, mt, ks, lane);
#pragma unroll
        for (int nt = 0; nt < 4; nt++) {
            mma16816(acc[mt][nt], ahif, bhif + nt * 2);
            mma16816(acc[mt][nt], alof, bhif + nt * 2);
            mma16816(acc[mt][nt], ahif, blof + nt * 2);
        }
    }
}

// mainloop: wait -> sync -> compute ks0 -> prefetch(c+1) mid-chunk -> ks1
#define GEMM_MAINLOOP()                                                        \
    load_chunk(sbase, 0, Ahi, Alo, Bhi, Blo, rowBase, colBase, 0, tid);        \
    for (int c = 0; c < 32; ++c) {                                             \
        int s = c & 1;                                                         \
        CP_WAIT0();                                                            \
        __syncthreads();                                                       \
        compute_ks(acc, sbase + s * STAGE_B, wm, wn, lane, 0);                 \
        if (c < 31)                                                            \
            load_chunk(sbase, s ^ 1, Ahi, Alo, Bhi, Blo, rowBase, colBase,     \
                       (c + 1) * 32, tid);                                     \
        compute_ks(acc, sbase + s * STAGE_B, wm, wn, lane, 1);                 \
    }

// --------- G GEMM body: C = Wq@Wk^T, epilogue writes Gt hi/lo --------------
__device__ void gemm_g_body(
    const __nv_bfloat16* __restrict__ Ahi, const __nv_bfloat16* __restrict__ Alo,
    const __nv_bfloat16* __restrict__ Bhi, const __nv_bfloat16* __restrict__ Blo,
    int gb)
{
    extern __shared__ char smem[];
    uint32_t sbase = s2u(smem);
    const int tid  = threadIdx.x;
    const int lane = tid & 31;
    const int wid  = tid >> 5;
    const int wm = (wid >> 2) * 64;
    const int wn = (wid & 3) * 32;
    const int rowBase = (gb & 7) * 128;   // k of Gt
    const int colBase = (gb >> 3) * 128;  // n of Gt

    float acc[4][4][4];
#pragma unroll
    for (int i = 0; i < 4; i++)
#pragma unroll
        for (int j = 0; j < 4; j++)
#pragma unroll
            for (int q = 0; q < 4; q++) acc[i][j][q] = 0.f;

    GEMM_MAINLOOP();

    __syncthreads();
#pragma unroll
    for (int mt = 0; mt < 4; mt++) {
        int lr = wm + mt * 16 + (lane >> 2);
#pragma unroll
        for (int nt = 0; nt < 4; nt++) {
            int lc = wn + nt * 8 + (lane & 3) * 2;
            sts2f(sbase + (lr * FPAD + lc) * 4, acc[mt][nt][0], acc[mt][nt][1]);
            sts2f(sbase + ((lr + 8) * FPAD + lc) * 4, acc[mt][nt][2], acc[mt][nt][3]);
        }
    }
    __syncthreads();

    int n_local = tid >> 1;
    int kh = (tid & 1) * 64;
    size_t gbase = (size_t)(colBase + n_local) * DIM + rowBase + kh;
#pragma unroll
    for (int kb = 0; kb < 64; kb += 8) {
        BfPack hp, lp;
#pragma unroll
        for (int i = 0; i < 8; i++) {
            float v = lds1f(sbase + ((kh + kb + i) * FPAD + n_local) * 4);
            __nv_bfloat16 h = __float2bfloat16_rn(v);
            hp.h[i] = h;
            lp.h[i] = __float2bfloat16_rn(v - __bfloat162float(h));
        }
        *(uint4*)(g_GtHi + gbase + kb) = hp.u;
        *(uint4*)(g_GtLo + gbase + kb) = lp.u;
    }
}

// --------- split_x body: gather + bf16 split + head-dot precompute ---------
// Also computes t[m,b,o] = (feats+new)[m,b,:].W_pred[o,:]  (fused streaming)
__device__ void split_x_body(const float* __restrict__ p,
                             const float* __restrict__ r,
                             const float* __restrict__ pn,
                             const float* __restrict__ rn,
                             const float* __restrict__ W_pred, int bx)
{
    __shared__ float sdot[2][4][OUTD];
    int t = threadIdx.x;
    int half = t >> 7;
    int row = bx * 2 + half;
    int tt = t & 127;
    int s = row >> 14, b = (row >> 3) & (BATCH - 1), m = row & 7;
    size_t off = ((size_t)m * BATCH + b) * DIM;
    const float* src  = (s ? r : p) + off;
    const float* nsrc = (s ? rn : pn) + off;
    float4 v0 = ((const float4*)src)[tt * 2];
    float4 v1 = ((const float4*)src)[tt * 2 + 1];
    float vv[8] = {v0.x, v0.y, v0.z, v0.w, v1.x, v1.y, v1.z, v1.w};
    BfPack hp, lp;
#pragma unroll
    for (int i = 0; i < 8; i++) {
        __nv_bfloat16 h = __float2bfloat16_rn(vv[i]);
        hp.h[i] = h;
        lp.h[i] = __float2bfloat16_rn(vv[i] - __bfloat162float(h));
    }
    ((uint4*)(g_Xhi + (size_t)row * DIM))[tt] = hp.u;
    ((uint4*)(g_Xlo + (size_t)row * DIM))[tt] = lp.u;

    // head-dot precompute: (v + n) . W_pred[o]
    float4 n0 = ((const float4*)nsrc)[tt * 2];
    float4 n1 = ((const float4*)nsrc)[tt * 2 + 1];
    float sv[8] = {vv[0] + n0.x, vv[1] + n0.y, vv[2] + n0.z, vv[3] + n0.w,
                   vv[4] + n1.x, vv[5] + n1.y, vv[6] + n1.z, vv[7] + n1.w};
    float dot[OUTD];
#pragma unroll
    for (int o = 0; o < OUTD; o++) {
        const float4* wrow = (const float4*)(W_pred + (size_t)o * DIM);
        float4 w0 = wrow[tt * 2];
        float4 w1 = wrow[tt * 2 + 1];
        dot[o] = sv[0] * w0.x + sv[1] * w0.y + sv[2] * w0.z + sv[3] * w0.w
               + sv[4] * w1.x + sv[5] * w1.y + sv[6] * w1.z + sv[7] * w1.w;
    }
    int lane = t & 31, w = tt >> 5;
#pragma unroll
    for (int o = 0; o < OUTD; o++) {
#pragma unroll
        for (int ofs = 16; ofs > 0; ofs >>= 1)
            dot[o] += __shfl_down_sync(0xFFFFFFFFu, dot[o], ofs);
        if (lane == 0) sdot[half][w][o] = dot[o];
    }
    __syncthreads();
    if (tt < OUTD) {
        float ssum = sdot[half][0][tt] + sdot[half][1][tt]
                   + sdot[half][2][tt] + sdot[half][3][tt];
        float* dst = s ? g_tr : g_tp;
        dst[((size_t)m * BATCH + b) * OUTD + tt] = ssum;
    }
}

// --------- combined aux: G-GEMM (64 CTAs) overlapped with split_x ----------
__global__ void __launch_bounds__(256) aux_kernel(
    const __nv_bfloat16* __restrict__ WqHi, const __nv_bfloat16* __restrict__ WqLo,
    const __nv_bfloat16* __restrict__ WkHi, const __nv_bfloat16* __restrict__ WkLo,
    const float* __restrict__ p_feats, const float* __restrict__ r_feats,
    const float* __restrict__ p_new,   const float* __restrict__ r_new,
    const float* __restrict__ W_pred)
{
    if (blockIdx.x < 64)
        gemm_g_body(WqHi, WqLo, WkHi, WkLo, blockIdx.x);
    else
        split_x_body(p_feats, r_feats, p_new, r_new, W_pred, blockIdx.x - 64);
}

// --------------- fused GEMM (Z = X@G) + gram epilogue ----------------------
__global__ void __launch_bounds__(256, 2) mma_gemm_fused(
    const __nv_bfloat16* __restrict__ Ahi, const __nv_bfloat16* __restrict__ Alo,
    const __nv_bfloat16* __restrict__ Bhi, const __nv_bfloat16* __restrict__ Blo,
    const float* __restrict__ fR, const float* __restrict__ fP)
{
    extern __shared__ char smem[];
    uint32_t sbase = s2u(smem);
    const int tid  = threadIdx.x;
    const int lane = tid & 31;
    const int wid  = tid >> 5;
    const int wm = (wid >> 2) * 64;
    const int wn = (wid & 3) * 32;
    const int rowBase = blockIdx.x * 128;
    const int colBase = blockIdx.y * 128;

    float acc[4][4][4];
#pragma unroll
    for (int i = 0; i < 4; i++)
#pragma unroll
        for (int j = 0; j < 4; j++)
#pragma unroll
            for (int q = 0; q < 4; q++) acc[i][j][q] = 0.f;

    GEMM_MAINLOOP();

    // gram epilogue: row tile = side, batches bb..bb+15, 8 query mols
    const int side = blockIdx.x >> 7;
    const int bb = (blockIdx.x & 127) * 16;
    const float* keys = side ? fP : fR;
    uint32_t zsm = sbase;
    uint32_t fsm = sbase + 64 * FPAD * 4;

#pragma unroll
    for (int pass = 0; pass < 2; pass++) {
        __syncthreads();
        // F loads first (latency hidden behind Z smem stores)
#pragma unroll
        for (int h = 0; h < 8; h++) {
            int idx = h * 256 + tid;
            int rowi = idx >> 5, ch = idx & 31;
            int bl = rowi >> 3, kk2 = rowi & 7;
            const float* src = keys +
                ((size_t)kk2 * BATCH + (bb + pass * 8 + bl)) * DIM + colBase + ch * 4;
            cpa16(fsm + (rowi * FPAD + ch * 4) * 4, src);
        }
        CP_COMMIT();
        if ((wid >> 2) == pass) {
#pragma unroll
            for (int mt = 0; mt < 4; mt++) {
                int lr = mt * 16 + (lane >> 2);
#pragma unroll
                for (int nt = 0; nt < 4; nt++) {
                    int lc = wn + nt * 8 + (lane & 3) * 2;
                    sts2f(zsm + (lr * FPAD + lc) * 4, acc[mt][nt][0], acc[mt][nt][1]);
                    sts2f(zsm + ((lr + 8) * FPAD + lc) * 4, acc[mt][nt][2], acc[mt][nt][3]);
                }
            }
        }
        CP_WAIT0();
        __syncthreads();

        // 2x2-blocked gram: lane -> (2q x 2k) block over half the D-range
        int bl = wid;
        int hh = lane >> 4;
        int q0 = ((lane >> 2) & 3) * 2;
        int k0 = (lane & 3) * 2;
        uint32_t z0 = zsm + ((bl * 8 + q0) * FPAD + hh * 64) * 4;
        uint32_t z1 = z0 + FPAD * 4;
        uint32_t f0 = fsm + ((bl * 8 + k0) * FPAD + hh * 64) * 4;
        uint32_t f1 = f0 + FPAD * 4;
        float s00 = 0.f, s01 = 0.f, s10 = 0.f, s11 = 0.f;
#pragma unroll
        for (int cc = 0; cc < 64; cc += 4) {
            float4 a0 = lds4f(z0 + cc * 4);
            float4 a1 = lds4f(z1 + cc * 4);
            float4 b0 = lds4f(f0 + cc * 4);
            float4 b1 = lds4f(f1 + cc * 4);
            s00 += a0.x * b0.x + a0.y * b0.y + a0.z * b0.z + a0.w * b0.w;
            s01 += a0.x * b1.x + a0.y * b1.y + a0.z * b1.z + a0.w * b1.w;
            s10 += a1.x * b0.x + a1.y * b0.y + a1.z * b0.z + a1.w * b0.w;
            s11 += a1.x * b1.x + a1.y * b1.y + a1.z * b1.z + a1.w * b1.w;
        }
        s00 += __shfl_xor_sync(0xFFFFFFFFu, s00, 16);
        s01 += __shfl_xor_sync(0xFFFFFFFFu, s01, 16);
        s10 += __shfl_xor_sync(0xFFFFFFFFu, s10, 16);
        s11 += __shfl_xor_sync(0xFFFFFFFFu, s11, 16);
        if (hh == 0) {
            size_t base = ((size_t)(blockIdx.y * 2 + side) * BATCH
                           + bb + pass * 8 + bl) * 64;
            g_Spart[base + q0 * 8 + k0]           = s00;
            g_Spart[base + q0 * 8 + k0 + 1]       = s01;
            g_Spart[base + (q0 + 1) * 8 + k0]     = s10;
            g_Spart[base + (q0 + 1) * 8 + k0 + 1] = s11;
        }
    }
}

// --------- final: softmax + att outputs + tiny head combine ----------------
__global__ void __launch_bounds__(128) att_final_kernel(
    const float* __restrict__ b_pred, float* __restrict__ d_out)
{
    const int b = blockIdx.x;
    const int t = threadIdx.x;
    __shared__ float sS[2][MOL][MOL];
    __shared__ float sProb[2][LQ][LQ];
    __shared__ float sAtt[2][LQ];
    __shared__ float sw[16];

    {
        int side = t >> 6, e = t & 63;
        float s = 0.f;
#pragma unroll
        for (int ct = 0; ct < 8; ct++)
            s += g_Spart[((size_t)(ct * 2 + side) * BATCH + b) * 64 + e];
        sS[side][e >> 3][e & 7] = s;
    }
    __syncthreads();

    if (t < 2 * LQ) {
        int sd = t / LQ, qq = t % LQ;
        int qi, qj;
        if (qq < MOL) { qi = qq; qj = -1; }
        else          { qi = c_pi[qq - MOL]; qj = c_pj[qq - MOL]; }
        float row[LQ];
        float maxv = -1e30f;
#pragma unroll
        for (int kk = 0; kk < LQ; kk++) {
            int ki, kj;
            if (kk < MOL) { ki = kk; kj = -1; }
            else          { ki = c_pi[kk - MOL]; kj = c_pj[kk - MOL]; }
            float v = sS[sd][qi][ki];
            if (kj >= 0) v += sS[sd][qi][kj];
            if (qj >= 0) {
                v += sS[sd][qj][ki];
                if (kj >= 0) v += sS[sd][qj][kj];
            }
            v *= 0.03125f;
            row[kk] = v;
            maxv = fmaxf(maxv, v);
        }
        float sum = 0.f;
#pragma unroll
        for (int kk = 0; kk < LQ; kk++) { row[kk] = expf(row[kk] - maxv); sum += row[kk]; }
        float inv = 1.f / sum;
#pragma unroll
        for (int kk = 0; kk < LQ; kk++) sProb[sd][qq][kk] = row[kk] * inv;
    }
    __syncthreads();

    if (t < 2 * LQ) {
        int sd = t / LQ, kk = t % LQ;
        float a = 0.f;
#pragma unroll
        for (int qq = 0; qq < LQ; qq++) a += sProb[sd][qq][kk];
        a *= (1.0f / LQ);
        sAtt[sd][kk] = a;
        d_out[BATCH * OUTD + sd * (BATCH * LQ) + b * LQ + kk] = a;
    }
    __syncthreads();

    if (t < 16) {
        int sd = t >> 3, m = t & 7;
        float w = sAtt[sd][m];
#pragma unroll
        for (int pp = 0; pp < NPAIR; pp++)
            if (c_pi[pp] == m || c_pj[pp] == m) w += sAtt[sd][MOL + pp];
        sw[sd * MOL + m] = w;
    }
    __syncthreads();

    if (t < OUTD) {
        float s = 0.f;
#pragma unroll
        for (int m = 0; m < MOL; m++) {
            s += sw[m]     * g_tr[((size_t)m * BATCH + b) * OUTD + t];
            s -= sw[8 + m] * g_tp[((size_t)m * BATCH + b) * OUTD + t];
        }
        d_out[b * OUTD + t] = s + b_pred[t];
    }
}

// ---------------------------------------------------------------------------
extern "C" void kernel_launch(void* const* d_in, const int* in_sizes, int n_in,
                              void* d_out, int out_size) {
    const float* r_feats = (const float*)d_in[0];
    const float* p_feats = (const float*)d_in[1];
    const float* r_new   = (const float*)d_in[2];
    const float* p_new   = (const float*)d_in[3];
    const float* Wq      = (const float*)d_in[4];
    const float* Wk      = (const float*)d_in[5];
    const float* W_pred  = (const float*)d_in[6];
    const float* b_pred  = (const float*)d_in[7];
    float* out = (float*)d_out;

    cudaFuncSetAttribute(aux_kernel, cudaFuncAttributeMaxDynamicSharedMemorySize,
                         SMEM_GEMM);
    cudaFuncSetAttribute(mma_gemm_fused, cudaFuncAttributeMaxDynamicSharedMemorySize,
                         SMEM_GEMM);

    __nv_bfloat16 *WqHi, *WqLo, *WkHi, *WkLo, *GtHi, *GtLo, *Xhi, *Xlo;
    cudaGetSymbolAddress((void**)&WqHi, g_WqHi);
    cudaGetSymbolAddress((void**)&WqLo, g_WqLo);
    cudaGetSymbolAddress((void**)&WkHi, g_WkHi);
    cudaGetSymbolAddress((void**)&WkLo, g_WkLo);
    cudaGetSymbolAddress((void**)&GtHi, g_GtHi);
    cudaGetSymbolAddress((void**)&GtLo, g_GtLo);
    cudaGetSymbolAddress((void**)&Xhi,  g_Xhi);
    cudaGetSymbolAddress((void**)&Xlo,  g_Xlo);

    // 1) weight splits
    split_w<<<2048, 128>>>(Wq, Wk);
    // 2) G-GEMM (64 CTAs) + split_x + head-dot precompute, one launch
    aux_kernel<<<64 + MROWS / 2, 256, SMEM_GEMM>>>(WqHi, WqLo, WkHi, WkLo,
                                                   p_feats, r_feats,
                                                   p_new, r_new, W_pred);
    // 3) fused GEMM + gram epilogue
    mma_gemm_fused<<<dim3(256, 8), 256, SMEM_GEMM>>>(Xhi, Xlo, GtHi, GtLo,
                                                     r_feats, p_feats);
    // 4) softmax + att outputs + tiny head combine
    att_final_kernel<<<BATCH, 128>>>(b_pred, out);
}

// round 13
// speedup vs baseline: 1.5291x; 1.2502x over previous
#include <cuda_runtime.h>
#include <cuda_bf16.h>
#include <cuda_fp16.h>
#include <cstdint>

constexpr int BATCH = 2048;
constexpr int DIM   = 1024;
constexpr int MOL   = 8;
constexpr int NPAIR = 28;
constexpr int LQ    = 36;
constexpr int OUTD  = 4;
constexpr int MROWS = 32768;           // 2 * BATCH * MOL

__constant__ int c_pi[NPAIR] = {0,0,0,0,0,0,0,1,1,1,1,1,1,2,2,2,2,2,3,3,3,3,4,4,4,5,5,6};
__constant__ int c_pj[NPAIR] = {1,2,3,4,5,6,7,2,3,4,5,6,7,3,4,5,6,7,4,5,6,7,5,6,7,6,7,7};

// ------------------------- static device scratch ---------------------------
__device__ __nv_bfloat16 g_WqHi[DIM * DIM];
__device__ __nv_bfloat16 g_WqLo[DIM * DIM];
__device__ __nv_bfloat16 g_WkHi[DIM * DIM];
__device__ __nv_bfloat16 g_WkLo[DIM * DIM];
__device__ __half        g_Gt[DIM * DIM];            // fp16 Gt[n][k] = G[k][n]
__device__ __half        g_Xhi[(size_t)MROWS * DIM]; // fp16 hi
__device__ __half        g_Xlo[(size_t)MROWS * DIM]; // fp16 lo (x exact as hi+lo)
__device__ float         g_Spart[8ull * 2 * BATCH * 64];  // 4 MB partial grams
__device__ float         g_tr[MOL * BATCH * OUTD];
__device__ float         g_tp[MOL * BATCH * OUTD];

// ------------------------------ helpers ------------------------------------
__device__ __forceinline__ uint32_t s2u(const void* p) {
    uint32_t a;
    asm("{ .reg .u64 t; cvta.to.shared.u64 t, %1; cvt.u32.u64 %0, t; }" : "=r"(a) : "l"(p));
    return a;
}
__device__ __forceinline__ void cpa16(uint32_t d, const void* g) {
    asm volatile("cp.async.cg.shared.global [%0], [%1], 16;" :: "r"(d), "l"(g));
}
#define CP_COMMIT()  asm volatile("cp.async.commit_group;" ::: "memory")
#define CP_WAIT0()   asm volatile("cp.async.wait_group 0;" ::: "memory")

__device__ __forceinline__ float4 lds4f(uint32_t a) {
    float4 v;
    asm volatile("ld.shared.v4.f32 {%0,%1,%2,%3}, [%4];"
        : "=f"(v.x), "=f"(v.y), "=f"(v.z), "=f"(v.w) : "r"(a));
    return v;
}
__device__ __forceinline__ float lds1f(uint32_t a) {
    float v;
    asm volatile("ld.shared.f32 %0, [%1];" : "=f"(v) : "r"(a));
    return v;
}
__device__ __forceinline__ void sts2f(uint32_t a, float x, float y) {
    asm volatile("st.shared.v2.f32 [%0], {%1,%2};" :: "r"(a), "f"(x), "f"(y));
}

__device__ __forceinline__ void lda4(uint32_t* f, uint32_t mbase, int wm, int mt,
                                     int ks, int lane) {
    int g = lane >> 3, r = lane & 7;
    int mloc = wm + mt * 16 + (g & 1) * 8 + r;
    int kloc = ks * 16 + (g >> 1) * 8;
    uint32_t a = mbase + (mloc * 40 + kloc) * 2;
    asm volatile("ldmatrix.sync.aligned.m8n8.x4.shared.b16 {%0,%1,%2,%3}, [%4];"
        : "=r"(f[0]), "=r"(f[1]), "=r"(f[2]), "=r"(f[3]) : "r"(a));
}
// B fragments for TWO adjacent nt tiles in one x4
__device__ __forceinline__ void ldb4(uint32_t* f, uint32_t mbase, int wn, int ntp,
                                     int ks, int lane) {
    int g = lane >> 3, r = lane & 7;
    int nloc = wn + ntp * 16 + (g >> 1) * 8 + r;
    int kloc = ks * 16 + (g & 1) * 8;
    uint32_t a = mbase + (nloc * 40 + kloc) * 2;
    asm volatile("ldmatrix.sync.aligned.m8n8.x4.shared.b16 {%0,%1,%2,%3}, [%4];"
        : "=r"(f[0]), "=r"(f[1]), "=r"(f[2]), "=r"(f[3]) : "r"(a));
}
__device__ __forceinline__ void mma_bf(float* c, const uint32_t* a, const uint32_t* b) {
    asm volatile("mma.sync.aligned.m16n8k16.row.col.f32.bf16.bf16.f32 "
        "{%0,%1,%2,%3}, {%4,%5,%6,%7}, {%8,%9}, {%0,%1,%2,%3};"
        : "+f"(c[0]), "+f"(c[1]), "+f"(c[2]), "+f"(c[3])
        : "r"(a[0]), "r"(a[1]), "r"(a[2]), "r"(a[3]), "r"(b[0]), "r"(b[1]));
}
__device__ __forceinline__ void mma_hf(float* c, const uint32_t* a, const uint32_t* b) {
    asm volatile("mma.sync.aligned.m16n8k16.row.col.f32.f16.f16.f32 "
        "{%0,%1,%2,%3}, {%4,%5,%6,%7}, {%8,%9}, {%0,%1,%2,%3};"
        : "+f"(c[0]), "+f"(c[1]), "+f"(c[2]), "+f"(c[3])
        : "r"(a[0]), "r"(a[1]), "r"(a[2]), "r"(a[3]), "r"(b[0]), "r"(b[1]));
}

union BfPack { __nv_bfloat16 h[8]; uint4 u; };
union HfPack { __half h[8]; uint4 u; };

// ------------------------- split_w kernel (bf16, for G-GEMM) ---------------
__global__ void __launch_bounds__(128) split_w(const float* __restrict__ Wq,
                                               const float* __restrict__ Wk) {
    int bx = blockIdx.x;
    int mat = bx >> 10, row = bx & 1023;
    const float* src = (mat ? Wk : Wq) + (size_t)row * DIM;
    __nv_bfloat16* hi = (mat ? g_WkHi : g_WqHi) + (size_t)row * DIM;
    __nv_bfloat16* lo = (mat ? g_WkLo : g_WqLo) + (size_t)row * DIM;
    int t = threadIdx.x;
    float4 v0 = ((const float4*)src)[t * 2];
    float4 v1 = ((const float4*)src)[t * 2 + 1];
    float vv[8] = {v0.x, v0.y, v0.z, v0.w, v1.x, v1.y, v1.z, v1.w};
    BfPack hp, lp;
#pragma unroll
    for (int i = 0; i < 8; i++) {
        __nv_bfloat16 h = __float2bfloat16_rn(vv[i]);
        hp.h[i] = h;
        lp.h[i] = __float2bfloat16_rn(vv[i] - __bfloat162float(h));
    }
    ((uint4*)(hi))[t] = hp.u;
    ((uint4*)(lo))[t] = lp.u;
}

// ------------------------- GEMM constants ----------------------------------
constexpr int MAT_ELE   = 128 * 40;             // elements per matrix tile
constexpr int STAGE_B4  = 4 * MAT_ELE * 2;      // bf16 3-term stage (G-GEMM)
constexpr int SMEM_G    = 2 * STAGE_B4;         // 81920
constexpr int STAGE_B3  = 3 * MAT_ELE * 2;      // fp16 2-term stage (main)
constexpr int FPAD      = 132;
constexpr int SMEM_MAIN = 2 * 64 * FPAD * 4;    // 67584 (> 2*STAGE_B3=61440)

// ---------------- bf16 4-matrix loader + 3-term compute (G-GEMM) -----------
__device__ __forceinline__ void load_chunk4(
    uint32_t sbase, int stage,
    const __nv_bfloat16* __restrict__ Ahi, const __nv_bfloat16* __restrict__ Alo,
    const __nv_bfloat16* __restrict__ Bhi, const __nv_bfloat16* __restrict__ Blo,
    int rowBase, int colBase, int k0, int tid)
{
    uint32_t st = sbase + stage * STAGE_B4;
#pragma unroll
    for (int mat = 0; mat < 4; mat++) {
        const __nv_bfloat16* src0 =
            (mat == 0) ? Ahi : (mat == 1) ? Alo : (mat == 2) ? Bhi : Blo;
        int base = (mat < 2) ? rowBase : colBase;
#pragma unroll
        for (int h = 0; h < 2; h++) {
            int idx = h * 256 + tid;
            int row = idx >> 2, ch = idx & 3;
            const __nv_bfloat16* src = src0 + (size_t)(base + row) * DIM + k0 + ch * 8;
            uint32_t dst = st + (mat * MAT_ELE + row * 40 + ch * 8) * 2;
            cpa16(dst, src);
        }
    }
    CP_COMMIT();
}

__device__ __forceinline__ void compute_ks4(
    float acc[4][4][4], uint32_t stb, int wm, int wn, int lane, int ks)
{
    uint32_t bAhi = stb;
    uint32_t bAlo = stb + MAT_ELE * 2;
    uint32_t bBhi = stb + 2 * MAT_ELE * 2;
    uint32_t bBlo = stb + 3 * MAT_ELE * 2;
    uint32_t bhif[8], blof[8];
    ldb4(bhif,     bBhi, wn, 0, ks, lane);
    ldb4(bhif + 4, bBhi, wn, 1, ks, lane);
    ldb4(blof,     bBlo, wn, 0, ks, lane);
    ldb4(blof + 4, bBlo, wn, 1, ks, lane);
#pragma unroll
    for (int mt = 0; mt < 4; mt++) {
        uint32_t ahif[4], alof[4];
        lda4(ahif, bAhi, wm, mt, ks, lane);
        lda4(alof, bAlo, wm, mt, ks, lane);
#pragma unroll
        for (int nt = 0; nt < 4; nt++) {
            mma_bf(acc[mt][nt], ahif, bhif + nt * 2);
            mma_bf(acc[mt][nt], alof, bhif + nt * 2);
            mma_bf(acc[mt][nt], ahif, blof + nt * 2);
        }
    }
}

// --------- G GEMM body: C = Wq@Wk^T, epilogue writes fp16 Gt (transposed) --
__device__ void gemm_g_body(
    const __nv_bfloat16* __restrict__ Ahi, const __nv_bfloat16* __restrict__ Alo,
    const __nv_bfloat16* __restrict__ Bhi, const __nv_bfloat16* __restrict__ Blo,
    int gb)
{
    extern __shared__ char smem[];
    uint32_t sbase = s2u(smem);
    const int tid  = threadIdx.x;
    const int lane = tid & 31;
    const int wid  = tid >> 5;
    const int wm = (wid >> 2) * 64;
    const int wn = (wid & 3) * 32;
    const int rowBase = (gb & 7) * 128;   // k of Gt
    const int colBase = (gb >> 3) * 128;  // n of Gt

    float acc[4][4][4];
#pragma unroll
    for (int i = 0; i < 4; i++)
#pragma unroll
        for (int j = 0; j < 4; j++)
#pragma unroll
            for (int q = 0; q < 4; q++) acc[i][j][q] = 0.f;

    load_chunk4(sbase, 0, Ahi, Alo, Bhi, Blo, rowBase, colBase, 0, tid);
    for (int c = 0; c < 32; ++c) {
        int s = c & 1;
        CP_WAIT0();
        __syncthreads();
        compute_ks4(acc, sbase + s * STAGE_B4, wm, wn, lane, 0);
        if (c < 31)
            load_chunk4(sbase, s ^ 1, Ahi, Alo, Bhi, Blo, rowBase, colBase,
                        (c + 1) * 32, tid);
        compute_ks4(acc, sbase + s * STAGE_B4, wm, wn, lane, 1);
    }

    __syncthreads();
#pragma unroll
    for (int mt = 0; mt < 4; mt++) {
        int lr = wm + mt * 16 + (lane >> 2);
#pragma unroll
        for (int nt = 0; nt < 4; nt++) {
            int lc = wn + nt * 8 + (lane & 3) * 2;
            sts2f(sbase + (lr * FPAD + lc) * 4, acc[mt][nt][0], acc[mt][nt][1]);
            sts2f(sbase + ((lr + 8) * FPAD + lc) * 4, acc[mt][nt][2], acc[mt][nt][3]);
        }
    }
    __syncthreads();

    // transpose-read + fp16 round + coalesced store (Gt hi only)
    int n_local = tid >> 1;
    int kh = (tid & 1) * 64;
    size_t gbase = (size_t)(colBase + n_local) * DIM + rowBase + kh;
#pragma unroll
    for (int kb = 0; kb < 64; kb += 8) {
        HfPack hp;
#pragma unroll
        for (int i = 0; i < 8; i++) {
            float v = lds1f(sbase + ((kh + kb + i) * FPAD + n_local) * 4);
            hp.h[i] = __float2half_rn(v);
        }
        *(uint4*)(g_Gt + gbase + kb) = hp.u;
    }
}

// --------- split_x body: gather + fp16 hi/lo split + head-dot precompute ---
__device__ void split_x_body(const float* __restrict__ p,
                             const float* __restrict__ r,
                             const float* __restrict__ pn,
                             const float* __restrict__ rn,
                             const float* __restrict__ W_pred, int bx)
{
    __shared__ float sdot[2][4][OUTD];
    int t = threadIdx.x;
    int half = t >> 7;
    int row = bx * 2 + half;
    int tt = t & 127;
    int s = row >> 14, b = (row >> 3) & (BATCH - 1), m = row & 7;
    size_t off = ((size_t)m * BATCH + b) * DIM;
    const float* src  = (s ? r : p) + off;
    const float* nsrc = (s ? rn : pn) + off;
    float4 v0 = ((const float4*)src)[tt * 2];
    float4 v1 = ((const float4*)src)[tt * 2 + 1];
    float vv[8] = {v0.x, v0.y, v0.z, v0.w, v1.x, v1.y, v1.z, v1.w};
    HfPack hp, lp;
#pragma unroll
    for (int i = 0; i < 8; i++) {
        __half h = __float2half_rn(vv[i]);
        hp.h[i] = h;
        lp.h[i] = __float2half_rn(vv[i] - __half2float(h));
    }
    ((uint4*)(g_Xhi + (size_t)row * DIM))[tt] = hp.u;
    ((uint4*)(g_Xlo + (size_t)row * DIM))[tt] = lp.u;

    // head-dot precompute: (v + n) . W_pred[o]
    float4 n0 = ((const float4*)nsrc)[tt * 2];
    float4 n1 = ((const float4*)nsrc)[tt * 2 + 1];
    float sv[8] = {vv[0] + n0.x, vv[1] + n0.y, vv[2] + n0.z, vv[3] + n0.w,
                   vv[4] + n1.x, vv[5] + n1.y, vv[6] + n1.z, vv[7] + n1.w};
    float dot[OUTD];
#pragma unroll
    for (int o = 0; o < OUTD; o++) {
        const float4* wrow = (const float4*)(W_pred + (size_t)o * DIM);
        float4 w0 = wrow[tt * 2];
        float4 w1 = wrow[tt * 2 + 1];
        dot[o] = sv[0] * w0.x + sv[1] * w0.y + sv[2] * w0.z + sv[3] * w0.w
               + sv[4] * w1.x + sv[5] * w1.y + sv[6] * w1.z + sv[7] * w1.w;
    }
    int lane = t & 31, w = tt >> 5;
#pragma unroll
    for (int o = 0; o < OUTD; o++) {
#pragma unroll
        for (int ofs = 16; ofs > 0; ofs >>= 1)
            dot[o] += __shfl_down_sync(0xFFFFFFFFu, dot[o], ofs);
        if (lane == 0) sdot[half][w][o] = dot[o];
    }
    __syncthreads();
    if (tt < OUTD) {
        float ssum = sdot[half][0][tt] + sdot[half][1][tt]
                   + sdot[half][2][tt] + sdot[half][3][tt];
        float* dst = s ? g_tr : g_tp;
        dst[((size_t)m * BATCH + b) * OUTD + tt] = ssum;
    }
}

// --------- combined aux: G-GEMM (64 CTAs) overlapped with split_x ----------
__global__ void __launch_bounds__(256) aux_kernel(
    const __nv_bfloat16* __restrict__ WqHi, const __nv_bfloat16* __restrict__ WqLo,
    const __nv_bfloat16* __restrict__ WkHi, const __nv_bfloat16* __restrict__ WkLo,
    const float* __restrict__ p_feats, const float* __restrict__ r_feats,
    const float* __restrict__ p_new,   const float* __restrict__ r_new,
    const float* __restrict__ W_pred)
{
    if (blockIdx.x < 64)
        gemm_g_body(WqHi, WqLo, WkHi, WkLo, blockIdx.x);
    else
        split_x_body(p_feats, r_feats, p_new, r_new, W_pred, blockIdx.x - 64);
}

// ---------------- fp16 3-matrix loader + 2-term compute (main) -------------
__device__ __forceinline__ void load_chunk3(
    uint32_t sbase, int stage,
    const __half* __restrict__ Ahi, const __half* __restrict__ Alo,
    const __half* __restrict__ B,
    int rowBase, int colBase, int k0, int tid)
{
    uint32_t st = sbase + stage * STAGE_B3;
#pragma unroll
    for (int mat = 0; mat < 3; mat++) {
        const __half* src0 = (mat == 0) ? Ahi : (mat == 1) ? Alo : B;
        int base = (mat < 2) ? rowBase : colBase;
#pragma unroll
        for (int h = 0; h < 2; h++) {
            int idx = h * 256 + tid;
            int row = idx >> 2, ch = idx & 3;
            const __half* src = src0 + (size_t)(base + row) * DIM + k0 + ch * 8;
            uint32_t dst = st + (mat * MAT_ELE + row * 40 + ch * 8) * 2;
            cpa16(dst, src);
        }
    }
    CP_COMMIT();
}

__device__ __forceinline__ void compute_ks3(
    float acc[4][4][4], uint32_t stb, int wm, int wn, int lane, int ks)
{
    uint32_t bAhi = stb;
    uint32_t bAlo = stb + MAT_ELE * 2;
    uint32_t bB   = stb + 2 * MAT_ELE * 2;
    uint32_t bf[8];
    ldb4(bf,     bB, wn, 0, ks, lane);
    ldb4(bf + 4, bB, wn, 1, ks, lane);
#pragma unroll
    for (int mt = 0; mt < 4; mt++) {
        uint32_t ahif[4], alof[4];
        lda4(ahif, bAhi, wm, mt, ks, lane);
        lda4(alof, bAlo, wm, mt, ks, lane);
#pragma unroll
        for (int nt = 0; nt < 4; nt++) {
            mma_hf(acc[mt][nt], ahif, bf + nt * 2);
            mma_hf(acc[mt][nt], alof, bf + nt * 2);
        }
    }
}

// --------------- fused GEMM (Z = X@G, fp16 2-term) + gram epilogue ---------
__global__ void __launch_bounds__(256, 2) mma_gemm_fused(
    const __half* __restrict__ Ahi, const __half* __restrict__ Alo,
    const __half* __restrict__ B,
    const float* __restrict__ fR, const float* __restrict__ fP)
{
    extern __shared__ char smem[];
    uint32_t sbase = s2u(smem);
    const int tid  = threadIdx.x;
    const int lane = tid & 31;
    const int wid  = tid >> 5;
    const int wm = (wid >> 2) * 64;
    const int wn = (wid & 3) * 32;
    const int rowBase = blockIdx.x * 128;
    const int colBase = blockIdx.y * 128;

    float acc[4][4][4];
#pragma unroll
    for (int i = 0; i < 4; i++)
#pragma unroll
        for (int j = 0; j < 4; j++)
#pragma unroll
            for (int q = 0; q < 4; q++) acc[i][j][q] = 0.f;

    load_chunk3(sbase, 0, Ahi, Alo, B, rowBase, colBase, 0, tid);
    for (int c = 0; c < 32; ++c) {
        int s = c & 1;
        CP_WAIT0();
        __syncthreads();
        compute_ks3(acc, sbase + s * STAGE_B3, wm, wn, lane, 0);
        if (c < 31)
            load_chunk3(sbase, s ^ 1, Ahi, Alo, B, rowBase, colBase,
                        (c + 1) * 32, tid);
        compute_ks3(acc, sbase + s * STAGE_B3, wm, wn, lane, 1);
    }

    // gram epilogue: row tile = side, batches bb..bb+15, 8 query mols
    const int side = blockIdx.x >> 7;
    const int bb = (blockIdx.x & 127) * 16;
    const float* keys = side ? fP : fR;
    uint32_t zsm = sbase;
    uint32_t fsm = sbase + 64 * FPAD * 4;

#pragma unroll
    for (int pass = 0; pass < 2; pass++) {
        __syncthreads();
        // F loads first (latency hidden behind Z smem stores)
#pragma unroll
        for (int h = 0; h < 8; h++) {
            int idx = h * 256 + tid;
            int rowi = idx >> 5, ch = idx & 31;
            int bl = rowi >> 3, kk2 = rowi & 7;
            const float* src = keys +
                ((size_t)kk2 * BATCH + (bb + pass * 8 + bl)) * DIM + colBase + ch * 4;
            cpa16(fsm + (rowi * FPAD + ch * 4) * 4, src);
        }
        CP_COMMIT();
        if ((wid >> 2) == pass) {
#pragma unroll
            for (int mt = 0; mt < 4; mt++) {
                int lr = mt * 16 + (lane >> 2);
#pragma unroll
                for (int nt = 0; nt < 4; nt++) {
                    int lc = wn + nt * 8 + (lane & 3) * 2;
                    sts2f(zsm + (lr * FPAD + lc) * 4, acc[mt][nt][0], acc[mt][nt][1]);
                    sts2f(zsm + ((lr + 8) * FPAD + lc) * 4, acc[mt][nt][2], acc[mt][nt][3]);
                }
            }
        }
        CP_WAIT0();
        __syncthreads();

        // 2x2-blocked gram: lane -> (2q x 2k) block over half the D-range
        int bl = wid;
        int hh = lane >> 4;
        int q0 = ((lane >> 2) & 3) * 2;
        int k0 = (lane & 3) * 2;
        uint32_t z0 = zsm + ((bl * 8 + q0) * FPAD + hh * 64) * 4;
        uint32_t z1 = z0 + FPAD * 4;
        uint32_t f0 = fsm + ((bl * 8 + k0) * FPAD + hh * 64) * 4;
        uint32_t f1 = f0 + FPAD * 4;
        float s00 = 0.f, s01 = 0.f, s10 = 0.f, s11 = 0.f;
#pragma unroll
        for (int cc = 0; cc < 64; cc += 4) {
            float4 a0 = lds4f(z0 + cc * 4);
            float4 a1 = lds4f(z1 + cc * 4);
            float4 b0 = lds4f(f0 + cc * 4);
            float4 b1 = lds4f(f1 + cc * 4);
            s00 += a0.x * b0.x + a0.y * b0.y + a0.z * b0.z + a0.w * b0.w;
            s01 += a0.x * b1.x + a0.y * b1.y + a0.z * b1.z + a0.w * b1.w;
            s10 += a1.x * b0.x + a1.y * b0.y + a1.z * b0.z + a1.w * b0.w;
            s11 += a1.x * b1.x + a1.y * b1.y + a1.z * b1.z + a1.w * b1.w;
        }
        s00 += __shfl_xor_sync(0xFFFFFFFFu, s00, 16);
        s01 += __shfl_xor_sync(0xFFFFFFFFu, s01, 16);
        s10 += __shfl_xor_sync(0xFFFFFFFFu, s10, 16);
        s11 += __shfl_xor_sync(0xFFFFFFFFu, s11, 16);
        if (hh == 0) {
            size_t base = ((size_t)(blockIdx.y * 2 + side) * BATCH
                           + bb + pass * 8 + bl) * 64;
            g_Spart[base + q0 * 8 + k0]           = s00;
            g_Spart[base + q0 * 8 + k0 + 1]       = s01;
            g_Spart[base + (q0 + 1) * 8 + k0]     = s10;
            g_Spart[base + (q0 + 1) * 8 + k0 + 1] = s11;
        }
    }
}

// --------- final: softmax + att outputs + tiny head combine ----------------
__global__ void __launch_bounds__(128) att_final_kernel(
    const float* __restrict__ b_pred, float* __restrict__ d_out)
{
    const int b = blockIdx.x;
    const int t = threadIdx.x;
    __shared__ float sS[2][MOL][MOL];
    __shared__ float sProb[2][LQ][LQ];
    __shared__ float sAtt[2][LQ];
    __shared__ float sw[16];

    {
        int side = t >> 6, e = t & 63;
        float s = 0.f;
#pragma unroll
        for (int ct = 0; ct < 8; ct++)
            s += g_Spart[((size_t)(ct * 2 + side) * BATCH + b) * 64 + e];
        sS[side][e >> 3][e & 7] = s;
    }
    __syncthreads();

    if (t < 2 * LQ) {
        int sd = t / LQ, qq = t % LQ;
        int qi, qj;
        if (qq < MOL) { qi = qq; qj = -1; }
        else          { qi = c_pi[qq - MOL]; qj = c_pj[qq - MOL]; }
        float row[LQ];
        float maxv = -1e30f;
#pragma unroll
        for (int kk = 0; kk < LQ; kk++) {
            int ki, kj;
            if (kk < MOL) { ki = kk; kj = -1; }
            else          { ki = c_pi[kk - MOL]; kj = c_pj[kk - MOL]; }
            float v = sS[sd][qi][ki];
            if (kj >= 0) v += sS[sd][qi][kj];
            if (qj >= 0) {
                v += sS[sd][qj][ki];
                if (kj >= 0) v += sS[sd][qj][kj];
            }
            v *= 0.03125f;
            row[kk] = v;
            maxv = fmaxf(maxv, v);
        }
        float sum = 0.f;
#pragma unroll
        for (int kk = 0; kk < LQ; kk++) { row[kk] = expf(row[kk] - maxv); sum += row[kk]; }
        float inv = 1.f / sum;
#pragma unroll
        for (int kk = 0; kk < LQ; kk++) sProb[sd][qq][kk] = row[kk] * inv;
    }
    __syncthreads();

    if (t < 2 * LQ) {
        int sd = t / LQ, kk = t % LQ;
        float a = 0.f;
#pragma unroll
        for (int qq = 0; qq < LQ; qq++) a += sProb[sd][qq][kk];
        a *= (1.0f / LQ);
        sAtt[sd][kk] = a;
        d_out[BATCH * OUTD + sd * (BATCH * LQ) + b * LQ + kk] = a;
    }
    __syncthreads();

    if (t < 16) {
        int sd = t >> 3, m = t & 7;
        float w = sAtt[sd][m];
#pragma unroll
        for (int pp = 0; pp < NPAIR; pp++)
            if (c_pi[pp] == m || c_pj[pp] == m) w += sAtt[sd][MOL + pp];
        sw[sd * MOL + m] = w;
    }
    __syncthreads();

    if (t < OUTD) {
        float s = 0.f;
#pragma unroll
        for (int m = 0; m < MOL; m++) {
            s += sw[m]     * g_tr[((size_t)m * BATCH + b) * OUTD + t];
            s -= sw[8 + m] * g_tp[((size_t)m * BATCH + b) * OUTD + t];
        }
        d_out[b * OUTD + t] = s + b_pred[t];
    }
}

// ---------------------------------------------------------------------------
extern "C" void kernel_launch(void* const* d_in, const int* in_sizes, int n_in,
                              void* d_out, int out_size) {
    const float* r_feats = (const float*)d_in[0];
    const float* p_feats = (const float*)d_in[1];
    const float* r_new   = (const float*)d_in[2];
    const float* p_new   = (const float*)d_in[3];
    const float* Wq      = (const float*)d_in[4];
    const float* Wk      = (const float*)d_in[5];
    const float* W_pred  = (const float*)d_in[6];
    const float* b_pred  = (const float*)d_in[7];
    float* out = (float*)d_out;

    cudaFuncSetAttribute(aux_kernel, cudaFuncAttributeMaxDynamicSharedMemorySize,
                         SMEM_G);
    cudaFuncSetAttribute(mma_gemm_fused, cudaFuncAttributeMaxDynamicSharedMemorySize,
                         SMEM_MAIN);

    __nv_bfloat16 *WqHi, *WqLo, *WkHi, *WkLo;
    __half *Gt, *Xhi, *Xlo;
    cudaGetSymbolAddress((void**)&WqHi, g_WqHi);
    cudaGetSymbolAddress((void**)&WqLo, g_WqLo);
    cudaGetSymbolAddress((void**)&WkHi, g_WkHi);
    cudaGetSymbolAddress((void**)&WkLo, g_WkLo);
    cudaGetSymbolAddress((void**)&Gt,   g_Gt);
    cudaGetSymbolAddress((void**)&Xhi,  g_Xhi);
    cudaGetSymbolAddress((void**)&Xlo,  g_Xlo);

    // 1) weight splits (bf16, feeds accurate 3-term G-GEMM)
    split_w<<<2048, 128>>>(Wq, Wk);
    // 2) G-GEMM (64 CTAs, bf16 3-term) + split_x (fp16) + head-dots, one launch
    aux_kernel<<<64 + MROWS / 2, 256, SMEM_G>>>(WqHi, WqLo, WkHi, WkLo,
                                                p_feats, r_feats,
                                                p_new, r_new, W_pred);
    // 3) fused GEMM (fp16 2-term) + gram epilogue
    mma_gemm_fused<<<dim3(256, 8), 256, SMEM_MAIN>>>(Xhi, Xlo, Gt,
                                                     r_feats, p_feats);
    // 4) softmax + att outputs + tiny head combine
    att_final_kernel<<<BATCH, 128>>>(b_pred, out);
}

// round 14
// speedup vs baseline: 1.9978x; 1.3065x over previous
#include <cuda_runtime.h>
#include <cuda_bf16.h>
#include <cuda_fp16.h>
#include <cstdint>

constexpr int BATCH = 2048;
constexpr int DIM   = 1024;
constexpr int MOL   = 8;
constexpr int NPAIR = 28;
constexpr int LQ    = 36;
constexpr int OUTD  = 4;
constexpr int MROWS = 32768;           // 2 * BATCH * MOL

__constant__ int c_pi[NPAIR] = {0,0,0,0,0,0,0,1,1,1,1,1,1,2,2,2,2,2,3,3,3,3,4,4,4,5,5,6};
__constant__ int c_pj[NPAIR] = {1,2,3,4,5,6,7,2,3,4,5,6,7,3,4,5,6,7,4,5,6,7,5,6,7,6,7,7};

// ------------------------- static device scratch ---------------------------
__device__ __nv_bfloat16 g_WqHi[DIM * DIM];
__device__ __nv_bfloat16 g_WqLo[DIM * DIM];
__device__ __nv_bfloat16 g_WkHi[DIM * DIM];
__device__ __nv_bfloat16 g_WkLo[DIM * DIM];
__device__ __half        g_Gt[DIM * DIM];            // fp16 Gt[n][k] = G[k][n]
__device__ __half        g_X[(size_t)MROWS * DIM];   // fp16 x (1-term)
__device__ float         g_Spart[8ull * 2 * BATCH * 64];  // 4 MB partial grams
__device__ float         g_tr[MOL * BATCH * OUTD];
__device__ float         g_tp[MOL * BATCH * OUTD];

// ------------------------------ helpers ------------------------------------
__device__ __forceinline__ uint32_t s2u(const void* p) {
    uint32_t a;
    asm("{ .reg .u64 t; cvta.to.shared.u64 t, %1; cvt.u32.u64 %0, t; }" : "=r"(a) : "l"(p));
    return a;
}
__device__ __forceinline__ void cpa16(uint32_t d, const void* g) {
    asm volatile("cp.async.cg.shared.global [%0], [%1], 16;" :: "r"(d), "l"(g));
}
#define CP_COMMIT()  asm volatile("cp.async.commit_group;" ::: "memory")
#define CP_WAIT0()   asm volatile("cp.async.wait_group 0;" ::: "memory")

__device__ __forceinline__ float4 lds4f(uint32_t a) {
    float4 v;
    asm volatile("ld.shared.v4.f32 {%0,%1,%2,%3}, [%4];"
        : "=f"(v.x), "=f"(v.y), "=f"(v.z), "=f"(v.w) : "r"(a));
    return v;
}
__device__ __forceinline__ float lds1f(uint32_t a) {
    float v;
    asm volatile("ld.shared.f32 %0, [%1];" : "=f"(v) : "r"(a));
    return v;
}
__device__ __forceinline__ void sts2f(uint32_t a, float x, float y) {
    asm volatile("st.shared.v2.f32 [%0], {%1,%2};" :: "r"(a), "f"(x), "f"(y));
}

__device__ __forceinline__ void lda4(uint32_t* f, uint32_t mbase, int wm, int mt,
                                     int ks, int lane) {
    int g = lane >> 3, r = lane & 7;
    int mloc = wm + mt * 16 + (g & 1) * 8 + r;
    int kloc = ks * 16 + (g >> 1) * 8;
    uint32_t a = mbase + (mloc * 40 + kloc) * 2;
    asm volatile("ldmatrix.sync.aligned.m8n8.x4.shared.b16 {%0,%1,%2,%3}, [%4];"
        : "=r"(f[0]), "=r"(f[1]), "=r"(f[2]), "=r"(f[3]) : "r"(a));
}
// B fragments for TWO adjacent nt tiles in one x4
__device__ __forceinline__ void ldb4(uint32_t* f, uint32_t mbase, int wn, int ntp,
                                     int ks, int lane) {
    int g = lane >> 3, r = lane & 7;
    int nloc = wn + ntp * 16 + (g >> 1) * 8 + r;
    int kloc = ks * 16 + (g & 1) * 8;
    uint32_t a = mbase + (nloc * 40 + kloc) * 2;
    asm volatile("ldmatrix.sync.aligned.m8n8.x4.shared.b16 {%0,%1,%2,%3}, [%4];"
        : "=r"(f[0]), "=r"(f[1]), "=r"(f[2]), "=r"(f[3]) : "r"(a));
}
__device__ __forceinline__ void mma_bf(float* c, const uint32_t* a, const uint32_t* b) {
    asm volatile("mma.sync.aligned.m16n8k16.row.col.f32.bf16.bf16.f32 "
        "{%0,%1,%2,%3}, {%4,%5,%6,%7}, {%8,%9}, {%0,%1,%2,%3};"
        : "+f"(c[0]), "+f"(c[1]), "+f"(c[2]), "+f"(c[3])
        : "r"(a[0]), "r"(a[1]), "r"(a[2]), "r"(a[3]), "r"(b[0]), "r"(b[1]));
}
__device__ __forceinline__ void mma_hf(float* c, const uint32_t* a, const uint32_t* b) {
    asm volatile("mma.sync.aligned.m16n8k16.row.col.f32.f16.f16.f32 "
        "{%0,%1,%2,%3}, {%4,%5,%6,%7}, {%8,%9}, {%0,%1,%2,%3};"
        : "+f"(c[0]), "+f"(c[1]), "+f"(c[2]), "+f"(c[3])
        : "r"(a[0]), "r"(a[1]), "r"(a[2]), "r"(a[3]), "r"(b[0]), "r"(b[1]));
}

union BfPack { __nv_bfloat16 h[8]; uint4 u; };
union HfPack { __half h[8]; uint4 u; };

// ------------------------- split_w kernel (bf16, for G-GEMM) ---------------
__global__ void __launch_bounds__(128) split_w(const float* __restrict__ Wq,
                                               const float* __restrict__ Wk) {
    int bx = blockIdx.x;
    int mat = bx >> 10, row = bx & 1023;
    const float* src = (mat ? Wk : Wq) + (size_t)row * DIM;
    __nv_bfloat16* hi = (mat ? g_WkHi : g_WqHi) + (size_t)row * DIM;
    __nv_bfloat16* lo = (mat ? g_WkLo : g_WqLo) + (size_t)row * DIM;
    int t = threadIdx.x;
    float4 v0 = ((const float4*)src)[t * 2];
    float4 v1 = ((const float4*)src)[t * 2 + 1];
    float vv[8] = {v0.x, v0.y, v0.z, v0.w, v1.x, v1.y, v1.z, v1.w};
    BfPack hp, lp;
#pragma unroll
    for (int i = 0; i < 8; i++) {
        __nv_bfloat16 h = __float2bfloat16_rn(vv[i]);
        hp.h[i] = h;
        lp.h[i] = __float2bfloat16_rn(vv[i] - __bfloat162float(h));
    }
    ((uint4*)(hi))[t] = hp.u;
    ((uint4*)(lo))[t] = lp.u;
}

// ------------------------- GEMM constants ----------------------------------
constexpr int MAT_ELE   = 128 * 40;             // elements per matrix tile
constexpr int STAGE_B4  = 4 * MAT_ELE * 2;      // bf16 3-term stage (G-GEMM)
constexpr int SMEM_G    = 2 * STAGE_B4;         // 81920
constexpr int STAGE_B2  = 2 * MAT_ELE * 2;      // fp16 1-term stage (main)
constexpr int FPAD      = 132;
constexpr int SMEM_MAIN = 2 * 64 * FPAD * 4;    // 67584 (> 2*STAGE_B2=40960)

// ---------------- bf16 4-matrix loader + 3-term compute (G-GEMM) -----------
__device__ __forceinline__ void load_chunk4(
    uint32_t sbase, int stage,
    const __nv_bfloat16* __restrict__ Ahi, const __nv_bfloat16* __restrict__ Alo,
    const __nv_bfloat16* __restrict__ Bhi, const __nv_bfloat16* __restrict__ Blo,
    int rowBase, int colBase, int k0, int tid)
{
    uint32_t st = sbase + stage * STAGE_B4;
#pragma unroll
    for (int mat = 0; mat < 4; mat++) {
        const __nv_bfloat16* src0 =
            (mat == 0) ? Ahi : (mat == 1) ? Alo : (mat == 2) ? Bhi : Blo;
        int base = (mat < 2) ? rowBase : colBase;
#pragma unroll
        for (int h = 0; h < 2; h++) {
            int idx = h * 256 + tid;
            int row = idx >> 2, ch = idx & 3;
            const __nv_bfloat16* src = src0 + (size_t)(base + row) * DIM + k0 + ch * 8;
            uint32_t dst = st + (mat * MAT_ELE + row * 40 + ch * 8) * 2;
            cpa16(dst, src);
        }
    }
    CP_COMMIT();
}

__device__ __forceinline__ void compute_ks4(
    float acc[4][4][4], uint32_t stb, int wm, int wn, int lane, int ks)
{
    uint32_t bAhi = stb;
    uint32_t bAlo = stb + MAT_ELE * 2;
    uint32_t bBhi = stb + 2 * MAT_ELE * 2;
    uint32_t bBlo = stb + 3 * MAT_ELE * 2;
    uint32_t bhif[8], blof[8];
    ldb4(bhif,     bBhi, wn, 0, ks, lane);
    ldb4(bhif + 4, bBhi, wn, 1, ks, lane);
    ldb4(blof,     bBlo, wn, 0, ks, lane);
    ldb4(blof + 4, bBlo, wn, 1, ks, lane);
#pragma unroll
    for (int mt = 0; mt < 4; mt++) {
        uint32_t ahif[4], alof[4];
        lda4(ahif, bAhi, wm, mt, ks, lane);
        lda4(alof, bAlo, wm, mt, ks, lane);
#pragma unroll
        for (int nt = 0; nt < 4; nt++) {
            mma_bf(acc[mt][nt], ahif, bhif + nt * 2);
            mma_bf(acc[mt][nt], alof, bhif + nt * 2);
            mma_bf(acc[mt][nt], ahif, blof + nt * 2);
        }
    }
}

// --------- G GEMM body: C = Wq@Wk^T, epilogue writes fp16 Gt (transposed) --
__device__ void gemm_g_body(
    const __nv_bfloat16* __restrict__ Ahi, const __nv_bfloat16* __restrict__ Alo,
    const __nv_bfloat16* __restrict__ Bhi, const __nv_bfloat16* __restrict__ Blo,
    int gb)
{
    extern __shared__ char smem[];
    uint32_t sbase = s2u(smem);
    const int tid  = threadIdx.x;
    const int lane = tid & 31;
    const int wid  = tid >> 5;
    const int wm = (wid >> 2) * 64;
    const int wn = (wid & 3) * 32;
    const int rowBase = (gb & 7) * 128;   // k of Gt
    const int colBase = (gb >> 3) * 128;  // n of Gt

    float acc[4][4][4];
#pragma unroll
    for (int i = 0; i < 4; i++)
#pragma unroll
        for (int j = 0; j < 4; j++)
#pragma unroll
            for (int q = 0; q < 4; q++) acc[i][j][q] = 0.f;

    load_chunk4(sbase, 0, Ahi, Alo, Bhi, Blo, rowBase, colBase, 0, tid);
    for (int c = 0; c < 32; ++c) {
        int s = c & 1;
        CP_WAIT0();
        __syncthreads();
        compute_ks4(acc, sbase + s * STAGE_B4, wm, wn, lane, 0);
        if (c < 31)
            load_chunk4(sbase, s ^ 1, Ahi, Alo, Bhi, Blo, rowBase, colBase,
                        (c + 1) * 32, tid);
        compute_ks4(acc, sbase + s * STAGE_B4, wm, wn, lane, 1);
    }

    __syncthreads();
#pragma unroll
    for (int mt = 0; mt < 4; mt++) {
        int lr = wm + mt * 16 + (lane >> 2);
#pragma unroll
        for (int nt = 0; nt < 4; nt++) {
            int lc = wn + nt * 8 + (lane & 3) * 2;
            sts2f(sbase + (lr * FPAD + lc) * 4, acc[mt][nt][0], acc[mt][nt][1]);
            sts2f(sbase + ((lr + 8) * FPAD + lc) * 4, acc[mt][nt][2], acc[mt][nt][3]);
        }
    }
    __syncthreads();

    // transpose-read + fp16 round + coalesced store
    int n_local = tid >> 1;
    int kh = (tid & 1) * 64;
    size_t gbase = (size_t)(colBase + n_local) * DIM + rowBase + kh;
#pragma unroll
    for (int kb = 0; kb < 64; kb += 8) {
        HfPack hp;
#pragma unroll
        for (int i = 0; i < 8; i++) {
            float v = lds1f(sbase + ((kh + kb + i) * FPAD + n_local) * 4);
            hp.h[i] = __float2half_rn(v);
        }
        *(uint4*)(g_Gt + gbase + kb) = hp.u;
    }
}

// --------- split_x body: gather + fp16 round + head-dot precompute ---------
__device__ void split_x_body(const float* __restrict__ p,
                             const float* __restrict__ r,
                             const float* __restrict__ pn,
                             const float* __restrict__ rn,
                             const float* __restrict__ W_pred, int bx)
{
    __shared__ float sdot[2][4][OUTD];
    int t = threadIdx.x;
    int half = t >> 7;
    int row = bx * 2 + half;
    int tt = t & 127;
    int s = row >> 14, b = (row >> 3) & (BATCH - 1), m = row & 7;
    size_t off = ((size_t)m * BATCH + b) * DIM;
    const float* src  = (s ? r : p) + off;
    const float* nsrc = (s ? rn : pn) + off;
    float4 v0 = ((const float4*)src)[tt * 2];
    float4 v1 = ((const float4*)src)[tt * 2 + 1];
    float vv[8] = {v0.x, v0.y, v0.z, v0.w, v1.x, v1.y, v1.z, v1.w};
    HfPack hp;
#pragma unroll
    for (int i = 0; i < 8; i++) hp.h[i] = __float2half_rn(vv[i]);
    ((uint4*)(g_X + (size_t)row * DIM))[tt] = hp.u;

    // head-dot precompute: (v + n) . W_pred[o]
    float4 n0 = ((const float4*)nsrc)[tt * 2];
    float4 n1 = ((const float4*)nsrc)[tt * 2 + 1];
    float sv[8] = {vv[0] + n0.x, vv[1] + n0.y, vv[2] + n0.z, vv[3] + n0.w,
                   vv[4] + n1.x, vv[5] + n1.y, vv[6] + n1.z, vv[7] + n1.w};
    float dot[OUTD];
#pragma unroll
    for (int o = 0; o < OUTD; o++) {
        const float4* wrow = (const float4*)(W_pred + (size_t)o * DIM);
        float4 w0 = wrow[tt * 2];
        float4 w1 = wrow[tt * 2 + 1];
        dot[o] = sv[0] * w0.x + sv[1] * w0.y + sv[2] * w0.z + sv[3] * w0.w
               + sv[4] * w1.x + sv[5] * w1.y + sv[6] * w1.z + sv[7] * w1.w;
    }
    int lane = t & 31, w = tt >> 5;
#pragma unroll
    for (int o = 0; o < OUTD; o++) {
#pragma unroll
        for (int ofs = 16; ofs > 0; ofs >>= 1)
            dot[o] += __shfl_down_sync(0xFFFFFFFFu, dot[o], ofs);
        if (lane == 0) sdot[half][w][o] = dot[o];
    }
    __syncthreads();
    if (tt < OUTD) {
        float ssum = sdot[half][0][tt] + sdot[half][1][tt]
                   + sdot[half][2][tt] + sdot[half][3][tt];
        float* dst = s ? g_tr : g_tp;
        dst[((size_t)m * BATCH + b) * OUTD + tt] = ssum;
    }
}

// --------- combined aux: G-GEMM (64 CTAs) overlapped with split_x ----------
__global__ void __launch_bounds__(256) aux_kernel(
    const __nv_bfloat16* __restrict__ WqHi, const __nv_bfloat16* __restrict__ WqLo,
    const __nv_bfloat16* __restrict__ WkHi, const __nv_bfloat16* __restrict__ WkLo,
    const float* __restrict__ p_feats, const float* __restrict__ r_feats,
    const float* __restrict__ p_new,   const float* __restrict__ r_new,
    const float* __restrict__ W_pred)
{
    if (blockIdx.x < 64)
        gemm_g_body(WqHi, WqLo, WkHi, WkLo, blockIdx.x);
    else
        split_x_body(p_feats, r_feats, p_new, r_new, W_pred, blockIdx.x - 64);
}

// ---------------- fp16 2-matrix loader + 1-term compute (main) -------------
__device__ __forceinline__ void load_chunk2(
    uint32_t sbase, int stage,
    const __half* __restrict__ A, const __half* __restrict__ B,
    int rowBase, int colBase, int k0, int tid)
{
    uint32_t st = sbase + stage * STAGE_B2;
#pragma unroll
    for (int mat = 0; mat < 2; mat++) {
        const __half* src0 = mat ? B : A;
        int base = mat ? colBase : rowBase;
#pragma unroll
        for (int h = 0; h < 2; h++) {
            int idx = h * 256 + tid;
            int row = idx >> 2, ch = idx & 3;
            const __half* src = src0 + (size_t)(base + row) * DIM + k0 + ch * 8;
            uint32_t dst = st + (mat * MAT_ELE + row * 40 + ch * 8) * 2;
            cpa16(dst, src);
        }
    }
    CP_COMMIT();
}

__device__ __forceinline__ void compute_ks2(
    float acc[4][4][4], uint32_t stb, int wm, int wn, int lane, int ks)
{
    uint32_t bA = stb;
    uint32_t bB = stb + MAT_ELE * 2;
    uint32_t bf[8];
    ldb4(bf,     bB, wn, 0, ks, lane);
    ldb4(bf + 4, bB, wn, 1, ks, lane);
#pragma unroll
    for (int mt = 0; mt < 4; mt++) {
        uint32_t af[4];
        lda4(af, bA, wm, mt, ks, lane);
#pragma unroll
        for (int nt = 0; nt < 4; nt++)
            mma_hf(acc[mt][nt], af, bf + nt * 2);
    }
}

// --------------- fused GEMM (Z = X@G, fp16 1-term) + gram epilogue ---------
__global__ void __launch_bounds__(256, 2) mma_gemm_fused(
    const __half* __restrict__ A, const __half* __restrict__ B,
    const float* __restrict__ fR, const float* __restrict__ fP)
{
    extern __shared__ char smem[];
    uint32_t sbase = s2u(smem);
    const int tid  = threadIdx.x;
    const int lane = tid & 31;
    const int wid  = tid >> 5;
    const int wm = (wid >> 2) * 64;
    const int wn = (wid & 3) * 32;
    const int rowBase = blockIdx.x * 128;
    const int colBase = blockIdx.y * 128;

    float acc[4][4][4];
#pragma unroll
    for (int i = 0; i < 4; i++)
#pragma unroll
        for (int j = 0; j < 4; j++)
#pragma unroll
            for (int q = 0; q < 4; q++) acc[i][j][q] = 0.f;

    load_chunk2(sbase, 0, A, B, rowBase, colBase, 0, tid);
    for (int c = 0; c < 32; ++c) {
        int s = c & 1;
        CP_WAIT0();
        __syncthreads();
        compute_ks2(acc, sbase + s * STAGE_B2, wm, wn, lane, 0);
        if (c < 31)
            load_chunk2(sbase, s ^ 1, A, B, rowBase, colBase, (c + 1) * 32, tid);
        compute_ks2(acc, sbase + s * STAGE_B2, wm, wn, lane, 1);
    }

    // gram epilogue: row tile = side, batches bb..bb+15, 8 query mols
    const int side = blockIdx.x >> 7;
    const int bb = (blockIdx.x & 127) * 16;
    const float* keys = side ? fP : fR;
    uint32_t zsm = sbase;
    uint32_t fsm = sbase + 64 * FPAD * 4;

#pragma unroll
    for (int pass = 0; pass < 2; pass++) {
        __syncthreads();
        // F loads first (latency hidden behind Z smem stores)
#pragma unroll
        for (int h = 0; h < 8; h++) {
            int idx = h * 256 + tid;
            int rowi = idx >> 5, ch = idx & 31;
            int bl = rowi >> 3, kk2 = rowi & 7;
            const float* src = keys +
                ((size_t)kk2 * BATCH + (bb + pass * 8 + bl)) * DIM + colBase + ch * 4;
            cpa16(fsm + (rowi * FPAD + ch * 4) * 4, src);
        }
        CP_COMMIT();
        if ((wid >> 2) == pass) {
#pragma unroll
            for (int mt = 0; mt < 4; mt++) {
                int lr = mt * 16 + (lane >> 2);
#pragma unroll
                for (int nt = 0; nt < 4; nt++) {
                    int lc = wn + nt * 8 + (lane & 3) * 2;
                    sts2f(zsm + (lr * FPAD + lc) * 4, acc[mt][nt][0], acc[mt][nt][1]);
                    sts2f(zsm + ((lr + 8) * FPAD + lc) * 4, acc[mt][nt][2], acc[mt][nt][3]);
                }
            }
        }
        CP_WAIT0();
        __syncthreads();

        // 2x2-blocked gram: lane -> (2q x 2k) block over half the D-range
        int bl = wid;
        int hh = lane >> 4;
        int q0 = ((lane >> 2) & 3) * 2;
        int k0 = (lane & 3) * 2;
        uint32_t z0 = zsm + ((bl * 8 + q0) * FPAD + hh * 64) * 4;
        uint32_t z1 = z0 + FPAD * 4;
        uint32_t f0 = fsm + ((bl * 8 + k0) * FPAD + hh * 64) * 4;
        uint32_t f1 = f0 + FPAD * 4;
        float s00 = 0.f, s01 = 0.f, s10 = 0.f, s11 = 0.f;
#pragma unroll
        for (int cc = 0; cc < 64; cc += 4) {
            float4 a0 = lds4f(z0 + cc * 4);
            float4 a1 = lds4f(z1 + cc * 4);
            float4 b0 = lds4f(f0 + cc * 4);
            float4 b1 = lds4f(f1 + cc * 4);
            s00 += a0.x * b0.x + a0.y * b0.y + a0.z * b0.z + a0.w * b0.w;
            s01 += a0.x * b1.x + a0.y * b1.y + a0.z * b1.z + a0.w * b1.w;
            s10 += a1.x * b0.x + a1.y * b0.y + a1.z * b0.z + a1.w * b0.w;
            s11 += a1.x * b1.x + a1.y * b1.y + a1.z * b1.z + a1.w * b1.w;
        }
        s00 += __shfl_xor_sync(0xFFFFFFFFu, s00, 16);
        s01 += __shfl_xor_sync(0xFFFFFFFFu, s01, 16);
        s10 += __shfl_xor_sync(0xFFFFFFFFu, s10, 16);
        s11 += __shfl_xor_sync(0xFFFFFFFFu, s11, 16);
        if (hh == 0) {
            size_t base = ((size_t)(blockIdx.y * 2 + side) * BATCH
                           + bb + pass * 8 + bl) * 64;
            g_Spart[base + q0 * 8 + k0]           = s00;
            g_Spart[base + q0 * 8 + k0 + 1]       = s01;
            g_Spart[base + (q0 + 1) * 8 + k0]     = s10;
            g_Spart[base + (q0 + 1) * 8 + k0 + 1] = s11;
        }
    }
}

// --------- final: softmax + att outputs + tiny head combine ----------------
__global__ void __launch_bounds__(128) att_final_kernel(
    const float* __restrict__ b_pred, float* __restrict__ d_out)
{
    const int b = blockIdx.x;
    const int t = threadIdx.x;
    __shared__ float sS[2][MOL][MOL];
    __shared__ float sProb[2][LQ][LQ];
    __shared__ float sAtt[2][LQ];
    __shared__ float sw[16];

    {
        int side = t >> 6, e = t & 63;
        float s = 0.f;
#pragma unroll
        for (int ct = 0; ct < 8; ct++)
            s += g_Spart[((size_t)(ct * 2 + side) * BATCH + b) * 64 + e];
        sS[side][e >> 3][e & 7] = s;
    }
    __syncthreads();

    if (t < 2 * LQ) {
        int sd = t / LQ, qq = t % LQ;
        int qi, qj;
        if (qq < MOL) { qi = qq; qj = -1; }
        else          { qi = c_pi[qq - MOL]; qj = c_pj[qq - MOL]; }
        float row[LQ];
        float maxv = -1e30f;
#pragma unroll
        for (int kk = 0; kk < LQ; kk++) {
            int ki, kj;
            if (kk < MOL) { ki = kk; kj = -1; }
            else          { ki = c_pi[kk - MOL]; kj = c_pj[kk - MOL]; }
            float v = sS[sd][qi][ki];
            if (kj >= 0) v += sS[sd][qi][kj];
            if (qj >= 0) {
                v += sS[sd][qj][ki];
                if (kj >= 0) v += sS[sd][qj][kj];
            }
            v *= 0.03125f;
            row[kk] = v;
            maxv = fmaxf(maxv, v);
        }
        float sum = 0.f;
#pragma unroll
        for (int kk = 0; kk < LQ; kk++) { row[kk] = expf(row[kk] - maxv); sum += row[kk]; }
        float inv = 1.f / sum;
#pragma unroll
        for (int kk = 0; kk < LQ; kk++) sProb[sd][qq][kk] = row[kk] * inv;
    }
    __syncthreads();

    if (t < 2 * LQ) {
        int sd = t / LQ, kk = t % LQ;
        float a = 0.f;
#pragma unroll
        for (int qq = 0; qq < LQ; qq++) a += sProb[sd][qq][kk];
        a *= (1.0f / LQ);
        sAtt[sd][kk] = a;
        d_out[BATCH * OUTD + sd * (BATCH * LQ) + b * LQ + kk] = a;
    }
    __syncthreads();

    if (t < 16) {
        int sd = t >> 3, m = t & 7;
        float w = sAtt[sd][m];
#pragma unroll
        for (int pp = 0; pp < NPAIR; pp++)
            if (c_pi[pp] == m || c_pj[pp] == m) w += sAtt[sd][MOL + pp];
        sw[sd * MOL + m] = w;
    }
    __syncthreads();

    if (t < OUTD) {
        float s = 0.f;
#pragma unroll
        for (int m = 0; m < MOL; m++) {
            s += sw[m]     * g_tr[((size_t)m * BATCH + b) * OUTD + t];
            s -= sw[8 + m] * g_tp[((size_t)m * BATCH + b) * OUTD + t];
        }
        d_out[b * OUTD + t] = s + b_pred[t];
    }
}

// ---------------------------------------------------------------------------
extern "C" void kernel_launch(void* const* d_in, const int* in_sizes, int n_in,
                              void* d_out, int out_size) {
    const float* r_feats = (const float*)d_in[0];
    const float* p_feats = (const float*)d_in[1];
    const float* r_new   = (const float*)d_in[2];
    const float* p_new   = (const float*)d_in[3];
    const float* Wq      = (const float*)d_in[4];
    const float* Wk      = (const float*)d_in[5];
    const float* W_pred  = (const float*)d_in[6];
    const float* b_pred  = (const float*)d_in[7];
    float* out = (float*)d_out;

    cudaFuncSetAttribute(aux_kernel, cudaFuncAttributeMaxDynamicSharedMemorySize,
                         SMEM_G);
    cudaFuncSetAttribute(mma_gemm_fused, cudaFuncAttributeMaxDynamicSharedMemorySize,
                         SMEM_MAIN);

    __nv_bfloat16 *WqHi, *WqLo, *WkHi, *WkLo;
    __half *Gt, *X;
    cudaGetSymbolAddress((void**)&WqHi, g_WqHi);
    cudaGetSymbolAddress((void**)&WqLo, g_WqLo);
    cudaGetSymbolAddress((void**)&WkHi, g_WkHi);
    cudaGetSymbolAddress((void**)&WkLo, g_WkLo);
    cudaGetSymbolAddress((void**)&Gt,   g_Gt);
    cudaGetSymbolAddress((void**)&X,    g_X);

    // 1) weight splits (bf16, feeds accurate 3-term G-GEMM)
    split_w<<<2048, 128>>>(Wq, Wk);
    // 2) G-GEMM (64 CTAs, bf16 3-term) + split_x (fp16) + head-dots
    aux_kernel<<<64 + MROWS / 2, 256, SMEM_G>>>(WqHi, WqLo, WkHi, WkLo,
                                                p_feats, r_feats,
                                                p_new, r_new, W_pred);
    // 3) fused GEMM (fp16 1-term) + gram epilogue
    mma_gemm_fused<<<dim3(256, 8), 256, SMEM_MAIN>>>(X, Gt, r_feats, p_feats);
    // 4) softmax + att outputs + tiny head combine
    att_final_kernel<<<BATCH, 128>>>(b_pred, out);
}

// round 15
// speedup vs baseline: 2.2552x; 1.1288x over previous
#include <cuda_runtime.h>
#include <cuda_bf16.h>
#include <cuda_fp16.h>
#include <cstdint>

constexpr int BATCH = 2048;
constexpr int DIM   = 1024;
constexpr int MOL   = 8;
constexpr int NPAIR = 28;
constexpr int LQ    = 36;
constexpr int OUTD  = 4;
constexpr int MROWS = 32768;           // 2 * BATCH * MOL

__constant__ int c_pi[NPAIR] = {0,0,0,0,0,0,0,1,1,1,1,1,1,2,2,2,2,2,3,3,3,3,4,4,4,5,5,6};
__constant__ int c_pj[NPAIR] = {1,2,3,4,5,6,7,2,3,4,5,6,7,3,4,5,6,7,4,5,6,7,5,6,7,6,7,7};

// ------------------------- static device scratch ---------------------------
__device__ __nv_bfloat16 g_WqHi[DIM * DIM];
__device__ __nv_bfloat16 g_WqLo[DIM * DIM];
__device__ __nv_bfloat16 g_WkHi[DIM * DIM];
__device__ __nv_bfloat16 g_WkLo[DIM * DIM];
__device__ __half        g_Gt[DIM * DIM];            // fp16 Gt[n][k] = G[k][n]
__device__ __half        g_X[(size_t)MROWS * DIM];   // fp16 x
__device__ float         g_Spart[8ull * 2 * BATCH * 64];
__device__ float         g_tr[MOL * BATCH * OUTD];
__device__ float         g_tp[MOL * BATCH * OUTD];

// ------------------------------ helpers ------------------------------------
__device__ __forceinline__ uint32_t s2u(const void* p) {
    uint32_t a;
    asm("{ .reg .u64 t; cvta.to.shared.u64 t, %1; cvt.u32.u64 %0, t; }" : "=r"(a) : "l"(p));
    return a;
}
__device__ __forceinline__ void cpa16(uint32_t d, const void* g) {
    asm volatile("cp.async.cg.shared.global [%0], [%1], 16;" :: "r"(d), "l"(g));
}
#define CP_COMMIT()  asm volatile("cp.async.commit_group;" ::: "memory")
#define CP_WAIT0()   asm volatile("cp.async.wait_group 0;" ::: "memory")

__device__ __forceinline__ float4 lds4f(uint32_t a) {
    float4 v;
    asm volatile("ld.shared.v4.f32 {%0,%1,%2,%3}, [%4];"
        : "=f"(v.x), "=f"(v.y), "=f"(v.z), "=f"(v.w) : "r"(a));
    return v;
}
__device__ __forceinline__ float lds1f(uint32_t a) {
    float v;
    asm volatile("ld.shared.f32 %0, [%1];" : "=f"(v) : "r"(a));
    return v;
}
__device__ __forceinline__ void sts2f(uint32_t a, float x, float y) {
    asm volatile("st.shared.v2.f32 [%0], {%1,%2};" :: "r"(a), "f"(x), "f"(y));
}

// stride-parameterized ldmatrix helpers (STRIDE in elements)
template<int STRIDE>
__device__ __forceinline__ void lda4(uint32_t* f, uint32_t mbase, int wm, int mt,
                                     int ks, int lane) {
    int g = lane >> 3, r = lane & 7;
    int mloc = wm + mt * 16 + (g & 1) * 8 + r;
    int kloc = ks * 16 + (g >> 1) * 8;
    uint32_t a = mbase + (mloc * STRIDE + kloc) * 2;
    asm volatile("ldmatrix.sync.aligned.m8n8.x4.shared.b16 {%0,%1,%2,%3}, [%4];"
        : "=r"(f[0]), "=r"(f[1]), "=r"(f[2]), "=r"(f[3]) : "r"(a));
}
template<int STRIDE>
__device__ __forceinline__ void ldb4(uint32_t* f, uint32_t mbase, int wn, int ntp,
                                     int ks, int lane) {
    int g = lane >> 3, r = lane & 7;
    int nloc = wn + ntp * 16 + (g >> 1) * 8 + r;
    int kloc = ks * 16 + (g & 1) * 8;
    uint32_t a = mbase + (nloc * STRIDE + kloc) * 2;
    asm volatile("ldmatrix.sync.aligned.m8n8.x4.shared.b16 {%0,%1,%2,%3}, [%4];"
        : "=r"(f[0]), "=r"(f[1]), "=r"(f[2]), "=r"(f[3]) : "r"(a));
}
__device__ __forceinline__ void mma_bf(float* c, const uint32_t* a, const uint32_t* b) {
    asm volatile("mma.sync.aligned.m16n8k16.row.col.f32.bf16.bf16.f32 "
        "{%0,%1,%2,%3}, {%4,%5,%6,%7}, {%8,%9}, {%0,%1,%2,%3};"
        : "+f"(c[0]), "+f"(c[1]), "+f"(c[2]), "+f"(c[3])
        : "r"(a[0]), "r"(a[1]), "r"(a[2]), "r"(a[3]), "r"(b[0]), "r"(b[1]));
}
__device__ __forceinline__ void mma_hf(float* c, const uint32_t* a, const uint32_t* b) {
    asm volatile("mma.sync.aligned.m16n8k16.row.col.f32.f16.f16.f32 "
        "{%0,%1,%2,%3}, {%4,%5,%6,%7}, {%8,%9}, {%0,%1,%2,%3};"
        : "+f"(c[0]), "+f"(c[1]), "+f"(c[2]), "+f"(c[3])
        : "r"(a[0]), "r"(a[1]), "r"(a[2]), "r"(a[3]), "r"(b[0]), "r"(b[1]));
}

union BfPack { __nv_bfloat16 h[8]; uint4 u; };
union HfPack { __half h[8]; uint4 u; };

// ------------------------- split_w kernel (bf16, for G-GEMM) ---------------
__global__ void __launch_bounds__(128) split_w(const float* __restrict__ Wq,
                                               const float* __restrict__ Wk) {
    int bx = blockIdx.x;
    int mat = bx >> 10, row = bx & 1023;
    const float* src = (mat ? Wk : Wq) + (size_t)row * DIM;
    __nv_bfloat16* hi = (mat ? g_WkHi : g_WqHi) + (size_t)row * DIM;
    __nv_bfloat16* lo = (mat ? g_WkLo : g_WqLo) + (size_t)row * DIM;
    int t = threadIdx.x;
    float4 v0 = ((const float4*)src)[t * 2];
    float4 v1 = ((const float4*)src)[t * 2 + 1];
    float vv[8] = {v0.x, v0.y, v0.z, v0.w, v1.x, v1.y, v1.z, v1.w};
    BfPack hp, lp;
#pragma unroll
    for (int i = 0; i < 8; i++) {
        __nv_bfloat16 h = __float2bfloat16_rn(vv[i]);
        hp.h[i] = h;
        lp.h[i] = __float2bfloat16_rn(vv[i] - __bfloat162float(h));
    }
    ((uint4*)(hi))[t] = hp.u;
    ((uint4*)(lo))[t] = lp.u;
}

// ------------------------- GEMM constants ----------------------------------
constexpr int MAT_ELE   = 128 * 40;             // bf16 G-GEMM tile (k32, pad 40)
constexpr int STAGE_B4  = 4 * MAT_ELE * 2;
constexpr int SMEM_G    = 2 * STAGE_B4;         // 81920
constexpr int MAT72     = 128 * 72;             // fp16 main tile (k64, pad 72)
constexpr int STAGE_K64 = 2 * MAT72 * 2;        // 36864 bytes (A + B)
constexpr int FPAD      = 132;
constexpr int SMEM_MAIN = 2 * STAGE_K64;        // 73728 (> epilogue 67584)

// ---------------- bf16 4-matrix loader + 3-term compute (G-GEMM) -----------
__device__ __forceinline__ void load_chunk4(
    uint32_t sbase, int stage,
    const __nv_bfloat16* __restrict__ Ahi, const __nv_bfloat16* __restrict__ Alo,
    const __nv_bfloat16* __restrict__ Bhi, const __nv_bfloat16* __restrict__ Blo,
    int rowBase, int colBase, int k0, int tid)
{
    uint32_t st = sbase + stage * STAGE_B4;
#pragma unroll
    for (int mat = 0; mat < 4; mat++) {
        const __nv_bfloat16* src0 =
            (mat == 0) ? Ahi : (mat == 1) ? Alo : (mat == 2) ? Bhi : Blo;
        int base = (mat < 2) ? rowBase : colBase;
#pragma unroll
        for (int h = 0; h < 2; h++) {
            int idx = h * 256 + tid;
            int row = idx >> 2, ch = idx & 3;
            const __nv_bfloat16* src = src0 + (size_t)(base + row) * DIM + k0 + ch * 8;
            uint32_t dst = st + (mat * MAT_ELE + row * 40 + ch * 8) * 2;
            cpa16(dst, src);
        }
    }
    CP_COMMIT();
}

__device__ __forceinline__ void compute_ks4(
    float acc[4][4][4], uint32_t stb, int wm, int wn, int lane, int ks)
{
    uint32_t bAhi = stb;
    uint32_t bAlo = stb + MAT_ELE * 2;
    uint32_t bBhi = stb + 2 * MAT_ELE * 2;
    uint32_t bBlo = stb + 3 * MAT_ELE * 2;
    uint32_t bhif[8], blof[8];
    ldb4<40>(bhif,     bBhi, wn, 0, ks, lane);
    ldb4<40>(bhif + 4, bBhi, wn, 1, ks, lane);
    ldb4<40>(blof,     bBlo, wn, 0, ks, lane);
    ldb4<40>(blof + 4, bBlo, wn, 1, ks, lane);
#pragma unroll
    for (int mt = 0; mt < 4; mt++) {
        uint32_t ahif[4], alof[4];
        lda4<40>(ahif, bAhi, wm, mt, ks, lane);
        lda4<40>(alof, bAlo, wm, mt, ks, lane);
#pragma unroll
        for (int nt = 0; nt < 4; nt++) {
            mma_bf(acc[mt][nt], ahif, bhif + nt * 2);
            mma_bf(acc[mt][nt], alof, bhif + nt * 2);
            mma_bf(acc[mt][nt], ahif, blof + nt * 2);
        }
    }
}

// --------- G GEMM body: C = Wq@Wk^T, epilogue writes fp16 Gt (transposed) --
__device__ void gemm_g_body(
    const __nv_bfloat16* __restrict__ Ahi, const __nv_bfloat16* __restrict__ Alo,
    const __nv_bfloat16* __restrict__ Bhi, const __nv_bfloat16* __restrict__ Blo,
    int gb)
{
    extern __shared__ char smem[];
    uint32_t sbase = s2u(smem);
    const int tid  = threadIdx.x;
    const int lane = tid & 31;
    const int wid  = tid >> 5;
    const int wm = (wid >> 2) * 64;
    const int wn = (wid & 3) * 32;
    const int rowBase = (gb & 7) * 128;   // k of Gt
    const int colBase = (gb >> 3) * 128;  // n of Gt

    float acc[4][4][4];
#pragma unroll
    for (int i = 0; i < 4; i++)
#pragma unroll
        for (int j = 0; j < 4; j++)
#pragma unroll
            for (int q = 0; q < 4; q++) acc[i][j][q] = 0.f;

    load_chunk4(sbase, 0, Ahi, Alo, Bhi, Blo, rowBase, colBase, 0, tid);
    for (int c = 0; c < 32; ++c) {
        int s = c & 1;
        CP_WAIT0();
        __syncthreads();
        compute_ks4(acc, sbase + s * STAGE_B4, wm, wn, lane, 0);
        if (c < 31)
            load_chunk4(sbase, s ^ 1, Ahi, Alo, Bhi, Blo, rowBase, colBase,
                        (c + 1) * 32, tid);
        compute_ks4(acc, sbase + s * STAGE_B4, wm, wn, lane, 1);
    }

    __syncthreads();
#pragma unroll
    for (int mt = 0; mt < 4; mt++) {
        int lr = wm + mt * 16 + (lane >> 2);
#pragma unroll
        for (int nt = 0; nt < 4; nt++) {
            int lc = wn + nt * 8 + (lane & 3) * 2;
            sts2f(sbase + (lr * FPAD + lc) * 4, acc[mt][nt][0], acc[mt][nt][1]);
            sts2f(sbase + ((lr + 8) * FPAD + lc) * 4, acc[mt][nt][2], acc[mt][nt][3]);
        }
    }
    __syncthreads();

    int n_local = tid >> 1;
    int kh = (tid & 1) * 64;
    size_t gbase = (size_t)(colBase + n_local) * DIM + rowBase + kh;
#pragma unroll
    for (int kb = 0; kb < 64; kb += 8) {
        HfPack hp;
#pragma unroll
        for (int i = 0; i < 8; i++) {
            float v = lds1f(sbase + ((kh + kb + i) * FPAD + n_local) * 4);
            hp.h[i] = __float2half_rn(v);
        }
        *(uint4*)(g_Gt + gbase + kb) = hp.u;
    }
}

// --------- split_x body: gather + fp16 round + head-dot precompute ---------
__device__ void split_x_body(const float* __restrict__ p,
                             const float* __restrict__ r,
                             const float* __restrict__ pn,
                             const float* __restrict__ rn,
                             const float* __restrict__ W_pred, int bx)
{
    __shared__ float sdot[2][4][OUTD];
    int t = threadIdx.x;
    int half = t >> 7;
    int row = bx * 2 + half;
    int tt = t & 127;
    int s = row >> 14, b = (row >> 3) & (BATCH - 1), m = row & 7;
    size_t off = ((size_t)m * BATCH + b) * DIM;
    const float* src  = (s ? r : p) + off;
    const float* nsrc = (s ? rn : pn) + off;
    float4 v0 = ((const float4*)src)[tt * 2];
    float4 v1 = ((const float4*)src)[tt * 2 + 1];
    float vv[8] = {v0.x, v0.y, v0.z, v0.w, v1.x, v1.y, v1.z, v1.w};
    HfPack hp;
#pragma unroll
    for (int i = 0; i < 8; i++) hp.h[i] = __float2half_rn(vv[i]);
    ((uint4*)(g_X + (size_t)row * DIM))[tt] = hp.u;

    float4 n0 = ((const float4*)nsrc)[tt * 2];
    float4 n1 = ((const float4*)nsrc)[tt * 2 + 1];
    float sv[8] = {vv[0] + n0.x, vv[1] + n0.y, vv[2] + n0.z, vv[3] + n0.w,
                   vv[4] + n1.x, vv[5] + n1.y, vv[6] + n1.z, vv[7] + n1.w};
    float dot[OUTD];
#pragma unroll
    for (int o = 0; o < OUTD; o++) {
        const float4* wrow = (const float4*)(W_pred + (size_t)o * DIM);
        float4 w0 = wrow[tt * 2];
        float4 w1 = wrow[tt * 2 + 1];
        dot[o] = sv[0] * w0.x + sv[1] * w0.y + sv[2] * w0.z + sv[3] * w0.w
               + sv[4] * w1.x + sv[5] * w1.y + sv[6] * w1.z + sv[7] * w1.w;
    }
    int lane = t & 31, w = tt >> 5;
#pragma unroll
    for (int o = 0; o < OUTD; o++) {
#pragma unroll
        for (int ofs = 16; ofs > 0; ofs >>= 1)
            dot[o] += __shfl_down_sync(0xFFFFFFFFu, dot[o], ofs);
        if (lane == 0) sdot[half][w][o] = dot[o];
    }
    __syncthreads();
    if (tt < OUTD) {
        float ssum = sdot[half][0][tt] + sdot[half][1][tt]
                   + sdot[half][2][tt] + sdot[half][3][tt];
        float* dst = s ? g_tr : g_tp;
        dst[((size_t)m * BATCH + b) * OUTD + tt] = ssum;
    }
}

// --------- combined aux: G-GEMM (64 CTAs) overlapped with split_x ----------
__global__ void __launch_bounds__(256) aux_kernel(
    const __nv_bfloat16* __restrict__ WqHi, const __nv_bfloat16* __restrict__ WqLo,
    const __nv_bfloat16* __restrict__ WkHi, const __nv_bfloat16* __restrict__ WkLo,
    const float* __restrict__ p_feats, const float* __restrict__ r_feats,
    const float* __restrict__ p_new,   const float* __restrict__ r_new,
    const float* __restrict__ W_pred)
{
    if (blockIdx.x < 64)
        gemm_g_body(WqHi, WqLo, WkHi, WkLo, blockIdx.x);
    else
        split_x_body(p_feats, r_feats, p_new, r_new, W_pred, blockIdx.x - 64);
}

// ---------------- fp16 k64-chunk loader + 1-term compute (main) ------------
__device__ __forceinline__ void load_chunk64(
    uint32_t sbase, int stage,
    const __half* __restrict__ A, const __half* __restrict__ B,
    int rowBase, int colBase, int k0, int tid)
{
    uint32_t st = sbase + stage * STAGE_K64;
#pragma unroll
    for (int mat = 0; mat < 2; mat++) {
        const __half* src0 = mat ? B : A;
        int base = mat ? colBase : rowBase;
#pragma unroll
        for (int h = 0; h < 4; h++) {
            int idx = h * 256 + tid;              // 0..1023 = 128 rows x 8 chunks
            int row = idx >> 3, ch = idx & 7;
            const __half* src = src0 + (size_t)(base + row) * DIM + k0 + ch * 8;
            uint32_t dst = st + (mat * MAT72 + row * 72 + ch * 8) * 2;
            cpa16(dst, src);
        }
    }
    CP_COMMIT();
}

__device__ __forceinline__ void compute_ks64(
    float acc[4][4][4], uint32_t stb, int wm, int wn, int lane, int ks)
{
    uint32_t bA = stb;
    uint32_t bB = stb + MAT72 * 2;
    uint32_t bf[8];
    ldb4<72>(bf,     bB, wn, 0, ks, lane);
    ldb4<72>(bf + 4, bB, wn, 1, ks, lane);
#pragma unroll
    for (int mt = 0; mt < 4; mt++) {
        uint32_t af[4];
        lda4<72>(af, bA, wm, mt, ks, lane);
#pragma unroll
        for (int nt = 0; nt < 4; nt++)
            mma_hf(acc[mt][nt], af, bf + nt * 2);
    }
}

// --------------- fused GEMM (Z = X@G, fp16 1-term, k64) + gram epilogue ----
__global__ void __launch_bounds__(256, 2) mma_gemm_fused(
    const __half* __restrict__ A, const __half* __restrict__ B,
    const float* __restrict__ fR, const float* __restrict__ fP)
{
    extern __shared__ char smem[];
    uint32_t sbase = s2u(smem);
    const int tid  = threadIdx.x;
    const int lane = tid & 31;
    const int wid  = tid >> 5;
    const int wm = (wid >> 2) * 64;
    const int wn = (wid & 3) * 32;
    const int rowBase = blockIdx.x * 128;
    const int colBase = blockIdx.y * 128;

    float acc[4][4][4];
#pragma unroll
    for (int i = 0; i < 4; i++)
#pragma unroll
        for (int j = 0; j < 4; j++)
#pragma unroll
            for (int q = 0; q < 4; q++) acc[i][j][q] = 0.f;

    load_chunk64(sbase, 0, A, B, rowBase, colBase, 0, tid);
    for (int c = 0; c < 16; ++c) {
        int s = c & 1;
        CP_WAIT0();
        __syncthreads();
        compute_ks64(acc, sbase + s * STAGE_K64, wm, wn, lane, 0);
        if (c < 15)
            load_chunk64(sbase, s ^ 1, A, B, rowBase, colBase, (c + 1) * 64, tid);
        compute_ks64(acc, sbase + s * STAGE_K64, wm, wn, lane, 1);
        compute_ks64(acc, sbase + s * STAGE_K64, wm, wn, lane, 2);
        compute_ks64(acc, sbase + s * STAGE_K64, wm, wn, lane, 3);
    }

    // gram epilogue: row tile = side, batches bb..bb+15, 8 query mols
    const int side = blockIdx.x >> 7;
    const int bb = (blockIdx.x & 127) * 16;
    const float* keys = side ? fP : fR;
    uint32_t zsm = sbase;
    uint32_t fsm = sbase + 64 * FPAD * 4;

#pragma unroll
    for (int pass = 0; pass < 2; pass++) {
        __syncthreads();
        // F loads first (latency hidden behind Z smem stores)
#pragma unroll
        for (int h = 0; h < 8; h++) {
            int idx = h * 256 + tid;
            int rowi = idx >> 5, ch = idx & 31;
            int bl = rowi >> 3, kk2 = rowi & 7;
            const float* src = keys +
                ((size_t)kk2 * BATCH + (bb + pass * 8 + bl)) * DIM + colBase + ch * 4;
            cpa16(fsm + (rowi * FPAD + ch * 4) * 4, src);
        }
        CP_COMMIT();
        if ((wid >> 2) == pass) {
#pragma unroll
            for (int mt = 0; mt < 4; mt++) {
                int lr = mt * 16 + (lane >> 2);
#pragma unroll
                for (int nt = 0; nt < 4; nt++) {
                    int lc = wn + nt * 8 + (lane & 3) * 2;
                    sts2f(zsm + (lr * FPAD + lc) * 4, acc[mt][nt][0], acc[mt][nt][1]);
                    sts2f(zsm + ((lr + 8) * FPAD + lc) * 4, acc[mt][nt][2], acc[mt][nt][3]);
                }
            }
        }
        CP_WAIT0();
        __syncthreads();

        // 2x2-blocked gram: lane -> (2q x 2k) block over half the D-range
        int bl = wid;
        int hh = lane >> 4;
        int q0 = ((lane >> 2) & 3) * 2;
        int k0 = (lane & 3) * 2;
        uint32_t z0 = zsm + ((bl * 8 + q0) * FPAD + hh * 64) * 4;
        uint32_t z1 = z0 + FPAD * 4;
        uint32_t f0 = fsm + ((bl * 8 + k0) * FPAD + hh * 64) * 4;
        uint32_t f1 = f0 + FPAD * 4;
        float s00 = 0.f, s01 = 0.f, s10 = 0.f, s11 = 0.f;
#pragma unroll
        for (int cc = 0; cc < 64; cc += 4) {
            float4 a0 = lds4f(z0 + cc * 4);
            float4 a1 = lds4f(z1 + cc * 4);
            float4 b0 = lds4f(f0 + cc * 4);
            float4 b1 = lds4f(f1 + cc * 4);
            s00 += a0.x * b0.x + a0.y * b0.y + a0.z * b0.z + a0.w * b0.w;
            s01 += a0.x * b1.x + a0.y * b1.y + a0.z * b1.z + a0.w * b1.w;
            s10 += a1.x * b0.x + a1.y * b0.y + a1.z * b0.z + a1.w * b0.w;
            s11 += a1.x * b1.x + a1.y * b1.y + a1.z * b1.z + a1.w * b1.w;
        }
        s00 += __shfl_xor_sync(0xFFFFFFFFu, s00, 16);
        s01 += __shfl_xor_sync(0xFFFFFFFFu, s01, 16);
        s10 += __shfl_xor_sync(0xFFFFFFFFu, s10, 16);
        s11 += __shfl_xor_sync(0xFFFFFFFFu, s11, 16);
        if (hh == 0) {
            size_t base = ((size_t)(blockIdx.y * 2 + side) * BATCH
                           + bb + pass * 8 + bl) * 64;
            g_Spart[base + q0 * 8 + k0]           = s00;
            g_Spart[base + q0 * 8 + k0 + 1]       = s01;
            g_Spart[base + (q0 + 1) * 8 + k0]     = s10;
            g_Spart[base + (q0 + 1) * 8 + k0 + 1] = s11;
        }
    }
}

// --------- final: softmax + att outputs + tiny head combine ----------------
__global__ void __launch_bounds__(128) att_final_kernel(
    const float* __restrict__ b_pred, float* __restrict__ d_out)
{
    const int b = blockIdx.x;
    const int t = threadIdx.x;
    __shared__ float sS[2][MOL][MOL];
    __shared__ float sProb[2][LQ][LQ];
    __shared__ float sAtt[2][LQ];
    __shared__ float sw[16];

    {
        int side = t >> 6, e = t & 63;
        float s = 0.f;
#pragma unroll
        for (int ct = 0; ct < 8; ct++)
            s += g_Spart[((size_t)(ct * 2 + side) * BATCH + b) * 64 + e];
        sS[side][e >> 3][e & 7] = s;
    }
    __syncthreads();

    if (t < 2 * LQ) {
        int sd = t / LQ, qq = t % LQ;
        int qi, qj;
        if (qq < MOL) { qi = qq; qj = -1; }
        else          { qi = c_pi[qq - MOL]; qj = c_pj[qq - MOL]; }
        float row[LQ];
        float maxv = -1e30f;
#pragma unroll
        for (int kk = 0; kk < LQ; kk++) {
            int ki, kj;
            if (kk < MOL) { ki = kk; kj = -1; }
            else          { ki = c_pi[kk - MOL]; kj = c_pj[kk - MOL]; }
            float v = sS[sd][qi][ki];
            if (kj >= 0) v += sS[sd][qi][kj];
            if (qj >= 0) {
                v += sS[sd][qj][ki];
                if (kj >= 0) v += sS[sd][qj][kj];
            }
            v *= 0.03125f;
            row[kk] = v;
            maxv = fmaxf(maxv, v);
        }
        float sum = 0.f;
#pragma unroll
        for (int kk = 0; kk < LQ; kk++) { row[kk] = expf(row[kk] - maxv); sum += row[kk]; }
        float inv = 1.f / sum;
#pragma unroll
        for (int kk = 0; kk < LQ; kk++) sProb[sd][qq][kk] = row[kk] * inv;
    }
    __syncthreads();

    if (t < 2 * LQ) {
        int sd = t / LQ, kk = t % LQ;
        float a = 0.f;
#pragma unroll
        for (int qq = 0; qq < LQ; qq++) a += sProb[sd][qq][kk];
        a *= (1.0f / LQ);
        sAtt[sd][kk] = a;
        d_out[BATCH * OUTD + sd * (BATCH * LQ) + b * LQ + kk] = a;
    }
    __syncthreads();

    if (t < 16) {
        int sd = t >> 3, m = t & 7;
        float w = sAtt[sd][m];
#pragma unroll
        for (int pp = 0; pp < NPAIR; pp++)
            if (c_pi[pp] == m || c_pj[pp] == m) w += sAtt[sd][MOL + pp];
        sw[sd * MOL + m] = w;
    }
    __syncthreads();

    if (t < OUTD) {
        float s = 0.f;
#pragma unroll
        for (int m = 0; m < MOL; m++) {
            s += sw[m]     * g_tr[((size_t)m * BATCH + b) * OUTD + t];
            s -= sw[8 + m] * g_tp[((size_t)m * BATCH + b) * OUTD + t];
        }
        d_out[b * OUTD + t] = s + b_pred[t];
    }
}

// ---------------------------------------------------------------------------
extern "C" void kernel_launch(void* const* d_in, const int* in_sizes, int n_in,
                              void* d_out, int out_size) {
    const float* r_feats = (const float*)d_in[0];
    const float* p_feats = (const float*)d_in[1];
    const float* r_new   = (const float*)d_in[2];
    const float* p_new   = (const float*)d_in[3];
    const float* Wq      = (const float*)d_in[4];
    const float* Wk      = (const float*)d_in[5];
    const float* W_pred  = (const float*)d_in[6];
    const float* b_pred  = (const float*)d_in[7];
    float* out = (float*)d_out;

    cudaFuncSetAttribute(aux_kernel, cudaFuncAttributeMaxDynamicSharedMemorySize,
                         SMEM_G);
    cudaFuncSetAttribute(mma_gemm_fused, cudaFuncAttributeMaxDynamicSharedMemorySize,
                         SMEM_MAIN);

    __nv_bfloat16 *WqHi, *WqLo, *WkHi, *WkLo;
    __half *Gt, *X;
    cudaGetSymbolAddress((void**)&WqHi, g_WqHi);
    cudaGetSymbolAddress((void**)&WqLo, g_WqLo);
    cudaGetSymbolAddress((void**)&WkHi, g_WkHi);
    cudaGetSymbolAddress((void**)&WkLo, g_WkLo);
    cudaGetSymbolAddress((void**)&Gt,   g_Gt);
    cudaGetSymbolAddress((void**)&X,    g_X);

    // 1) weight splits (bf16, feeds accurate 3-term G-GEMM)
    split_w<<<2048, 128>>>(Wq, Wk);
    // 2) G-GEMM (64 CTAs, bf16 3-term) + split_x (fp16) + head-dots
    aux_kernel<<<64 + MROWS / 2, 256, SMEM_G>>>(WqHi, WqLo, WkHi, WkLo,
                                                p_feats, r_feats,
                                                p_new, r_new, W_pred);
    // 3) fused GEMM (fp16 1-term, k64 chunks) + gram epilogue
    mma_gemm_fused<<<dim3(256, 8), 256, SMEM_MAIN>>>(X, Gt, r_feats, p_feats);
    // 4) softmax + att outputs + tiny head combine
    att_final_kernel<<<BATCH, 128>>>(b_pred, out);
}